// round 1
// baseline (speedup 1.0000x reference)
#include <cuda_runtime.h>
#include <math.h>

// Problem constants
#define BATCH 8
#define CDIM 96
#define HH 224
#define HW 50176              // 224*224
#define L_TOK 401408          // 8*224*224
#define NWIN 8192             // 8 * 32 * 32 windows

// Scratch (static device arrays; no runtime allocation)
__device__ float g_ln1[(size_t)L_TOK * 96];
__device__ float g_xn[(size_t)L_TOK * 96];
__device__ float g_qkv[(size_t)L_TOK * 288];
__device__ float g_ctx[(size_t)L_TOK * 96];
__device__ float g_h[(size_t)L_TOK * 96];
__device__ float g_ln2[(size_t)L_TOK * 96];
__device__ float g_m1[(size_t)L_TOK * 384];
__device__ float g_y[(size_t)L_TOK * 96];

// ---------------------------------------------------------------------------
// Kernel 1: NCHW -> NHWC transpose + LayerNorm1.  32 tokens x 96 ch per block.
// ---------------------------------------------------------------------------
__global__ __launch_bounds__(256) void k_in_ln(const float* __restrict__ x,
                                               const float* __restrict__ w,
                                               const float* __restrict__ b) {
    __shared__ float s[96][33];
    __shared__ float mu_s[32], rs_s[32];
    int tile = blockIdx.x;                 // 12544 tiles
    int bb = tile / 1568;
    int t0 = (tile % 1568) * 32;           // token offset within batch
    int tid = threadIdx.x;

    const float* xb = x + (size_t)bb * 96 * HW + t0;
#pragma unroll
    for (int l = 0; l < 12; ++l) {
        int e = tid + l * 256;
        int ch = e >> 5, tl = e & 31;
        s[ch][tl] = xb[(size_t)ch * HW + tl];
    }
    __syncthreads();

    int tok = tid >> 3, sub = tid & 7;
    float acc = 0.f;
#pragma unroll
    for (int k = 0; k < 12; ++k) acc += s[sub + 8 * k][tok];
    acc += __shfl_down_sync(0xffffffffu, acc, 4);
    acc += __shfl_down_sync(0xffffffffu, acc, 2);
    acc += __shfl_down_sync(0xffffffffu, acc, 1);
    float mean = __shfl_sync(0xffffffffu, acc, (tid & 31) & ~7) * (1.f / 96.f);
    float vv = 0.f;
#pragma unroll
    for (int k = 0; k < 12; ++k) {
        float d = s[sub + 8 * k][tok] - mean;
        vv += d * d;
    }
    vv += __shfl_down_sync(0xffffffffu, vv, 4);
    vv += __shfl_down_sync(0xffffffffu, vv, 2);
    vv += __shfl_down_sync(0xffffffffu, vv, 1);
    float var = __shfl_sync(0xffffffffu, vv, (tid & 31) & ~7) * (1.f / 96.f);
    if (sub == 0) { mu_s[tok] = mean; rs_s[tok] = rsqrtf(var + 1e-5f); }
    __syncthreads();

    size_t base = ((size_t)bb * HW + t0) * 96;
#pragma unroll
    for (int l = 0; l < 12; ++l) {
        int e = tid + l * 256;
        int tk = e / 96, ch = e % 96;
        float val = s[ch][tk];
        g_xn[base + e] = val;
        g_ln1[base + e] = (val - mu_s[tk]) * rs_s[tk] * w[ch] + b[ch];
    }
}

// ---------------------------------------------------------------------------
// Generic register-tiled fp32 GEMM: out[M,N] = A[M,K] @ W[N,K]^T (+epilogue)
// BM=128, BN=96, BK=16, 256 threads, 8x6 per thread.
// MODE 0: +bias    MODE 1: +bias +res    MODE 2: +bias then exact GELU
// ---------------------------------------------------------------------------
template <int N, int K, int MODE>
__global__ __launch_bounds__(256) void k_gemm(const float* __restrict__ A,
                                              const float* __restrict__ W,
                                              const float* __restrict__ bias,
                                              const float* __restrict__ res,
                                              float* __restrict__ out) {
    __shared__ float As[16][129];
    __shared__ float Bs[16][97];
    int m0 = blockIdx.x * 128;
    int n0 = blockIdx.y * 96;
    int tid = threadIdx.x;
    int tx = tid & 15, ty = tid >> 4;

    float acc[8][6];
#pragma unroll
    for (int r = 0; r < 8; ++r)
#pragma unroll
        for (int c = 0; c < 6; ++c) acc[r][c] = 0.f;

    for (int k0 = 0; k0 < K; k0 += 16) {
#pragma unroll
        for (int l = 0; l < 8; ++l) {
            int e = tid + l * 256;
            int m = e >> 4, kk = e & 15;
            As[kk][m] = A[(size_t)(m0 + m) * K + k0 + kk];
        }
#pragma unroll
        for (int l = 0; l < 6; ++l) {
            int e = tid + l * 256;
            int n = e >> 4, kk = e & 15;
            Bs[kk][n] = W[(size_t)(n0 + n) * K + k0 + kk];
        }
        __syncthreads();
#pragma unroll
        for (int kk = 0; kk < 16; ++kk) {
            float a[8], bv[6];
#pragma unroll
            for (int r = 0; r < 8; ++r) a[r] = As[kk][ty * 8 + r];
#pragma unroll
            for (int c = 0; c < 6; ++c) bv[c] = Bs[kk][tx * 6 + c];
#pragma unroll
            for (int r = 0; r < 8; ++r)
#pragma unroll
                for (int c = 0; c < 6; ++c) acc[r][c] += a[r] * bv[c];
        }
        __syncthreads();
    }

#pragma unroll
    for (int r = 0; r < 8; ++r) {
        int m = m0 + ty * 8 + r;
        size_t rowo = (size_t)m * N;
#pragma unroll
        for (int c = 0; c < 6; ++c) {
            int n = n0 + tx * 6 + c;
            float v = acc[r][c] + bias[n];
            if (MODE == 1) v += res[rowo + n];
            if (MODE == 2) v = 0.5f * v * (1.0f + erff(v * 0.70710678118654752f));
            out[rowo + n] = v;
        }
    }
}

// ---------------------------------------------------------------------------
// Kernel 3: per-window shifted attention. One CTA per 7x7 window.
// Gathers q,k,v rows of g_qkv (roll fused into index), scores+bias+mask,
// softmax, attn@V, scatter to g_ctx at the same token indices.
// ---------------------------------------------------------------------------
__global__ __launch_bounds__(256) void k_attn(const float* __restrict__ rel_table) {
    extern __shared__ float sm[];
    float* qs = sm;                 // 49*97
    float* ks = sm + 49 * 97;
    float* vs = sm + 2 * 49 * 97;
    float* att = sm + 3 * 49 * 97;  // 49*52
    __shared__ int tok_s[49];
    __shared__ int lbl_s[49];

    int win = blockIdx.x;
    int bb = win >> 10;
    int wr = (win >> 5) & 31;
    int wc = win & 31;
    int tid = threadIdx.x;

    if (tid < 49) {
        int i = tid / 7, j = tid % 7;
        int sr = wr * 7 + i, sc = wc * 7 + j;   // shifted coords
        int r = sr + 3; if (r >= 224) r -= 224; // unshift (gather == scatter idx)
        int c = sc + 3; if (c >= 224) c -= 224;
        tok_s[tid] = bb * HW + r * 224 + c;
        int rb = (sr < 217) ? 0 : (sr < 221 ? 1 : 2);
        int cb = (sc < 217) ? 0 : (sc < 221 ? 1 : 2);
        lbl_s[tid] = rb * 3 + cb;
    }
    __syncthreads();

    // gather q (pre-scaled), k, v
    for (int e = tid; e < 49 * 288; e += 256) {
        int row = e / 288, ch = e % 288;
        float v = g_qkv[(size_t)tok_s[row] * 288 + ch];
        if (ch < 96)       qs[row * 97 + ch] = v * 0.10206207261596575f; // 96^-0.5
        else if (ch < 192) ks[row * 97 + ch - 96] = v;
        else               vs[row * 97 + ch - 192] = v;
    }
    __syncthreads();

    // scores + relative-position bias + shift mask
    for (int e = tid; e < 49 * 49; e += 256) {
        int i = e / 49, j = e % 49;
        const float* qp = qs + i * 97;
        const float* kp = ks + j * 97;
        float s = 0.f;
#pragma unroll 8
        for (int ch = 0; ch < 96; ++ch) s += qp[ch] * kp[ch];
        int idx = (i / 7 - j / 7 + 6) * 13 + (i % 7 - j % 7 + 6);
        s += rel_table[idx];
        if (lbl_s[i] != lbl_s[j]) s -= 100.0f;
        att[i * 52 + j] = s;
    }
    __syncthreads();

    // softmax per row (8 warps, rows strided)
    int warp = tid >> 5, lane = tid & 31;
    for (int row = warp; row < 49; row += 8) {
        float x0 = att[row * 52 + lane];
        float x1 = (lane + 32 < 49) ? att[row * 52 + lane + 32] : -1e30f;
        float mx = fmaxf(x0, x1);
        for (int o = 16; o; o >>= 1) mx = fmaxf(mx, __shfl_xor_sync(0xffffffffu, mx, o));
        float e0 = expf(x0 - mx);
        float e1 = (lane + 32 < 49) ? expf(x1 - mx) : 0.f;
        float sum = e0 + e1;
        for (int o = 16; o; o >>= 1) sum += __shfl_xor_sync(0xffffffffu, sum, o);
        float inv = 1.0f / sum;
        att[row * 52 + lane] = e0 * inv;
        if (lane + 32 < 49) att[row * 52 + lane + 32] = e1 * inv;
    }
    __syncthreads();

    // out = att @ V, scatter
    for (int e = tid; e < 49 * 96; e += 256) {
        int i = e / 96, ch = e % 96;
        const float* ap = att + i * 52;
        float s = 0.f;
#pragma unroll 7
        for (int j = 0; j < 49; ++j) s += ap[j] * vs[j * 97 + ch];
        g_ctx[(size_t)tok_s[i] * 96 + ch] = s;
    }
}

// ---------------------------------------------------------------------------
// Kernel 5: LayerNorm2 on g_h (rows already contiguous). One warp per token.
// ---------------------------------------------------------------------------
__global__ __launch_bounds__(128) void k_ln2(const float* __restrict__ w,
                                             const float* __restrict__ b) {
    int t = blockIdx.x * 4 + (threadIdx.x >> 5);
    int lane = threadIdx.x & 31;
    const float* hp = g_h + (size_t)t * 96;
    float v0 = hp[lane], v1 = hp[lane + 32], v2 = hp[lane + 64];
    float s = v0 + v1 + v2;
    for (int o = 16; o; o >>= 1) s += __shfl_xor_sync(0xffffffffu, s, o);
    float mean = s * (1.f / 96.f);
    float d0 = v0 - mean, d1 = v1 - mean, d2 = v2 - mean;
    float vv = d0 * d0 + d1 * d1 + d2 * d2;
    for (int o = 16; o; o >>= 1) vv += __shfl_xor_sync(0xffffffffu, vv, o);
    float rstd = rsqrtf(vv * (1.f / 96.f) + 1e-5f);
    float* op = g_ln2 + (size_t)t * 96;
    op[lane]      = d0 * rstd * w[lane] + b[lane];
    op[lane + 32] = d1 * rstd * w[lane + 32] + b[lane + 32];
    op[lane + 64] = d2 * rstd * w[lane + 64] + b[lane + 64];
}

// ---------------------------------------------------------------------------
// Kernel 8: NHWC -> NCHW transpose of g_y into d_out.
// ---------------------------------------------------------------------------
__global__ __launch_bounds__(256) void k_out(float* __restrict__ out) {
    __shared__ float s[96][33];
    int tile = blockIdx.x;
    int bb = tile / 1568;
    int t0 = (tile % 1568) * 32;
    int tid = threadIdx.x;
    size_t base = ((size_t)bb * HW + t0) * 96;
#pragma unroll
    for (int l = 0; l < 12; ++l) {
        int e = tid + l * 256;
        int tk = e / 96, ch = e % 96;
        s[ch][tk] = g_y[base + e];
    }
    __syncthreads();
    float* ob = out + (size_t)bb * 96 * HW + t0;
#pragma unroll
    for (int l = 0; l < 12; ++l) {
        int e = tid + l * 256;
        int ch = e >> 5, tl = e & 31;
        ob[(size_t)ch * HW + tl] = s[ch][tl];
    }
}

// ---------------------------------------------------------------------------
extern "C" void kernel_launch(void* const* d_in, const int* in_sizes, int n_in,
                              void* d_out, int out_size) {
    const float* x    = (const float*)d_in[0];
    const float* n1w  = (const float*)d_in[1];
    const float* n1b  = (const float*)d_in[2];
    const float* qkvw = (const float*)d_in[3];
    const float* qkvb = (const float*)d_in[4];
    const float* rel  = (const float*)d_in[5];
    const float* pw   = (const float*)d_in[6];
    const float* pb   = (const float*)d_in[7];
    const float* n2w  = (const float*)d_in[8];
    const float* n2b  = (const float*)d_in[9];
    const float* w1   = (const float*)d_in[10];
    const float* b1   = (const float*)d_in[11];
    const float* w2   = (const float*)d_in[12];
    const float* b2   = (const float*)d_in[13];
    float* out = (float*)d_out;

    void *p_ln1, *p_xn, *p_qkv, *p_ctx, *p_h, *p_ln2, *p_m1, *p_y;
    cudaGetSymbolAddress(&p_ln1, g_ln1);
    cudaGetSymbolAddress(&p_xn,  g_xn);
    cudaGetSymbolAddress(&p_qkv, g_qkv);
    cudaGetSymbolAddress(&p_ctx, g_ctx);
    cudaGetSymbolAddress(&p_h,   g_h);
    cudaGetSymbolAddress(&p_ln2, g_ln2);
    cudaGetSymbolAddress(&p_m1,  g_m1);
    cudaGetSymbolAddress(&p_y,   g_y);

    const int ATTN_SMEM = (3 * 49 * 97 + 49 * 52) * 4;  // 67228 B
    cudaFuncSetAttribute(k_attn, cudaFuncAttributeMaxDynamicSharedMemorySize, ATTN_SMEM);

    // 1) NCHW->NHWC + LN1
    k_in_ln<<<12544, 256>>>(x, n1w, n1b);
    // 2) QKV = ln1 @ qkv_w^T + b  ([L,96] x [288,96]^T)
    k_gemm<288, 96, 0><<<dim3(3136, 3), 256>>>((const float*)p_ln1, qkvw, qkvb, nullptr, (float*)p_qkv);
    // 3) per-window attention -> ctx
    k_attn<<<NWIN, 256, ATTN_SMEM>>>(rel);
    // 4) h = ctx @ proj_w^T + b + x
    k_gemm<96, 96, 1><<<dim3(3136, 1), 256>>>((const float*)p_ctx, pw, pb, (const float*)p_xn, (float*)p_h);
    // 5) ln2(h)
    k_ln2<<<100352, 128>>>(n2w, n2b);
    // 6) m1 = gelu(ln2 @ w1^T + b1)
    k_gemm<384, 96, 2><<<dim3(3136, 4), 256>>>((const float*)p_ln2, w1, b1, nullptr, (float*)p_m1);
    // 7) y = m1 @ w2^T + b2 + h
    k_gemm<96, 384, 1><<<dim3(3136, 1), 256>>>((const float*)p_m1, w2, b2, (const float*)p_h, (float*)p_y);
    // 8) NHWC -> NCHW
    k_out<<<12544, 256>>>(out);
}

// round 2
// speedup vs baseline: 1.1284x; 1.1284x over previous
#include <cuda_runtime.h>
#include <math.h>

#define BATCH 8
#define CDIM 96
#define HW 50176              // 224*224
#define L_TOK 401408          // 8*224*224
#define NWIN 8192             // 8 * 32 * 32 windows

// Scratch
__device__ float g_ln1[(size_t)L_TOK * 96];
__device__ float g_xn[(size_t)L_TOK * 96];
__device__ float g_qkv[(size_t)L_TOK * 288];
__device__ float g_ctx[(size_t)L_TOK * 96];
__device__ float g_h[(size_t)L_TOK * 96];
__device__ float g_ln2[(size_t)L_TOK * 96];
__device__ float g_m1[(size_t)L_TOK * 384];

// ---- packed f32x2 helpers -------------------------------------------------
__device__ __forceinline__ unsigned long long fma2(unsigned long long a,
                                                   unsigned long long b,
                                                   unsigned long long c) {
    unsigned long long d;
    asm("fma.rn.f32x2 %0, %1, %2, %3;" : "=l"(d) : "l"(a), "l"(b), "l"(c));
    return d;
}
__device__ __forceinline__ unsigned long long pack2(float lo, float hi) {
    unsigned long long r;
    asm("mov.b64 %0, {%1, %2};" : "=l"(r) : "f"(lo), "f"(hi));
    return r;
}
__device__ __forceinline__ unsigned long long ld2s(const float* p) {
    float2 t = *reinterpret_cast<const float2*>(p);
    return pack2(t.x, t.y);
}
__device__ __forceinline__ float2 unpack2(unsigned long long v) {
    float2 t;
    asm("mov.b64 {%0, %1}, %2;" : "=f"(t.x), "=f"(t.y) : "l"(v));
    return t;
}

// ---------------------------------------------------------------------------
// Kernel 1: NCHW -> NHWC transpose + LayerNorm1.  32 tokens x 96 ch per block.
// ---------------------------------------------------------------------------
__global__ __launch_bounds__(256) void k_in_ln(const float* __restrict__ x,
                                               const float* __restrict__ w,
                                               const float* __restrict__ b) {
    __shared__ float s[96][33];
    __shared__ float mu_s[32], rs_s[32];
    int tile = blockIdx.x;
    int bb = tile / 1568;
    int t0 = (tile % 1568) * 32;
    int tid = threadIdx.x;

    const float* xb = x + (size_t)bb * 96 * HW + t0;
#pragma unroll
    for (int l = 0; l < 12; ++l) {
        int e = tid + l * 256;
        int ch = e >> 5, tl = e & 31;
        s[ch][tl] = xb[(size_t)ch * HW + tl];
    }
    __syncthreads();

    int tok = tid >> 3, sub = tid & 7;
    float acc = 0.f;
#pragma unroll
    for (int k = 0; k < 12; ++k) acc += s[sub + 8 * k][tok];
    acc += __shfl_down_sync(0xffffffffu, acc, 4);
    acc += __shfl_down_sync(0xffffffffu, acc, 2);
    acc += __shfl_down_sync(0xffffffffu, acc, 1);
    float mean = __shfl_sync(0xffffffffu, acc, (tid & 31) & ~7) * (1.f / 96.f);
    float vv = 0.f;
#pragma unroll
    for (int k = 0; k < 12; ++k) {
        float d = s[sub + 8 * k][tok] - mean;
        vv += d * d;
    }
    vv += __shfl_down_sync(0xffffffffu, vv, 4);
    vv += __shfl_down_sync(0xffffffffu, vv, 2);
    vv += __shfl_down_sync(0xffffffffu, vv, 1);
    float var = __shfl_sync(0xffffffffu, vv, (tid & 31) & ~7) * (1.f / 96.f);
    if (sub == 0) { mu_s[tok] = mean; rs_s[tok] = rsqrtf(var + 1e-5f); }
    __syncthreads();

    size_t base = ((size_t)bb * HW + t0) * 96;
#pragma unroll
    for (int l = 0; l < 12; ++l) {
        int e = tid + l * 256;
        int tk = e / 96, ch = e % 96;
        float val = s[ch][tk];
        g_xn[base + e] = val;
        g_ln1[base + e] = (val - mu_s[tk]) * rs_s[tk] * w[ch] + b[ch];
    }
}

// ---------------------------------------------------------------------------
// f32x2 register-tiled GEMM: out[M,N] = A[M,K] @ W[N,K]^T (+epilogue)
// BM=128, BN=96, BK=16, 256 threads, 8x6 per thread (4 row-pairs x 6 cols).
// MODE 0: +bias                      (QKV)
// MODE 2: +bias, exact GELU          (MLP1)
// MODE 3: +bias +res -> out(h); fused LN -> out2          (proj)
// MODE 4: +bias +res -> NCHW-transposed store to out      (MLP2, final)
// ---------------------------------------------------------------------------
template <int N, int K, int MODE>
__global__ __launch_bounds__(256) void k_gemm(const float* __restrict__ A,
                                              const float* __restrict__ W,
                                              const float* __restrict__ bias,
                                              const float* __restrict__ res,
                                              float* __restrict__ out,
                                              const float* __restrict__ lnw,
                                              const float* __restrict__ lnb,
                                              float* __restrict__ out2) {
    __shared__ float As[16][130];   // 130: even stride so row-pair LDS.64 stays aligned
    __shared__ float Bs[16][97];
    int m0 = blockIdx.x * 128;
    int n0 = blockIdx.y * 96;
    int tid = threadIdx.x;
    int tx = tid & 15, ty = tid >> 4;

    unsigned long long acc2[4][6];
#pragma unroll
    for (int p = 0; p < 4; ++p)
#pragma unroll
        for (int c = 0; c < 6; ++c) acc2[p][c] = 0ull;

    for (int k0 = 0; k0 < K; k0 += 16) {
#pragma unroll
        for (int l = 0; l < 8; ++l) {
            int e = tid + l * 256;
            int m = e >> 4, kk = e & 15;
            As[kk][m] = A[(size_t)(m0 + m) * K + k0 + kk];
        }
#pragma unroll
        for (int l = 0; l < 6; ++l) {
            int e = tid + l * 256;
            int n = e >> 4, kk = e & 15;
            Bs[kk][n] = W[(size_t)(n0 + n) * K + k0 + kk];
        }
        __syncthreads();
#pragma unroll
        for (int kk = 0; kk < 16; ++kk) {
            unsigned long long a2[4];
#pragma unroll
            for (int p = 0; p < 4; ++p) a2[p] = ld2s(&As[kk][ty * 8 + 2 * p]);
#pragma unroll
            for (int c = 0; c < 6; ++c) {
                float bv = Bs[kk][tx * 6 + c];
                unsigned long long b2 = pack2(bv, bv);
#pragma unroll
                for (int p = 0; p < 4; ++p) acc2[p][c] = fma2(a2[p], b2, acc2[p][c]);
            }
        }
        __syncthreads();
    }

    // unpack to v[8][6] and add bias
    float v[8][6];
#pragma unroll
    for (int p = 0; p < 4; ++p)
#pragma unroll
        for (int c = 0; c < 6; ++c) {
            float2 t = unpack2(acc2[p][c]);
            float bi = bias[n0 + tx * 6 + c];
            v[2 * p][c] = t.x + bi;
            v[2 * p + 1][c] = t.y + bi;
        }

    if constexpr (MODE == 0) {
#pragma unroll
        for (int r = 0; r < 8; ++r) {
            size_t rowo = (size_t)(m0 + ty * 8 + r) * N;
#pragma unroll
            for (int c = 0; c < 6; ++c) out[rowo + n0 + tx * 6 + c] = v[r][c];
        }
    }
    if constexpr (MODE == 2) {
#pragma unroll
        for (int r = 0; r < 8; ++r) {
            size_t rowo = (size_t)(m0 + ty * 8 + r) * N;
#pragma unroll
            for (int c = 0; c < 6; ++c) {
                float h = v[r][c];
                out[rowo + n0 + tx * 6 + c] =
                    0.5f * h * (1.0f + erff(h * 0.70710678118654752f));
            }
        }
    }
    if constexpr (MODE == 3) {
        // h = v + res, then LN over N=96 (one block spans full row width).
        // Lanes with identical ty form a 16-lane group; xor masks 1,2,4,8
        // reduce within the group.
#pragma unroll
        for (int r = 0; r < 8; ++r) {
            size_t rowo = (size_t)(m0 + ty * 8 + r) * 96;
            float s = 0.f, q = 0.f;
#pragma unroll
            for (int c = 0; c < 6; ++c) {
                float h = v[r][c] + res[rowo + tx * 6 + c];
                v[r][c] = h;
                s += h;
                q += h * h;
            }
#pragma unroll
            for (int mk = 1; mk <= 8; mk <<= 1) {
                s += __shfl_xor_sync(0xffffffffu, s, mk);
                q += __shfl_xor_sync(0xffffffffu, q, mk);
            }
            float mean = s * (1.f / 96.f);
            float var = q * (1.f / 96.f) - mean * mean;
            float rstd = rsqrtf(var + 1e-5f);
#pragma unroll
            for (int c = 0; c < 6; ++c) {
                int n = tx * 6 + c;
                float h = v[r][c];
                out[rowo + n] = h;
                out2[rowo + n] = (h - mean) * rstd * lnw[n] + lnb[n];
            }
        }
    }
    if constexpr (MODE == 4) {
        __shared__ float st[128][97];
#pragma unroll
        for (int r = 0; r < 8; ++r) {
            size_t rowo = (size_t)(m0 + ty * 8 + r) * 96;
#pragma unroll
            for (int c = 0; c < 6; ++c)
                st[ty * 8 + r][tx * 6 + c] = v[r][c] + res[rowo + tx * 6 + c];
        }
        __syncthreads();
        int bb = m0 / HW, hw0 = m0 % HW;
        float* ob = out + (size_t)bb * 96 * HW + hw0;
#pragma unroll
        for (int l = 0; l < 48; ++l) {
            int e = tid + l * 256;
            int ch = e >> 7, tok = e & 127;
            ob[(size_t)ch * HW + tok] = st[tok][ch];
        }
    }
}

// ---------------------------------------------------------------------------
// Kernel 3: per-window shifted attention, one CTA per 7x7 window (f32x2).
// ---------------------------------------------------------------------------
__global__ __launch_bounds__(256) void k_attn(const float* __restrict__ rel_table) {
    extern __shared__ float sm[];
    float* qs = sm;                 // 49*98
    float* ks = sm + 49 * 98;
    float* vs = sm + 2 * 49 * 98;
    float* att = sm + 3 * 49 * 98;  // 49*52
    __shared__ int tok_s[49];
    __shared__ int lbl_s[49];

    int win = blockIdx.x;
    int bb = win >> 10;
    int wr = (win >> 5) & 31;
    int wc = win & 31;
    int tid = threadIdx.x;

    if (tid < 49) {
        int i = tid / 7, j = tid % 7;
        int sr = wr * 7 + i, sc = wc * 7 + j;
        int r = sr + 3; if (r >= 224) r -= 224;
        int c = sc + 3; if (c >= 224) c -= 224;
        tok_s[tid] = bb * HW + r * 224 + c;
        int rb = (sr < 217) ? 0 : (sr < 221 ? 1 : 2);
        int cb = (sc < 217) ? 0 : (sc < 221 ? 1 : 2);
        lbl_s[tid] = rb * 3 + cb;
    }
    __syncthreads();

    for (int e = tid; e < 49 * 288; e += 256) {
        int row = e / 288, ch = e % 288;
        float v = g_qkv[(size_t)tok_s[row] * 288 + ch];
        if (ch < 96)       qs[row * 98 + ch] = v * 0.10206207261596575f;
        else if (ch < 192) ks[row * 98 + ch - 96] = v;
        else               vs[row * 98 + ch - 192] = v;
    }
    __syncthreads();

    // scores (f32x2 dot) + bias + mask
    for (int e = tid; e < 49 * 49; e += 256) {
        int i = e / 49, j = e % 49;
        const float* qp = qs + i * 98;
        const float* kp = ks + j * 98;
        unsigned long long acc = 0ull;
#pragma unroll 8
        for (int ch = 0; ch < 96; ch += 2)
            acc = fma2(ld2s(qp + ch), ld2s(kp + ch), acc);
        float2 t = unpack2(acc);
        float s = t.x + t.y;
        int idx = (i / 7 - j / 7 + 6) * 13 + (i % 7 - j % 7 + 6);
        s += rel_table[idx];
        if (lbl_s[i] != lbl_s[j]) s -= 100.0f;
        att[i * 52 + j] = s;
    }
    __syncthreads();

    int warp = tid >> 5, lane = tid & 31;
    for (int row = warp; row < 49; row += 8) {
        float x0 = att[row * 52 + lane];
        float x1 = (lane + 32 < 49) ? att[row * 52 + lane + 32] : -1e30f;
        float mx = fmaxf(x0, x1);
        for (int o = 16; o; o >>= 1) mx = fmaxf(mx, __shfl_xor_sync(0xffffffffu, mx, o));
        float e0 = expf(x0 - mx);
        float e1 = (lane + 32 < 49) ? expf(x1 - mx) : 0.f;
        float sum = e0 + e1;
        for (int o = 16; o; o >>= 1) sum += __shfl_xor_sync(0xffffffffu, sum, o);
        float inv = 1.0f / sum;
        att[row * 52 + lane] = e0 * inv;
        if (lane + 32 < 49) att[row * 52 + lane + 32] = e1 * inv;
    }
    __syncthreads();

    // out = att @ V (two channels per element via f32x2), scatter
    for (int e = tid; e < 49 * 48; e += 256) {
        int i = e / 48, chp = (e % 48) * 2;
        const float* ap = att + i * 52;
        unsigned long long acc = 0ull;
#pragma unroll 7
        for (int j = 0; j < 49; ++j) {
            float a = ap[j];
            acc = fma2(pack2(a, a), ld2s(&vs[j * 98 + chp]), acc);
        }
        float2 t = unpack2(acc);
        *reinterpret_cast<float2*>(&g_ctx[(size_t)tok_s[i] * 96 + chp]) = t;
    }
}

// ---------------------------------------------------------------------------
extern "C" void kernel_launch(void* const* d_in, const int* in_sizes, int n_in,
                              void* d_out, int out_size) {
    const float* x    = (const float*)d_in[0];
    const float* n1w  = (const float*)d_in[1];
    const float* n1b  = (const float*)d_in[2];
    const float* qkvw = (const float*)d_in[3];
    const float* qkvb = (const float*)d_in[4];
    const float* rel  = (const float*)d_in[5];
    const float* pw   = (const float*)d_in[6];
    const float* pb   = (const float*)d_in[7];
    const float* n2w  = (const float*)d_in[8];
    const float* n2b  = (const float*)d_in[9];
    const float* w1   = (const float*)d_in[10];
    const float* b1   = (const float*)d_in[11];
    const float* w2   = (const float*)d_in[12];
    const float* b2   = (const float*)d_in[13];
    float* out = (float*)d_out;

    void *p_ln1, *p_xn, *p_qkv, *p_ctx, *p_h, *p_ln2, *p_m1;
    cudaGetSymbolAddress(&p_ln1, g_ln1);
    cudaGetSymbolAddress(&p_xn,  g_xn);
    cudaGetSymbolAddress(&p_qkv, g_qkv);
    cudaGetSymbolAddress(&p_ctx, g_ctx);
    cudaGetSymbolAddress(&p_h,   g_h);
    cudaGetSymbolAddress(&p_ln2, g_ln2);
    cudaGetSymbolAddress(&p_m1,  g_m1);

    const int ATTN_SMEM = (3 * 49 * 98 + 49 * 52) * 4;  // 67816 B
    cudaFuncSetAttribute(k_attn, cudaFuncAttributeMaxDynamicSharedMemorySize, ATTN_SMEM);

    // 1) NCHW->NHWC + LN1
    k_in_ln<<<12544, 256>>>(x, n1w, n1b);
    // 2) QKV
    k_gemm<288, 96, 0><<<dim3(3136, 3), 256>>>((const float*)p_ln1, qkvw, qkvb,
                                               nullptr, (float*)p_qkv, nullptr, nullptr, nullptr);
    // 3) attention
    k_attn<<<NWIN, 256, ATTN_SMEM>>>(rel);
    // 4) proj + residual + fused LN2
    k_gemm<96, 96, 3><<<dim3(3136, 1), 256>>>((const float*)p_ctx, pw, pb,
                                              (const float*)p_xn, (float*)p_h,
                                              n2w, n2b, (float*)p_ln2);
    // 5) MLP1 + GELU
    k_gemm<384, 96, 2><<<dim3(3136, 4), 256>>>((const float*)p_ln2, w1, b1,
                                               nullptr, (float*)p_m1, nullptr, nullptr, nullptr);
    // 6) MLP2 + residual + fused NCHW transpose -> d_out
    k_gemm<96, 384, 4><<<dim3(3136, 1), 256>>>((const float*)p_m1, w2, b2,
                                               (const float*)p_h, out, nullptr, nullptr, nullptr);
}

// round 3
// speedup vs baseline: 1.7714x; 1.5699x over previous
#include <cuda_runtime.h>
#include <math.h>

#define BATCH 8
#define CDIM 96
#define HW 50176              // 224*224
#define L_TOK 401408          // 8*224*224
#define NWIN 8192             // 8 * 32 * 32 windows

// Scratch
__device__ float g_ln1[(size_t)L_TOK * 96];
__device__ float g_xn[(size_t)L_TOK * 96];
__device__ float g_qkv[(size_t)L_TOK * 288];
__device__ float g_ctx[(size_t)L_TOK * 96];
__device__ float g_h[(size_t)L_TOK * 96];
__device__ float g_ln2[(size_t)L_TOK * 96];
__device__ float g_m1[(size_t)L_TOK * 384];

// ---- helpers --------------------------------------------------------------
__device__ __forceinline__ unsigned long long fma2(unsigned long long a,
                                                   unsigned long long b,
                                                   unsigned long long c) {
    unsigned long long d;
    asm("fma.rn.f32x2 %0, %1, %2, %3;" : "=l"(d) : "l"(a), "l"(b), "l"(c));
    return d;
}
__device__ __forceinline__ unsigned long long pack2(float lo, float hi) {
    unsigned long long r;
    asm("mov.b64 %0, {%1, %2};" : "=l"(r) : "f"(lo), "f"(hi));
    return r;
}
__device__ __forceinline__ unsigned long long ld2s(const float* p) {
    float2 t = *reinterpret_cast<const float2*>(p);
    return pack2(t.x, t.y);
}
__device__ __forceinline__ float2 unpack2(unsigned long long v) {
    float2 t;
    asm("mov.b64 {%0, %1}, %2;" : "=f"(t.x), "=f"(t.y) : "l"(v));
    return t;
}
__device__ __forceinline__ unsigned tf32c(float f) {
    unsigned r;
    asm("cvt.rna.tf32.f32 %0, %1;" : "=r"(r) : "f"(f));
    return r;
}
__device__ __forceinline__ void mma8(float* c, const unsigned* a,
                                     unsigned b0, unsigned b1) {
    asm("mma.sync.aligned.m16n8k8.row.col.f32.tf32.tf32.f32 "
        "{%0,%1,%2,%3}, {%4,%5,%6,%7}, {%8,%9}, {%0,%1,%2,%3};"
        : "+f"(c[0]), "+f"(c[1]), "+f"(c[2]), "+f"(c[3])
        : "r"(a[0]), "r"(a[1]), "r"(a[2]), "r"(a[3]), "r"(b0), "r"(b1));
}

// ---------------------------------------------------------------------------
// Kernel 1: NCHW -> NHWC transpose + LayerNorm1.
// ---------------------------------------------------------------------------
__global__ __launch_bounds__(256) void k_in_ln(const float* __restrict__ x,
                                               const float* __restrict__ w,
                                               const float* __restrict__ b) {
    __shared__ float s[96][33];
    __shared__ float mu_s[32], rs_s[32];
    int tile = blockIdx.x;
    int bb = tile / 1568;
    int t0 = (tile % 1568) * 32;
    int tid = threadIdx.x;

    const float* xb = x + (size_t)bb * 96 * HW + t0;
#pragma unroll
    for (int l = 0; l < 12; ++l) {
        int e = tid + l * 256;
        int ch = e >> 5, tl = e & 31;
        s[ch][tl] = xb[(size_t)ch * HW + tl];
    }
    __syncthreads();

    int tok = tid >> 3, sub = tid & 7;
    float acc = 0.f;
#pragma unroll
    for (int k = 0; k < 12; ++k) acc += s[sub + 8 * k][tok];
    acc += __shfl_down_sync(0xffffffffu, acc, 4);
    acc += __shfl_down_sync(0xffffffffu, acc, 2);
    acc += __shfl_down_sync(0xffffffffu, acc, 1);
    float mean = __shfl_sync(0xffffffffu, acc, (tid & 31) & ~7) * (1.f / 96.f);
    float vv = 0.f;
#pragma unroll
    for (int k = 0; k < 12; ++k) {
        float d = s[sub + 8 * k][tok] - mean;
        vv += d * d;
    }
    vv += __shfl_down_sync(0xffffffffu, vv, 4);
    vv += __shfl_down_sync(0xffffffffu, vv, 2);
    vv += __shfl_down_sync(0xffffffffu, vv, 1);
    float var = __shfl_sync(0xffffffffu, vv, (tid & 31) & ~7) * (1.f / 96.f);
    if (sub == 0) { mu_s[tok] = mean; rs_s[tok] = rsqrtf(var + 1e-5f); }
    __syncthreads();

    size_t base = ((size_t)bb * HW + t0) * 96;
#pragma unroll
    for (int l = 0; l < 12; ++l) {
        int e = tid + l * 256;
        int tk = e / 96, ch = e % 96;
        float val = s[ch][tk];
        g_xn[base + e] = val;
        g_ln1[base + e] = (val - mu_s[tk]) * rs_s[tk] * w[ch] + b[ch];
    }
}

// ---------------------------------------------------------------------------
// tf32 tensor-core GEMM: out[M,N] = A[M,K] @ W[N,K]^T (+epilogue)
// BM=128, BN=96, BK=32. 8 warps: 4(M) x 2(N); warp tile 32x48 (2x6 mma tiles).
// K octets permuted in smem (kp = (k%4)*2 + k/4) so fragment pairs are LDS.64.
// MODE 0: +bias                                  (QKV)
// MODE 2: +bias, exact GELU                      (MLP1)
// MODE 3: +bias +res -> out(h); fused LN -> out2 (proj, N=96)
// MODE 4: +bias +res -> NCHW transposed store    (MLP2, N=96, final)
// ---------------------------------------------------------------------------
template <int N, int K, int MODE>
__global__ __launch_bounds__(256) void k_mma(const float* __restrict__ A,
                                             const float* __restrict__ W,
                                             const float* __restrict__ bias,
                                             const float* __restrict__ res,
                                             float* __restrict__ out,
                                             const float* __restrict__ lnw,
                                             const float* __restrict__ lnb,
                                             float* __restrict__ out2) {
    extern __shared__ unsigned smem_u[];
    unsigned (*As)[40] = reinterpret_cast<unsigned (*)[40]>(smem_u);            // 128x40
    unsigned (*Bs)[40] = reinterpret_cast<unsigned (*)[40]>(smem_u + 128 * 40); // 96x40

    int tid = threadIdx.x;
    int lane = tid & 31, warp = tid >> 5;
    int warp_m = warp & 3, warp_n = warp >> 2;
    int g = lane >> 2, tig = lane & 3;
    int m0 = blockIdx.x * 128, n0 = blockIdx.y * 96;

    float acc[2][6][4];
#pragma unroll
    for (int mt = 0; mt < 2; ++mt)
#pragma unroll
        for (int nt = 0; nt < 6; ++nt)
#pragma unroll
            for (int q = 0; q < 4; ++q) acc[mt][nt][q] = 0.f;

    for (int k0 = 0; k0 < K; k0 += 32) {
        if (k0) __syncthreads();
#pragma unroll
        for (int l = 0; l < 2; ++l) {
            int o = tid + l * 256;
            int row = o >> 2, oct = o & 3;
            const float4* p = reinterpret_cast<const float4*>(
                A + (size_t)(m0 + row) * K + k0 + oct * 8);
            float4 v1 = p[0], v2 = p[1];
            unsigned* d = &As[row][oct * 8];
            d[0] = tf32c(v1.x); d[1] = tf32c(v2.x);
            d[2] = tf32c(v1.y); d[3] = tf32c(v2.y);
            d[4] = tf32c(v1.z); d[5] = tf32c(v2.z);
            d[6] = tf32c(v1.w); d[7] = tf32c(v2.w);
        }
        for (int o = tid; o < 384; o += 256) {
            int row = o >> 2, oct = o & 3;
            const float4* p = reinterpret_cast<const float4*>(
                W + (size_t)(n0 + row) * K + k0 + oct * 8);
            float4 v1 = p[0], v2 = p[1];
            unsigned* d = &Bs[row][oct * 8];
            d[0] = tf32c(v1.x); d[1] = tf32c(v2.x);
            d[2] = tf32c(v1.y); d[3] = tf32c(v2.y);
            d[4] = tf32c(v1.z); d[5] = tf32c(v2.z);
            d[6] = tf32c(v1.w); d[7] = tf32c(v2.w);
        }
        __syncthreads();
#pragma unroll
        for (int ks = 0; ks < 4; ++ks) {
            unsigned a[2][4];
#pragma unroll
            for (int mt = 0; mt < 2; ++mt) {
                uint2 p0 = *reinterpret_cast<const uint2*>(
                    &As[warp_m * 32 + mt * 16 + g][ks * 8 + 2 * tig]);
                uint2 p1 = *reinterpret_cast<const uint2*>(
                    &As[warp_m * 32 + mt * 16 + g + 8][ks * 8 + 2 * tig]);
                a[mt][0] = p0.x; a[mt][2] = p0.y;
                a[mt][1] = p1.x; a[mt][3] = p1.y;
            }
#pragma unroll
            for (int nt = 0; nt < 6; ++nt) {
                uint2 bp = *reinterpret_cast<const uint2*>(
                    &Bs[warp_n * 48 + nt * 8 + g][ks * 8 + 2 * tig]);
#pragma unroll
                for (int mt = 0; mt < 2; ++mt)
                    mma8(acc[mt][nt], a[mt], bp.x, bp.y);
            }
        }
    }

    // ---- epilogues --------------------------------------------------------
    if constexpr (MODE == 0 || MODE == 2) {
#pragma unroll
        for (int mt = 0; mt < 2; ++mt) {
            int r0 = m0 + warp_m * 32 + mt * 16 + g;
#pragma unroll
            for (int nt = 0; nt < 6; ++nt) {
                int col = n0 + warp_n * 48 + nt * 8 + 2 * tig;
                float bi0 = bias[col], bi1 = bias[col + 1];
                float v0 = acc[mt][nt][0] + bi0, v1 = acc[mt][nt][1] + bi1;
                float v2 = acc[mt][nt][2] + bi0, v3 = acc[mt][nt][3] + bi1;
                if (MODE == 2) {
                    v0 = 0.5f * v0 * (1.0f + erff(v0 * 0.70710678118654752f));
                    v1 = 0.5f * v1 * (1.0f + erff(v1 * 0.70710678118654752f));
                    v2 = 0.5f * v2 * (1.0f + erff(v2 * 0.70710678118654752f));
                    v3 = 0.5f * v3 * (1.0f + erff(v3 * 0.70710678118654752f));
                }
                *reinterpret_cast<float2*>(&out[(size_t)r0 * N + col]) =
                    make_float2(v0, v1);
                *reinterpret_cast<float2*>(&out[(size_t)(r0 + 8) * N + col]) =
                    make_float2(v2, v3);
            }
        }
    }
    if constexpr (MODE == 3) {
        float (*st)[100] = reinterpret_cast<float (*)[100]>(smem_u);
        __syncthreads();  // done with As/Bs across all warps
#pragma unroll
        for (int mt = 0; mt < 2; ++mt) {
            int lr0 = warp_m * 32 + mt * 16 + g;
            int r0 = m0 + lr0;
#pragma unroll
            for (int nt = 0; nt < 6; ++nt) {
                int col = warp_n * 48 + nt * 8 + 2 * tig;
                float bi0 = bias[col], bi1 = bias[col + 1];
                float2 rs0 = *reinterpret_cast<const float2*>(&res[(size_t)r0 * 96 + col]);
                float2 rs1 = *reinterpret_cast<const float2*>(&res[(size_t)(r0 + 8) * 96 + col]);
                float h0 = acc[mt][nt][0] + bi0 + rs0.x;
                float h1 = acc[mt][nt][1] + bi1 + rs0.y;
                float h2 = acc[mt][nt][2] + bi0 + rs1.x;
                float h3 = acc[mt][nt][3] + bi1 + rs1.y;
                *reinterpret_cast<float2*>(&out[(size_t)r0 * 96 + col]) = make_float2(h0, h1);
                *reinterpret_cast<float2*>(&out[(size_t)(r0 + 8) * 96 + col]) = make_float2(h2, h3);
                *reinterpret_cast<float2*>(&st[lr0][col]) = make_float2(h0, h1);
                *reinterpret_cast<float2*>(&st[lr0 + 8][col]) = make_float2(h2, h3);
            }
        }
        __syncthreads();
        int r = tid >> 1, half = tid & 1;
        const float* rp = &st[r][half * 48];
        float s = 0.f, q = 0.f;
        float vals[48];
#pragma unroll
        for (int i = 0; i < 12; ++i) {
            float4 v = *reinterpret_cast<const float4*>(rp + i * 4);
            vals[i * 4 + 0] = v.x; vals[i * 4 + 1] = v.y;
            vals[i * 4 + 2] = v.z; vals[i * 4 + 3] = v.w;
            s += v.x + v.y + v.z + v.w;
            q += v.x * v.x + v.y * v.y + v.z * v.z + v.w * v.w;
        }
        s += __shfl_xor_sync(0xffffffffu, s, 1);
        q += __shfl_xor_sync(0xffffffffu, q, 1);
        float mean = s * (1.f / 96.f);
        float var = q * (1.f / 96.f) - mean * mean;
        float rstd = rsqrtf(var + 1e-5f);
        float* op = out2 + (size_t)(m0 + r) * 96 + half * 48;
#pragma unroll
        for (int i = 0; i < 12; ++i) {
            int c = half * 48 + i * 4;
            float4 o;
            o.x = (vals[i * 4 + 0] - mean) * rstd * lnw[c + 0] + lnb[c + 0];
            o.y = (vals[i * 4 + 1] - mean) * rstd * lnw[c + 1] + lnb[c + 1];
            o.z = (vals[i * 4 + 2] - mean) * rstd * lnw[c + 2] + lnb[c + 2];
            o.w = (vals[i * 4 + 3] - mean) * rstd * lnw[c + 3] + lnb[c + 3];
            *reinterpret_cast<float4*>(op + i * 4) = o;
        }
    }
    if constexpr (MODE == 4) {
        float (*st)[98] = reinterpret_cast<float (*)[98]>(smem_u);
        __syncthreads();
#pragma unroll
        for (int mt = 0; mt < 2; ++mt) {
            int lr0 = warp_m * 32 + mt * 16 + g;
            int r0 = m0 + lr0;
#pragma unroll
            for (int nt = 0; nt < 6; ++nt) {
                int col = warp_n * 48 + nt * 8 + 2 * tig;
                float bi0 = bias[col], bi1 = bias[col + 1];
                float2 rs0 = *reinterpret_cast<const float2*>(&res[(size_t)r0 * 96 + col]);
                float2 rs1 = *reinterpret_cast<const float2*>(&res[(size_t)(r0 + 8) * 96 + col]);
                *reinterpret_cast<float2*>(&st[lr0][col]) =
                    make_float2(acc[mt][nt][0] + bi0 + rs0.x, acc[mt][nt][1] + bi1 + rs0.y);
                *reinterpret_cast<float2*>(&st[lr0 + 8][col]) =
                    make_float2(acc[mt][nt][2] + bi0 + rs1.x, acc[mt][nt][3] + bi1 + rs1.y);
            }
        }
        __syncthreads();
        int bb = m0 / HW, hw0 = m0 % HW;
        float* ob = out + (size_t)bb * 96 * HW + hw0;
#pragma unroll
        for (int l = 0; l < 48; ++l) {
            int e = tid + l * 256;
            int ch = e >> 7, tok = e & 127;
            ob[(size_t)ch * HW + tok] = st[tok][ch];
        }
    }
}

// ---------------------------------------------------------------------------
// Kernel 3: per-window shifted attention, one CTA per 7x7 window (f32x2).
// ---------------------------------------------------------------------------
__global__ __launch_bounds__(256) void k_attn(const float* __restrict__ rel_table) {
    extern __shared__ float sm[];
    float* qs = sm;                 // 49*98
    float* ks = sm + 49 * 98;
    float* vs = sm + 2 * 49 * 98;
    float* att = sm + 3 * 49 * 98;  // 49*52
    __shared__ int tok_s[49];
    __shared__ int lbl_s[49];

    int win = blockIdx.x;
    int bb = win >> 10;
    int wr = (win >> 5) & 31;
    int wc = win & 31;
    int tid = threadIdx.x;

    if (tid < 49) {
        int i = tid / 7, j = tid % 7;
        int sr = wr * 7 + i, sc = wc * 7 + j;
        int r = sr + 3; if (r >= 224) r -= 224;
        int c = sc + 3; if (c >= 224) c -= 224;
        tok_s[tid] = bb * HW + r * 224 + c;
        int rb = (sr < 217) ? 0 : (sr < 221 ? 1 : 2);
        int cb = (sc < 217) ? 0 : (sc < 221 ? 1 : 2);
        lbl_s[tid] = rb * 3 + cb;
    }
    __syncthreads();

    for (int e = tid; e < 49 * 288; e += 256) {
        int row = e / 288, ch = e % 288;
        float v = g_qkv[(size_t)tok_s[row] * 288 + ch];
        if (ch < 96)       qs[row * 98 + ch] = v * 0.10206207261596575f;
        else if (ch < 192) ks[row * 98 + ch - 96] = v;
        else               vs[row * 98 + ch - 192] = v;
    }
    __syncthreads();

    for (int e = tid; e < 49 * 49; e += 256) {
        int i = e / 49, j = e % 49;
        const float* qp = qs + i * 98;
        const float* kp = ks + j * 98;
        unsigned long long acc = 0ull;
#pragma unroll 8
        for (int ch = 0; ch < 96; ch += 2)
            acc = fma2(ld2s(qp + ch), ld2s(kp + ch), acc);
        float2 t = unpack2(acc);
        float s = t.x + t.y;
        int idx = (i / 7 - j / 7 + 6) * 13 + (i % 7 - j % 7 + 6);
        s += rel_table[idx];
        if (lbl_s[i] != lbl_s[j]) s -= 100.0f;
        att[i * 52 + j] = s;
    }
    __syncthreads();

    int warp = tid >> 5, lane = tid & 31;
    for (int row = warp; row < 49; row += 8) {
        float x0 = att[row * 52 + lane];
        float x1 = (lane + 32 < 49) ? att[row * 52 + lane + 32] : -1e30f;
        float mx = fmaxf(x0, x1);
        for (int o = 16; o; o >>= 1) mx = fmaxf(mx, __shfl_xor_sync(0xffffffffu, mx, o));
        float e0 = expf(x0 - mx);
        float e1 = (lane + 32 < 49) ? expf(x1 - mx) : 0.f;
        float sum = e0 + e1;
        for (int o = 16; o; o >>= 1) sum += __shfl_xor_sync(0xffffffffu, sum, o);
        float inv = 1.0f / sum;
        att[row * 52 + lane] = e0 * inv;
        if (lane + 32 < 49) att[row * 52 + lane + 32] = e1 * inv;
    }
    __syncthreads();

    for (int e = tid; e < 49 * 48; e += 256) {
        int i = e / 48, chp = (e % 48) * 2;
        const float* ap = att + i * 52;
        unsigned long long acc = 0ull;
#pragma unroll 7
        for (int j = 0; j < 49; ++j) {
            float a = ap[j];
            acc = fma2(pack2(a, a), ld2s(&vs[j * 98 + chp]), acc);
        }
        float2 t = unpack2(acc);
        *reinterpret_cast<float2*>(&g_ctx[(size_t)tok_s[i] * 96 + chp]) = t;
    }
}

// ---------------------------------------------------------------------------
extern "C" void kernel_launch(void* const* d_in, const int* in_sizes, int n_in,
                              void* d_out, int out_size) {
    const float* x    = (const float*)d_in[0];
    const float* n1w  = (const float*)d_in[1];
    const float* n1b  = (const float*)d_in[2];
    const float* qkvw = (const float*)d_in[3];
    const float* qkvb = (const float*)d_in[4];
    const float* rel  = (const float*)d_in[5];
    const float* pw   = (const float*)d_in[6];
    const float* pb   = (const float*)d_in[7];
    const float* n2w  = (const float*)d_in[8];
    const float* n2b  = (const float*)d_in[9];
    const float* w1   = (const float*)d_in[10];
    const float* b1   = (const float*)d_in[11];
    const float* w2   = (const float*)d_in[12];
    const float* b2   = (const float*)d_in[13];
    float* out = (float*)d_out;

    void *p_ln1, *p_xn, *p_qkv, *p_ctx, *p_h, *p_ln2, *p_m1;
    cudaGetSymbolAddress(&p_ln1, g_ln1);
    cudaGetSymbolAddress(&p_xn,  g_xn);
    cudaGetSymbolAddress(&p_qkv, g_qkv);
    cudaGetSymbolAddress(&p_ctx, g_ctx);
    cudaGetSymbolAddress(&p_h,   g_h);
    cudaGetSymbolAddress(&p_ln2, g_ln2);
    cudaGetSymbolAddress(&p_m1,  g_m1);

    const int GEMM_SMEM = (128 + 96) * 40 * 4;            // 35840
    const int SMEM_M3 = 128 * 100 * 4;                    // 51200
    const int SMEM_M4 = 128 * 98 * 4;                     // 50176
    cudaFuncSetAttribute(k_mma<288, 96, 0>, cudaFuncAttributeMaxDynamicSharedMemorySize, GEMM_SMEM);
    cudaFuncSetAttribute(k_mma<384, 96, 2>, cudaFuncAttributeMaxDynamicSharedMemorySize, GEMM_SMEM);
    cudaFuncSetAttribute(k_mma<96, 96, 3>,  cudaFuncAttributeMaxDynamicSharedMemorySize, SMEM_M3);
    cudaFuncSetAttribute(k_mma<96, 384, 4>, cudaFuncAttributeMaxDynamicSharedMemorySize, SMEM_M4);

    const int ATTN_SMEM = (3 * 49 * 98 + 49 * 52) * 4;    // 67816 B
    cudaFuncSetAttribute(k_attn, cudaFuncAttributeMaxDynamicSharedMemorySize, ATTN_SMEM);

    // 1) NCHW->NHWC + LN1
    k_in_ln<<<12544, 256>>>(x, n1w, n1b);
    // 2) QKV
    k_mma<288, 96, 0><<<dim3(3136, 3), 256, GEMM_SMEM>>>(
        (const float*)p_ln1, qkvw, qkvb, nullptr, (float*)p_qkv, nullptr, nullptr, nullptr);
    // 3) attention
    k_attn<<<NWIN, 256, ATTN_SMEM>>>(rel);
    // 4) proj + residual + fused LN2
    k_mma<96, 96, 3><<<dim3(3136, 1), 256, SMEM_M3>>>(
        (const float*)p_ctx, pw, pb, (const float*)p_xn, (float*)p_h, n2w, n2b, (float*)p_ln2);
    // 5) MLP1 + GELU
    k_mma<384, 96, 2><<<dim3(3136, 4), 256, GEMM_SMEM>>>(
        (const float*)p_ln2, w1, b1, nullptr, (float*)p_m1, nullptr, nullptr, nullptr);
    // 6) MLP2 + residual + fused NCHW transpose -> d_out
    k_mma<96, 384, 4><<<dim3(3136, 1), 256, SMEM_M4>>>(
        (const float*)p_m1, w2, b2, (const float*)p_h, out, nullptr, nullptr, nullptr);
}

// round 4
// speedup vs baseline: 2.4978x; 1.4101x over previous
#include <cuda_runtime.h>
#include <cuda_bf16.h>
#include <math.h>

#define BATCH 8
#define HW 50176              // 224*224
#define L_TOK 401408          // 8*224*224
#define NWIN 8192

// Scratch: bf16 for GEMM inputs, fp32 for the residual stream.
__device__ __nv_bfloat16 g_ln1[(size_t)L_TOK * 96];
__device__ __nv_bfloat16 g_qkv[(size_t)L_TOK * 288];
__device__ __nv_bfloat16 g_ctx[(size_t)L_TOK * 96];
__device__ float         g_h[(size_t)L_TOK * 96];
__device__ __nv_bfloat16 g_ln2[(size_t)L_TOK * 96];
__device__ __nv_bfloat16 g_m1[(size_t)L_TOK * 384];

// ---- helpers --------------------------------------------------------------
__device__ __forceinline__ unsigned long long fma2(unsigned long long a,
                                                   unsigned long long b,
                                                   unsigned long long c) {
    unsigned long long d;
    asm("fma.rn.f32x2 %0, %1, %2, %3;" : "=l"(d) : "l"(a), "l"(b), "l"(c));
    return d;
}
__device__ __forceinline__ unsigned long long pack2(float lo, float hi) {
    unsigned long long r;
    asm("mov.b64 %0, {%1, %2};" : "=l"(r) : "f"(lo), "f"(hi));
    return r;
}
__device__ __forceinline__ unsigned long long ld2s(const float* p) {
    float2 t = *reinterpret_cast<const float2*>(p);
    return pack2(t.x, t.y);
}
__device__ __forceinline__ float2 unpack2(unsigned long long v) {
    float2 t;
    asm("mov.b64 {%0, %1}, %2;" : "=f"(t.x), "=f"(t.y) : "l"(v));
    return t;
}
__device__ __forceinline__ unsigned bf2u(float a, float b) {
    __nv_bfloat162 h = __floats2bfloat162_rn(a, b);
    return *reinterpret_cast<unsigned*>(&h);
}
__device__ __forceinline__ void mma16(float* c, const unsigned* a,
                                      unsigned b0, unsigned b1) {
    asm("mma.sync.aligned.m16n8k16.row.col.f32.bf16.bf16.f32 "
        "{%0,%1,%2,%3}, {%4,%5,%6,%7}, {%8,%9}, {%0,%1,%2,%3};"
        : "+f"(c[0]), "+f"(c[1]), "+f"(c[2]), "+f"(c[3])
        : "r"(a[0]), "r"(a[1]), "r"(a[2]), "r"(a[3]), "r"(b0), "r"(b1));
}

// ---------------------------------------------------------------------------
// Kernel 1: NCHW -> NHWC + LayerNorm1 -> bf16 ln1.
// ---------------------------------------------------------------------------
__global__ __launch_bounds__(256) void k_in_ln(const float* __restrict__ x,
                                               const float* __restrict__ w,
                                               const float* __restrict__ b) {
    __shared__ float s[96][33];
    __shared__ float mu_s[32], rs_s[32];
    int tile = blockIdx.x;
    int bb = tile / 1568;
    int t0 = (tile % 1568) * 32;
    int tid = threadIdx.x;

    const float* xb = x + (size_t)bb * 96 * HW + t0;
#pragma unroll
    for (int l = 0; l < 12; ++l) {
        int e = tid + l * 256;
        int ch = e >> 5, tl = e & 31;
        s[ch][tl] = xb[(size_t)ch * HW + tl];
    }
    __syncthreads();

    int tok = tid >> 3, sub = tid & 7;
    float acc = 0.f;
#pragma unroll
    for (int k = 0; k < 12; ++k) acc += s[sub + 8 * k][tok];
    acc += __shfl_down_sync(0xffffffffu, acc, 4);
    acc += __shfl_down_sync(0xffffffffu, acc, 2);
    acc += __shfl_down_sync(0xffffffffu, acc, 1);
    float mean = __shfl_sync(0xffffffffu, acc, (tid & 31) & ~7) * (1.f / 96.f);
    float vv = 0.f;
#pragma unroll
    for (int k = 0; k < 12; ++k) {
        float d = s[sub + 8 * k][tok] - mean;
        vv += d * d;
    }
    vv += __shfl_down_sync(0xffffffffu, vv, 4);
    vv += __shfl_down_sync(0xffffffffu, vv, 2);
    vv += __shfl_down_sync(0xffffffffu, vv, 1);
    float var = __shfl_sync(0xffffffffu, vv, (tid & 31) & ~7) * (1.f / 96.f);
    if (sub == 0) { mu_s[tok] = mean; rs_s[tok] = rsqrtf(var + 1e-5f); }
    __syncthreads();

    size_t base = ((size_t)bb * HW + t0) * 96;
#pragma unroll
    for (int l = 0; l < 12; ++l) {
        int e = tid + l * 256;
        int tk = e / 96, ch = e % 96;
        float val = s[ch][tk];
        g_ln1[base + e] = __float2bfloat16((val - mu_s[tk]) * rs_s[tk] * w[ch] + b[ch]);
    }
}

// ---------------------------------------------------------------------------
// bf16 tensor-core GEMM: out[M,N] = A[M,K](bf16) @ W[N,K](fp32->bf16)^T
// BM=128, BN=96, BK=32 halves. 8 warps 4(M)x2(N); warp tile 32x48.
// MODE 0: +bias -> bf16 out                         (QKV)
// MODE 2: +bias, GELU -> bf16 out                   (MLP1)
// MODE 3: +bias; LN pass adds NCHW x residual ->
//         fp32 h (outv) + bf16 ln2 (out2)           (proj)
// MODE 4: +bias +fp32 res -> NCHW fp32 store        (MLP2, final)
// ---------------------------------------------------------------------------
template <int N, int K, int MODE>
__global__ __launch_bounds__(256) void k_mma(const __nv_bfloat16* __restrict__ A,
                                             const float* __restrict__ W,
                                             const float* __restrict__ bias,
                                             const float* __restrict__ res,
                                             void* __restrict__ outv,
                                             const float* __restrict__ lnw,
                                             const float* __restrict__ lnb,
                                             __nv_bfloat16* __restrict__ out2) {
    extern __shared__ unsigned smem_u[];
    unsigned (*As)[20] = reinterpret_cast<unsigned (*)[20]>(smem_u);             // 128 rows x 32 halves
    unsigned (*Bs)[20] = reinterpret_cast<unsigned (*)[20]>(smem_u + 128 * 20);  // 96 rows x 32 halves

    int tid = threadIdx.x;
    int lane = tid & 31, warp = tid >> 5;
    int warp_m = warp & 3, warp_n = warp >> 2;
    int g = lane >> 2, tig = lane & 3;
    int m0 = blockIdx.x * 128, n0 = blockIdx.y * 96;

    float acc[2][6][4];
#pragma unroll
    for (int mt = 0; mt < 2; ++mt)
#pragma unroll
        for (int nt = 0; nt < 6; ++nt)
#pragma unroll
            for (int q = 0; q < 4; ++q) acc[mt][nt][q] = 0.f;

    for (int k0 = 0; k0 < K; k0 += 32) {
        if (k0) __syncthreads();
        // A tile: 128 rows x 32 halves; int4 = 8 halves.
#pragma unroll
        for (int l = 0; l < 2; ++l) {
            int o = tid + l * 256;
            int row = o >> 2, chunk = o & 3;
            int4 v = *reinterpret_cast<const int4*>(
                A + (size_t)(m0 + row) * K + k0 + chunk * 8);
            unsigned* d = &As[row][chunk * 4];
            d[0] = v.x; d[1] = v.y; d[2] = v.z; d[3] = v.w;
        }
        // B tile: 96 rows x 32 floats -> bf16.
        for (int o = tid; o < 768; o += 256) {
            int row = o >> 3, chunk = o & 7;
            float4 v = *reinterpret_cast<const float4*>(
                W + (size_t)(n0 + row) * K + k0 + chunk * 4);
            Bs[row][chunk * 2]     = bf2u(v.x, v.y);
            Bs[row][chunk * 2 + 1] = bf2u(v.z, v.w);
        }
        __syncthreads();
#pragma unroll
        for (int ks = 0; ks < 2; ++ks) {
            unsigned a[2][4];
#pragma unroll
            for (int mt = 0; mt < 2; ++mt) {
                int r = warp_m * 32 + mt * 16 + g;
                a[mt][0] = As[r][ks * 8 + tig];
                a[mt][2] = As[r][ks * 8 + tig + 4];
                a[mt][1] = As[r + 8][ks * 8 + tig];
                a[mt][3] = As[r + 8][ks * 8 + tig + 4];
            }
#pragma unroll
            for (int nt = 0; nt < 6; ++nt) {
                int cb = warp_n * 48 + nt * 8 + g;
                unsigned b0 = Bs[cb][ks * 8 + tig];
                unsigned b1 = Bs[cb][ks * 8 + tig + 4];
#pragma unroll
                for (int mt = 0; mt < 2; ++mt)
                    mma16(acc[mt][nt], a[mt], b0, b1);
            }
        }
    }

    // ---- epilogues --------------------------------------------------------
    if constexpr (MODE == 0 || MODE == 2) {
        __nv_bfloat16* out = reinterpret_cast<__nv_bfloat16*>(outv);
#pragma unroll
        for (int mt = 0; mt < 2; ++mt) {
            int r0 = m0 + warp_m * 32 + mt * 16 + g;
#pragma unroll
            for (int nt = 0; nt < 6; ++nt) {
                int col = n0 + warp_n * 48 + nt * 8 + 2 * tig;
                float bi0 = bias[col], bi1 = bias[col + 1];
                float v0 = acc[mt][nt][0] + bi0, v1 = acc[mt][nt][1] + bi1;
                float v2 = acc[mt][nt][2] + bi0, v3 = acc[mt][nt][3] + bi1;
                if (MODE == 2) {
                    v0 = 0.5f * v0 * (1.0f + erff(v0 * 0.70710678118654752f));
                    v1 = 0.5f * v1 * (1.0f + erff(v1 * 0.70710678118654752f));
                    v2 = 0.5f * v2 * (1.0f + erff(v2 * 0.70710678118654752f));
                    v3 = 0.5f * v3 * (1.0f + erff(v3 * 0.70710678118654752f));
                }
                *reinterpret_cast<unsigned*>(&out[(size_t)r0 * N + col]) = bf2u(v0, v1);
                *reinterpret_cast<unsigned*>(&out[(size_t)(r0 + 8) * N + col]) = bf2u(v2, v3);
            }
        }
    }
    if constexpr (MODE == 3) {
        float* hout = reinterpret_cast<float*>(outv);
        float (*st)[100] = reinterpret_cast<float (*)[100]>(smem_u);
        __syncthreads();
#pragma unroll
        for (int mt = 0; mt < 2; ++mt) {
            int lr0 = warp_m * 32 + mt * 16 + g;
#pragma unroll
            for (int nt = 0; nt < 6; ++nt) {
                int col = warp_n * 48 + nt * 8 + 2 * tig;
                float bi0 = bias[col], bi1 = bias[col + 1];
                st[lr0][col]         = acc[mt][nt][0] + bi0;
                st[lr0][col + 1]     = acc[mt][nt][1] + bi1;
                st[lr0 + 8][col]     = acc[mt][nt][2] + bi0;
                st[lr0 + 8][col + 1] = acc[mt][nt][3] + bi1;
            }
        }
        __syncthreads();
        // LN pass: 2 threads per token row; residual read directly from NCHW x.
        int r = tid >> 1, half = tid & 1;
        int bb = m0 / HW, hw0 = m0 % HW;
        const float* xb = res + (size_t)bb * 96 * HW + hw0 + r;
        float vals[48];
        float s = 0.f, q = 0.f;
#pragma unroll
        for (int i = 0; i < 12; ++i) {
            float4 v = *reinterpret_cast<const float4*>(&st[r][half * 48 + i * 4]);
            float h0 = v.x + xb[(size_t)(half * 48 + i * 4 + 0) * HW];
            float h1 = v.y + xb[(size_t)(half * 48 + i * 4 + 1) * HW];
            float h2 = v.z + xb[(size_t)(half * 48 + i * 4 + 2) * HW];
            float h3 = v.w + xb[(size_t)(half * 48 + i * 4 + 3) * HW];
            vals[i * 4 + 0] = h0; vals[i * 4 + 1] = h1;
            vals[i * 4 + 2] = h2; vals[i * 4 + 3] = h3;
            s += h0 + h1 + h2 + h3;
            q += h0 * h0 + h1 * h1 + h2 * h2 + h3 * h3;
        }
        s += __shfl_xor_sync(0xffffffffu, s, 1);
        q += __shfl_xor_sync(0xffffffffu, q, 1);
        float mean = s * (1.f / 96.f);
        float var = q * (1.f / 96.f) - mean * mean;
        float rstd = rsqrtf(var + 1e-5f);
        float* hp = hout + (size_t)(m0 + r) * 96 + half * 48;
        __nv_bfloat16* lp = out2 + (size_t)(m0 + r) * 96 + half * 48;
#pragma unroll
        for (int i = 0; i < 12; ++i) {
            int c = half * 48 + i * 4;
            *reinterpret_cast<float4*>(hp + i * 4) =
                make_float4(vals[i * 4], vals[i * 4 + 1], vals[i * 4 + 2], vals[i * 4 + 3]);
            unsigned u0 = bf2u((vals[i * 4 + 0] - mean) * rstd * lnw[c + 0] + lnb[c + 0],
                               (vals[i * 4 + 1] - mean) * rstd * lnw[c + 1] + lnb[c + 1]);
            unsigned u1 = bf2u((vals[i * 4 + 2] - mean) * rstd * lnw[c + 2] + lnb[c + 2],
                               (vals[i * 4 + 3] - mean) * rstd * lnw[c + 3] + lnb[c + 3]);
            uint2 uu; uu.x = u0; uu.y = u1;
            *reinterpret_cast<uint2*>(lp + i * 4) = uu;
        }
    }
    if constexpr (MODE == 4) {
        float* out = reinterpret_cast<float*>(outv);
        float (*st)[98] = reinterpret_cast<float (*)[98]>(smem_u);
        __syncthreads();
#pragma unroll
        for (int mt = 0; mt < 2; ++mt) {
            int lr0 = warp_m * 32 + mt * 16 + g;
            int r0 = m0 + lr0;
#pragma unroll
            for (int nt = 0; nt < 6; ++nt) {
                int col = warp_n * 48 + nt * 8 + 2 * tig;
                float bi0 = bias[col], bi1 = bias[col + 1];
                float2 rs0 = *reinterpret_cast<const float2*>(&res[(size_t)r0 * 96 + col]);
                float2 rs1 = *reinterpret_cast<const float2*>(&res[(size_t)(r0 + 8) * 96 + col]);
                *reinterpret_cast<float2*>(&st[lr0][col]) =
                    make_float2(acc[mt][nt][0] + bi0 + rs0.x, acc[mt][nt][1] + bi1 + rs0.y);
                *reinterpret_cast<float2*>(&st[lr0 + 8][col]) =
                    make_float2(acc[mt][nt][2] + bi0 + rs1.x, acc[mt][nt][3] + bi1 + rs1.y);
            }
        }
        __syncthreads();
        int bb = m0 / HW, hw0 = m0 % HW;
        float* ob = out + (size_t)bb * 96 * HW + hw0;
#pragma unroll
        for (int l = 0; l < 48; ++l) {
            int e = tid + l * 256;
            int ch = e >> 7, tok = e & 127;
            ob[(size_t)ch * HW + tok] = st[tok][ch];
        }
    }
}

// ---------------------------------------------------------------------------
// Kernel 3: per-window shifted attention (bf16 qkv in, bf16 ctx out).
// ---------------------------------------------------------------------------
__global__ __launch_bounds__(256) void k_attn(const float* __restrict__ rel_table) {
    extern __shared__ float sm[];
    float* qs = sm;                 // 49*98
    float* ks = sm + 49 * 98;
    float* vs = sm + 2 * 49 * 98;
    float* att = sm + 3 * 49 * 98;  // 49*52
    __shared__ int tok_s[49];
    __shared__ int lbl_s[49];

    int win = blockIdx.x;
    int bb = win >> 10;
    int wr = (win >> 5) & 31;
    int wc = win & 31;
    int tid = threadIdx.x;

    if (tid < 49) {
        int i = tid / 7, j = tid % 7;
        int sr = wr * 7 + i, sc = wc * 7 + j;
        int r = sr + 3; if (r >= 224) r -= 224;
        int c = sc + 3; if (c >= 224) c -= 224;
        tok_s[tid] = bb * HW + r * 224 + c;
        int rb = (sr < 217) ? 0 : (sr < 221 ? 1 : 2);
        int cb = (sc < 217) ? 0 : (sc < 221 ? 1 : 2);
        lbl_s[tid] = rb * 3 + cb;
    }
    __syncthreads();

    // gather: 4 bf16 per uint2 access
    for (int e = tid; e < 49 * 72; e += 256) {
        int row = e / 72, c4 = (e % 72) * 4;
        const __nv_bfloat162* p = reinterpret_cast<const __nv_bfloat162*>(
            g_qkv + (size_t)tok_s[row] * 288 + c4);
        float2 f0 = __bfloat1622float2(p[0]);
        float2 f1 = __bfloat1622float2(p[1]);
        float* dst;
        int cc;
        if (c4 < 96)       { dst = qs; cc = c4;
                             f0.x *= 0.10206207261596575f; f0.y *= 0.10206207261596575f;
                             f1.x *= 0.10206207261596575f; f1.y *= 0.10206207261596575f; }
        else if (c4 < 192) { dst = ks; cc = c4 - 96; }
        else               { dst = vs; cc = c4 - 192; }
        dst[row * 98 + cc]     = f0.x;
        dst[row * 98 + cc + 1] = f0.y;
        dst[row * 98 + cc + 2] = f1.x;
        dst[row * 98 + cc + 3] = f1.y;
    }
    __syncthreads();

    for (int e = tid; e < 49 * 49; e += 256) {
        int i = e / 49, j = e % 49;
        const float* qp = qs + i * 98;
        const float* kp = ks + j * 98;
        unsigned long long acc = 0ull;
#pragma unroll 8
        for (int ch = 0; ch < 96; ch += 2)
            acc = fma2(ld2s(qp + ch), ld2s(kp + ch), acc);
        float2 t = unpack2(acc);
        float s = t.x + t.y;
        int idx = (i / 7 - j / 7 + 6) * 13 + (i % 7 - j % 7 + 6);
        s += rel_table[idx];
        if (lbl_s[i] != lbl_s[j]) s -= 100.0f;
        att[i * 52 + j] = s;
    }
    __syncthreads();

    int warp = tid >> 5, lane = tid & 31;
    for (int row = warp; row < 49; row += 8) {
        float x0 = att[row * 52 + lane];
        float x1 = (lane + 32 < 49) ? att[row * 52 + lane + 32] : -1e30f;
        float mx = fmaxf(x0, x1);
        for (int o = 16; o; o >>= 1) mx = fmaxf(mx, __shfl_xor_sync(0xffffffffu, mx, o));
        float e0 = expf(x0 - mx);
        float e1 = (lane + 32 < 49) ? expf(x1 - mx) : 0.f;
        float sum = e0 + e1;
        for (int o = 16; o; o >>= 1) sum += __shfl_xor_sync(0xffffffffu, sum, o);
        float inv = 1.0f / sum;
        att[row * 52 + lane] = e0 * inv;
        if (lane + 32 < 49) att[row * 52 + lane + 32] = e1 * inv;
    }
    __syncthreads();

    for (int e = tid; e < 49 * 48; e += 256) {
        int i = e / 48, chp = (e % 48) * 2;
        const float* ap = att + i * 52;
        unsigned long long acc = 0ull;
#pragma unroll 7
        for (int j = 0; j < 49; ++j) {
            float a = ap[j];
            acc = fma2(pack2(a, a), ld2s(&vs[j * 98 + chp]), acc);
        }
        float2 t = unpack2(acc);
        *reinterpret_cast<unsigned*>(&g_ctx[(size_t)tok_s[i] * 96 + chp]) = bf2u(t.x, t.y);
    }
}

// ---------------------------------------------------------------------------
extern "C" void kernel_launch(void* const* d_in, const int* in_sizes, int n_in,
                              void* d_out, int out_size) {
    const float* x    = (const float*)d_in[0];
    const float* n1w  = (const float*)d_in[1];
    const float* n1b  = (const float*)d_in[2];
    const float* qkvw = (const float*)d_in[3];
    const float* qkvb = (const float*)d_in[4];
    const float* rel  = (const float*)d_in[5];
    const float* pw   = (const float*)d_in[6];
    const float* pb   = (const float*)d_in[7];
    const float* n2w  = (const float*)d_in[8];
    const float* n2b  = (const float*)d_in[9];
    const float* w1   = (const float*)d_in[10];
    const float* b1   = (const float*)d_in[11];
    const float* w2   = (const float*)d_in[12];
    const float* b2   = (const float*)d_in[13];
    float* out = (float*)d_out;

    void *p_ln1, *p_qkv, *p_ctx, *p_h, *p_ln2, *p_m1;
    cudaGetSymbolAddress(&p_ln1, g_ln1);
    cudaGetSymbolAddress(&p_qkv, g_qkv);
    cudaGetSymbolAddress(&p_ctx, g_ctx);
    cudaGetSymbolAddress(&p_h,   g_h);
    cudaGetSymbolAddress(&p_ln2, g_ln2);
    cudaGetSymbolAddress(&p_m1,  g_m1);

    const int GEMM_SMEM = (128 + 96) * 20 * 4;   // 17920
    const int SMEM_M3 = 128 * 100 * 4;           // 51200
    const int SMEM_M4 = 128 * 98 * 4;            // 50176
    cudaFuncSetAttribute(k_mma<288, 96, 0>, cudaFuncAttributeMaxDynamicSharedMemorySize, GEMM_SMEM);
    cudaFuncSetAttribute(k_mma<384, 96, 2>, cudaFuncAttributeMaxDynamicSharedMemorySize, GEMM_SMEM);
    cudaFuncSetAttribute(k_mma<96, 96, 3>,  cudaFuncAttributeMaxDynamicSharedMemorySize, SMEM_M3);
    cudaFuncSetAttribute(k_mma<96, 384, 4>, cudaFuncAttributeMaxDynamicSharedMemorySize, SMEM_M4);

    const int ATTN_SMEM = (3 * 49 * 98 + 49 * 52) * 4;   // 67816
    cudaFuncSetAttribute(k_attn, cudaFuncAttributeMaxDynamicSharedMemorySize, ATTN_SMEM);

    // 1) NCHW->NHWC + LN1 (bf16)
    k_in_ln<<<12544, 256>>>(x, n1w, n1b);
    // 2) QKV (bf16 out)
    k_mma<288, 96, 0><<<dim3(3136, 3), 256, GEMM_SMEM>>>(
        (const __nv_bfloat16*)p_ln1, qkvw, qkvb, nullptr, p_qkv, nullptr, nullptr, nullptr);
    // 3) attention
    k_attn<<<NWIN, 256, ATTN_SMEM>>>(rel);
    // 4) proj + x residual (direct NCHW read) + fused LN2
    k_mma<96, 96, 3><<<dim3(3136, 1), 256, SMEM_M3>>>(
        (const __nv_bfloat16*)p_ctx, pw, pb, x, p_h, n2w, n2b, (__nv_bfloat16*)p_ln2);
    // 5) MLP1 + GELU (bf16 out)
    k_mma<384, 96, 2><<<dim3(3136, 4), 256, GEMM_SMEM>>>(
        (const __nv_bfloat16*)p_ln2, w1, b1, nullptr, p_m1, nullptr, nullptr, nullptr);
    // 6) MLP2 + h residual + fused NCHW transpose -> d_out
    k_mma<96, 384, 4><<<dim3(3136, 1), 256, SMEM_M4>>>(
        (const __nv_bfloat16*)p_m1, w2, b2, (const float*)p_h, out, nullptr, nullptr, nullptr);
}

// round 5
// speedup vs baseline: 4.5527x; 1.8227x over previous
#include <cuda_runtime.h>
#include <cuda_bf16.h>
#include <math.h>

#define HW 50176              // 224*224
#define L_TOK 401408          // 8*224*224
#define NWIN 8192

// Scratch
__device__ __nv_bfloat16 g_ln1[(size_t)L_TOK * 96];
__device__ __nv_bfloat16 g_qkv[(size_t)L_TOK * 288];
__device__ __nv_bfloat16 g_ctx[(size_t)L_TOK * 96];
__device__ float         g_h[(size_t)L_TOK * 96];
__device__ __nv_bfloat16 g_ln2[(size_t)L_TOK * 96];
__device__ __nv_bfloat16 g_m1[(size_t)L_TOK * 384];
// bf16 weights
__device__ __nv_bfloat16 g_bwq[288 * 96];
__device__ __nv_bfloat16 g_bwp[96 * 96];
__device__ __nv_bfloat16 g_bw1[384 * 96];
__device__ __nv_bfloat16 g_bw2[96 * 384];

// ---- helpers --------------------------------------------------------------
__device__ __forceinline__ unsigned bf2u(float a, float b) {
    __nv_bfloat162 h = __floats2bfloat162_rn(a, b);
    return *reinterpret_cast<unsigned*>(&h);
}
__device__ __forceinline__ void mma16(float* c, const unsigned* a,
                                      unsigned b0, unsigned b1) {
    asm("mma.sync.aligned.m16n8k16.row.col.f32.bf16.bf16.f32 "
        "{%0,%1,%2,%3}, {%4,%5,%6,%7}, {%8,%9}, {%0,%1,%2,%3};"
        : "+f"(c[0]), "+f"(c[1]), "+f"(c[2]), "+f"(c[3])
        : "r"(a[0]), "r"(a[1]), "r"(a[2]), "r"(a[3]), "r"(b0), "r"(b1));
}
__device__ __forceinline__ unsigned s2u(const void* p) {
    return (unsigned)__cvta_generic_to_shared(p);
}
__device__ __forceinline__ void cp16(unsigned dst, const void* src) {
    asm volatile("cp.async.cg.shared.global [%0], [%1], 16;" :: "r"(dst), "l"(src));
}
#define CP_COMMIT() asm volatile("cp.async.commit_group;")
#define CP_WAIT0()  asm volatile("cp.async.wait_group 0;")
#define CP_WAIT1()  asm volatile("cp.async.wait_group 1;")

// ---------------------------------------------------------------------------
// Kernel 0: weights fp32 -> bf16
// ---------------------------------------------------------------------------
__global__ __launch_bounds__(256) void k_prep(const float* __restrict__ qkvw,
                                              const float* __restrict__ pw,
                                              const float* __restrict__ w1,
                                              const float* __restrict__ w2) {
    int i = blockIdx.x * 256 + threadIdx.x;   // 110592 total
    if (i < 27648)       g_bwq[i] = __float2bfloat16(qkvw[i]);
    else if (i < 36864)  g_bwp[i - 27648] = __float2bfloat16(pw[i - 27648]);
    else if (i < 73728)  g_bw1[i - 36864] = __float2bfloat16(w1[i - 36864]);
    else                 g_bw2[i - 73728] = __float2bfloat16(w2[i - 73728]);
}

// ---------------------------------------------------------------------------
// Kernel 1: NCHW -> NHWC + LayerNorm1 -> bf16
// ---------------------------------------------------------------------------
__global__ __launch_bounds__(256) void k_in_ln(const float* __restrict__ x,
                                               const float* __restrict__ w,
                                               const float* __restrict__ b) {
    __shared__ float s[96][33];
    __shared__ float mu_s[32], rs_s[32];
    int tile = blockIdx.x;
    int bb = tile / 1568;
    int t0 = (tile % 1568) * 32;
    int tid = threadIdx.x;

    const float* xb = x + (size_t)bb * 96 * HW + t0;
#pragma unroll
    for (int l = 0; l < 12; ++l) {
        int e = tid + l * 256;
        int ch = e >> 5, tl = e & 31;
        s[ch][tl] = xb[(size_t)ch * HW + tl];
    }
    __syncthreads();

    int tok = tid >> 3, sub = tid & 7;
    float acc = 0.f;
#pragma unroll
    for (int k = 0; k < 12; ++k) acc += s[sub + 8 * k][tok];
    acc += __shfl_down_sync(0xffffffffu, acc, 4);
    acc += __shfl_down_sync(0xffffffffu, acc, 2);
    acc += __shfl_down_sync(0xffffffffu, acc, 1);
    float mean = __shfl_sync(0xffffffffu, acc, (tid & 31) & ~7) * (1.f / 96.f);
    float vv = 0.f;
#pragma unroll
    for (int k = 0; k < 12; ++k) {
        float d = s[sub + 8 * k][tok] - mean;
        vv += d * d;
    }
    vv += __shfl_down_sync(0xffffffffu, vv, 4);
    vv += __shfl_down_sync(0xffffffffu, vv, 2);
    vv += __shfl_down_sync(0xffffffffu, vv, 1);
    float var = __shfl_sync(0xffffffffu, vv, (tid & 31) & ~7) * (1.f / 96.f);
    if (sub == 0) { mu_s[tok] = mean; rs_s[tok] = rsqrtf(var + 1e-5f); }
    __syncthreads();

    size_t base = ((size_t)bb * HW + t0) * 96;
#pragma unroll
    for (int l = 0; l < 12; ++l) {
        int e = tid + l * 256;
        int tk = e / 96, ch = e % 96;
        float val = s[ch][tk];
        g_ln1[base + e] = __float2bfloat16((val - mu_s[tk]) * rs_s[tk] * w[ch] + b[ch]);
    }
}

// ---------------------------------------------------------------------------
// K=96 GEMM, full-K cp.async prefetch. BM=128, BN=96.
// A rows padded to 104 halves (208B); conflict-free fragment banks.
// MODE 0: +bias -> bf16     MODE 2: +bias +GELU -> bf16
// MODE 3: +bias; +NCHW x residual -> fp32 h + bf16 ln2
// ---------------------------------------------------------------------------
template <int N, int MODE>
__global__ __launch_bounds__(256) void k_mma96(const __nv_bfloat16* __restrict__ A,
                                               const __nv_bfloat16* __restrict__ W,
                                               const float* __restrict__ bias,
                                               const float* __restrict__ res,
                                               void* __restrict__ outv,
                                               const float* __restrict__ lnw,
                                               const float* __restrict__ lnb,
                                               __nv_bfloat16* __restrict__ out2) {
    extern __shared__ unsigned smem_u[];
    int tid = threadIdx.x;
    int lane = tid & 31, warp = tid >> 5;
    int warp_m = warp & 3, warp_n = warp >> 2;
    int g = lane >> 2, tig = lane & 3;
    int m0 = blockIdx.x * 128, n0 = blockIdx.y * 96;

    unsigned sbase = s2u(smem_u);
    // A: 128 rows x 12 chunks of 16B, row stride 208B (52 unsigneds)
#pragma unroll
    for (int l = 0; l < 6; ++l) {
        int o = tid + l * 256;
        int row = o / 12, ch = o % 12;
        cp16(sbase + row * 208 + ch * 16, A + (size_t)(m0 + row) * 96 + ch * 8);
    }
    // B: 96 rows x 12 chunks at byte offset 26624
#pragma unroll
    for (int l = 0; l < 5; ++l) {
        int o = tid + l * 256;
        if (o < 1152) {
            int row = o / 12, ch = o % 12;
            cp16(sbase + 26624 + row * 208 + ch * 16, W + (size_t)(n0 + row) * 96 + ch * 8);
        }
    }
    CP_COMMIT();

    float acc[2][6][4];
#pragma unroll
    for (int mt = 0; mt < 2; ++mt)
#pragma unroll
        for (int nt = 0; nt < 6; ++nt)
#pragma unroll
            for (int q = 0; q < 4; ++q) acc[mt][nt][q] = 0.f;

    CP_WAIT0();
    __syncthreads();

    const unsigned* AsU = smem_u;
    const unsigned* BsU = smem_u + 6656;
#pragma unroll
    for (int ks = 0; ks < 6; ++ks) {
        unsigned a[2][4];
#pragma unroll
        for (int mt = 0; mt < 2; ++mt) {
            int r = warp_m * 32 + mt * 16 + g;
            a[mt][0] = AsU[r * 52 + ks * 8 + tig];
            a[mt][2] = AsU[r * 52 + ks * 8 + tig + 4];
            a[mt][1] = AsU[(r + 8) * 52 + ks * 8 + tig];
            a[mt][3] = AsU[(r + 8) * 52 + ks * 8 + tig + 4];
        }
#pragma unroll
        for (int nt = 0; nt < 6; ++nt) {
            int cb = warp_n * 48 + nt * 8 + g;
            unsigned b0 = BsU[cb * 52 + ks * 8 + tig];
            unsigned b1 = BsU[cb * 52 + ks * 8 + tig + 4];
#pragma unroll
            for (int mt = 0; mt < 2; ++mt)
                mma16(acc[mt][nt], a[mt], b0, b1);
        }
    }

    if constexpr (MODE == 0 || MODE == 2) {
        __nv_bfloat16* out = reinterpret_cast<__nv_bfloat16*>(outv);
#pragma unroll
        for (int mt = 0; mt < 2; ++mt) {
            int r0 = m0 + warp_m * 32 + mt * 16 + g;
#pragma unroll
            for (int nt = 0; nt < 6; ++nt) {
                int col = n0 + warp_n * 48 + nt * 8 + 2 * tig;
                float bi0 = bias[col], bi1 = bias[col + 1];
                float v0 = acc[mt][nt][0] + bi0, v1 = acc[mt][nt][1] + bi1;
                float v2 = acc[mt][nt][2] + bi0, v3 = acc[mt][nt][3] + bi1;
                if (MODE == 2) {
                    v0 = 0.5f * v0 * (1.0f + erff(v0 * 0.70710678118654752f));
                    v1 = 0.5f * v1 * (1.0f + erff(v1 * 0.70710678118654752f));
                    v2 = 0.5f * v2 * (1.0f + erff(v2 * 0.70710678118654752f));
                    v3 = 0.5f * v3 * (1.0f + erff(v3 * 0.70710678118654752f));
                }
                *reinterpret_cast<unsigned*>(&out[(size_t)r0 * N + col]) = bf2u(v0, v1);
                *reinterpret_cast<unsigned*>(&out[(size_t)(r0 + 8) * N + col]) = bf2u(v2, v3);
            }
        }
    }
    if constexpr (MODE == 3) {
        float* hout = reinterpret_cast<float*>(outv);
        float (*st)[100] = reinterpret_cast<float (*)[100]>(smem_u);
        __syncthreads();
#pragma unroll
        for (int mt = 0; mt < 2; ++mt) {
            int lr0 = warp_m * 32 + mt * 16 + g;
#pragma unroll
            for (int nt = 0; nt < 6; ++nt) {
                int col = warp_n * 48 + nt * 8 + 2 * tig;
                float bi0 = bias[col], bi1 = bias[col + 1];
                st[lr0][col]         = acc[mt][nt][0] + bi0;
                st[lr0][col + 1]     = acc[mt][nt][1] + bi1;
                st[lr0 + 8][col]     = acc[mt][nt][2] + bi0;
                st[lr0 + 8][col + 1] = acc[mt][nt][3] + bi1;
            }
        }
        __syncthreads();
        int r = tid >> 1, half = tid & 1;
        int bb = m0 / HW, hw0 = m0 % HW;
        const float* xb = res + (size_t)bb * 96 * HW + hw0 + r;
        float vals[48];
        float s = 0.f, q = 0.f;
#pragma unroll
        for (int i = 0; i < 12; ++i) {
            float4 v = *reinterpret_cast<const float4*>(&st[r][half * 48 + i * 4]);
            float h0 = v.x + xb[(size_t)(half * 48 + i * 4 + 0) * HW];
            float h1 = v.y + xb[(size_t)(half * 48 + i * 4 + 1) * HW];
            float h2 = v.z + xb[(size_t)(half * 48 + i * 4 + 2) * HW];
            float h3 = v.w + xb[(size_t)(half * 48 + i * 4 + 3) * HW];
            vals[i * 4 + 0] = h0; vals[i * 4 + 1] = h1;
            vals[i * 4 + 2] = h2; vals[i * 4 + 3] = h3;
            s += h0 + h1 + h2 + h3;
            q += h0 * h0 + h1 * h1 + h2 * h2 + h3 * h3;
        }
        s += __shfl_xor_sync(0xffffffffu, s, 1);
        q += __shfl_xor_sync(0xffffffffu, q, 1);
        float mean = s * (1.f / 96.f);
        float var = q * (1.f / 96.f) - mean * mean;
        float rstd = rsqrtf(var + 1e-5f);
        float* hp = hout + (size_t)(m0 + r) * 96 + half * 48;
        __nv_bfloat16* lp = out2 + (size_t)(m0 + r) * 96 + half * 48;
#pragma unroll
        for (int i = 0; i < 12; ++i) {
            int c = half * 48 + i * 4;
            *reinterpret_cast<float4*>(hp + i * 4) =
                make_float4(vals[i * 4], vals[i * 4 + 1], vals[i * 4 + 2], vals[i * 4 + 3]);
            uint2 uu;
            uu.x = bf2u((vals[i * 4 + 0] - mean) * rstd * lnw[c + 0] + lnb[c + 0],
                        (vals[i * 4 + 1] - mean) * rstd * lnw[c + 1] + lnb[c + 1]);
            uu.y = bf2u((vals[i * 4 + 2] - mean) * rstd * lnw[c + 2] + lnb[c + 2],
                        (vals[i * 4 + 3] - mean) * rstd * lnw[c + 3] + lnb[c + 3]);
            *reinterpret_cast<uint2*>(lp + i * 4) = uu;
        }
    }
}

// ---------------------------------------------------------------------------
// K=384 GEMM (MLP2), 2-stage cp.async ring (BK=64). N=96.
// +bias +fp32 res, NCHW transposed fp32 store.
// ---------------------------------------------------------------------------
__global__ __launch_bounds__(256) void k_mma384(const __nv_bfloat16* __restrict__ A,
                                                const __nv_bfloat16* __restrict__ W,
                                                const float* __restrict__ bias,
                                                const float* __restrict__ res,
                                                float* __restrict__ out) {
    extern __shared__ unsigned smem_u[];
    int tid = threadIdx.x;
    int lane = tid & 31, warp = tid >> 5;
    int warp_m = warp & 3, warp_n = warp >> 2;
    int g = lane >> 2, tig = lane & 3;
    int m0 = blockIdx.x * 128;

    unsigned sbase = s2u(smem_u);
    // stage layout (bytes): A0@0, A1@18432, B0@36864, B1@50688; row stride 144B (36u)
    auto load_stage = [&](int s, int k0) {
#pragma unroll
        for (int l = 0; l < 4; ++l) {
            int o = tid + l * 256;
            int row = o >> 3, ch = o & 7;
            cp16(sbase + s * 18432 + row * 144 + ch * 16,
                 A + (size_t)(m0 + row) * 384 + k0 + ch * 8);
        }
#pragma unroll
        for (int l = 0; l < 3; ++l) {
            int o = tid + l * 256;
            int row = o >> 3, ch = o & 7;
            cp16(sbase + 36864 + s * 13824 + row * 144 + ch * 16,
                 W + (size_t)row * 384 + k0 + ch * 8);
        }
    };

    float acc[2][6][4];
#pragma unroll
    for (int mt = 0; mt < 2; ++mt)
#pragma unroll
        for (int nt = 0; nt < 6; ++nt)
#pragma unroll
            for (int q = 0; q < 4; ++q) acc[mt][nt][q] = 0.f;

    load_stage(0, 0);
    CP_COMMIT();

    for (int ki = 0; ki < 6; ++ki) {
        if (ki < 5) {
            load_stage((ki + 1) & 1, (ki + 1) * 64);
            CP_COMMIT();
            CP_WAIT1();
        } else {
            CP_WAIT0();
        }
        __syncthreads();
        const unsigned* AsU = smem_u + (ki & 1) * 4608;
        const unsigned* BsU = smem_u + 9216 + (ki & 1) * 3456;
#pragma unroll
        for (int ks = 0; ks < 4; ++ks) {
            unsigned a[2][4];
#pragma unroll
            for (int mt = 0; mt < 2; ++mt) {
                int r = warp_m * 32 + mt * 16 + g;
                a[mt][0] = AsU[r * 36 + ks * 8 + tig];
                a[mt][2] = AsU[r * 36 + ks * 8 + tig + 4];
                a[mt][1] = AsU[(r + 8) * 36 + ks * 8 + tig];
                a[mt][3] = AsU[(r + 8) * 36 + ks * 8 + tig + 4];
            }
#pragma unroll
            for (int nt = 0; nt < 6; ++nt) {
                int cb = warp_n * 48 + nt * 8 + g;
                unsigned b0 = BsU[cb * 36 + ks * 8 + tig];
                unsigned b1 = BsU[cb * 36 + ks * 8 + tig + 4];
#pragma unroll
                for (int mt = 0; mt < 2; ++mt)
                    mma16(acc[mt][nt], a[mt], b0, b1);
            }
        }
        __syncthreads();
    }

    float (*st)[98] = reinterpret_cast<float (*)[98]>(smem_u);
#pragma unroll
    for (int mt = 0; mt < 2; ++mt) {
        int lr0 = warp_m * 32 + mt * 16 + g;
        int r0 = m0 + lr0;
#pragma unroll
        for (int nt = 0; nt < 6; ++nt) {
            int col = warp_n * 48 + nt * 8 + 2 * tig;
            float bi0 = bias[col], bi1 = bias[col + 1];
            float2 rs0 = *reinterpret_cast<const float2*>(&res[(size_t)r0 * 96 + col]);
            float2 rs1 = *reinterpret_cast<const float2*>(&res[(size_t)(r0 + 8) * 96 + col]);
            *reinterpret_cast<float2*>(&st[lr0][col]) =
                make_float2(acc[mt][nt][0] + bi0 + rs0.x, acc[mt][nt][1] + bi1 + rs0.y);
            *reinterpret_cast<float2*>(&st[lr0 + 8][col]) =
                make_float2(acc[mt][nt][2] + bi0 + rs1.x, acc[mt][nt][3] + bi1 + rs1.y);
        }
    }
    __syncthreads();
    int bb = m0 / HW, hw0 = m0 % HW;
    float* ob = out + (size_t)bb * 96 * HW + hw0;
#pragma unroll
    for (int l = 0; l < 48; ++l) {
        int e = tid + l * 256;
        int ch = e >> 7, tok = e & 127;
        ob[(size_t)ch * HW + tok] = st[tok][ch];
    }
}

// ---------------------------------------------------------------------------
// Attention: one CTA per window, bf16 MMA for scores and AV.
// smem (unsigned units): qs[64*52] @0, ks[64*52] @3328, vT[96*36] @6656,
//                        attb[64*36] @10112, sc fp32[64*68] @12416
// ---------------------------------------------------------------------------
#define QS_U 0
#define KS_U 3328
#define VT_U 6656
#define AT_U 10112
#define SC_U 12416

__global__ __launch_bounds__(256) void k_attn(const float* __restrict__ rel_table) {
    extern __shared__ unsigned smem_u[];
    __shared__ int tok_s[49];
    __shared__ int lbl_s[49];

    int win = blockIdx.x;
    int bb = win >> 10;
    int wr = (win >> 5) & 31;
    int wc = win & 31;
    int tid = threadIdx.x;
    int lane = tid & 31, warp = tid >> 5;
    int g = lane >> 2, tig = lane & 3;
    int mt = warp & 3, nhalf = warp >> 2;

    if (tid < 49) {
        int i = tid / 7, j = tid % 7;
        int sr = wr * 7 + i, sc = wc * 7 + j;
        int r = sr + 3; if (r >= 224) r -= 224;
        int c = sc + 3; if (c >= 224) c -= 224;
        tok_s[tid] = bb * HW + r * 224 + c;
        int rb = (sr < 217) ? 0 : (sr < 221 ? 1 : 2);
        int cb = (sc < 217) ? 0 : (sc < 221 ? 1 : 2);
        lbl_s[tid] = rb * 3 + cb;
    }
    // zero vT (padding cols must contribute exact zeros in AV)
    for (int e = tid; e < 3456; e += 256) smem_u[VT_U + e] = 0u;
    __syncthreads();

    // gather Q,K via cp.async (16B chunks), V via LDG + transposed STS
    unsigned sbase = s2u(smem_u);
#pragma unroll
    for (int l = 0; l < 5; ++l) {
        int e = tid + l * 256;
        if (e < 1176) {
            int half = e >= 588;
            int ee = e - half * 588;
            int row = ee / 12, ch = ee % 12;
            const __nv_bfloat16* src = g_qkv + (size_t)tok_s[row] * 288 + half * 96 + ch * 8;
            cp16(sbase + (half ? KS_U * 4 : 0) + row * 208 + ch * 16, src);
        }
    }
    CP_COMMIT();
    {
        __nv_bfloat16* vth = reinterpret_cast<__nv_bfloat16*>(smem_u + VT_U);
#pragma unroll
        for (int l = 0; l < 5; ++l) {
            int e = tid + l * 256;
            if (e < 1176) {
                int row = e / 24, c4 = (e % 24) * 4;
                uint2 raw = *reinterpret_cast<const uint2*>(
                    g_qkv + (size_t)tok_s[row] * 288 + 192 + c4);
                __nv_bfloat162 p0 = *reinterpret_cast<__nv_bfloat162*>(&raw.x);
                __nv_bfloat162 p1 = *reinterpret_cast<__nv_bfloat162*>(&raw.y);
                vth[(c4 + 0) * 72 + row] = p0.x;
                vth[(c4 + 1) * 72 + row] = p0.y;
                vth[(c4 + 2) * 72 + row] = p1.x;
                vth[(c4 + 3) * 72 + row] = p1.y;
            }
        }
    }
    CP_WAIT0();
    __syncthreads();

    // ---- scores: Q[64x96] @ K^T -> sc[64x64] fp32 -------------------------
    {
        const unsigned* qsU = smem_u + QS_U;
        const unsigned* ksU = smem_u + KS_U;
        float acc[4][4];
#pragma unroll
        for (int t = 0; t < 4; ++t)
#pragma unroll
            for (int q = 0; q < 4; ++q) acc[t][q] = 0.f;
#pragma unroll
        for (int ks = 0; ks < 6; ++ks) {
            unsigned a[4];
            int r = mt * 16 + g;
            a[0] = qsU[r * 52 + ks * 8 + tig];
            a[2] = qsU[r * 52 + ks * 8 + tig + 4];
            a[1] = qsU[(r + 8) * 52 + ks * 8 + tig];
            a[3] = qsU[(r + 8) * 52 + ks * 8 + tig + 4];
#pragma unroll
            for (int t = 0; t < 4; ++t) {
                int cb = (nhalf * 4 + t) * 8 + g;
                unsigned b0 = ksU[cb * 52 + ks * 8 + tig];
                unsigned b1 = ksU[cb * 52 + ks * 8 + tig + 4];
                mma16(acc[t], a, b0, b1);
            }
        }
        float* sc = reinterpret_cast<float*>(smem_u + SC_U);
        const float scale = 0.10206207261596575f;
#pragma unroll
        for (int t = 0; t < 4; ++t) {
            int j0 = (nhalf * 4 + t) * 8 + 2 * tig;
#pragma unroll
            for (int rr = 0; rr < 2; ++rr) {
                int i = mt * 16 + g + rr * 8;
                float v0 = acc[t][rr * 2 + 0] * scale;
                float v1 = acc[t][rr * 2 + 1] * scale;
                if (i < 49) {
                    if (j0 < 49) {
                        int idx = (i / 7 - j0 / 7 + 6) * 13 + (i % 7 - j0 % 7 + 6);
                        v0 += rel_table[idx];
                        if (lbl_s[i] != lbl_s[j0]) v0 -= 100.0f;
                    }
                    int j1 = j0 + 1;
                    if (j1 < 49) {
                        int idx = (i / 7 - j1 / 7 + 6) * 13 + (i % 7 - j1 % 7 + 6);
                        v1 += rel_table[idx];
                        if (lbl_s[i] != lbl_s[j1]) v1 -= 100.0f;
                    }
                }
                *reinterpret_cast<float2*>(&sc[i * 68 + j0]) = make_float2(v0, v1);
            }
        }
    }
    __syncthreads();

    // ---- softmax rows 0..48, write bf16 probs (cols>=49 zero) -------------
    {
        float* sc = reinterpret_cast<float*>(smem_u + SC_U);
        __nv_bfloat16* atth = reinterpret_cast<__nv_bfloat16*>(smem_u + AT_U);
        for (int row = warp; row < 49; row += 8) {
            float x0 = sc[row * 68 + lane];
            float x1 = (lane + 32 < 49) ? sc[row * 68 + lane + 32] : -1e30f;
            float mx = fmaxf(x0, x1);
            for (int o = 16; o; o >>= 1) mx = fmaxf(mx, __shfl_xor_sync(0xffffffffu, mx, o));
            float e0 = expf(x0 - mx);
            float e1 = (lane + 32 < 49) ? expf(x1 - mx) : 0.f;
            float sum = e0 + e1;
            for (int o = 16; o; o >>= 1) sum += __shfl_xor_sync(0xffffffffu, sum, o);
            float inv = 1.0f / sum;
            atth[row * 72 + lane] = __float2bfloat16(e0 * inv);
            atth[row * 72 + lane + 32] = __float2bfloat16((lane + 32 < 49) ? e1 * inv : 0.f);
        }
    }
    __syncthreads();

    // ---- AV: P[64x64] @ V^T[96x64] -> ctx ---------------------------------
    {
        const unsigned* atU = smem_u + AT_U;
        const unsigned* vtU = smem_u + VT_U;
        float acc[6][4];
#pragma unroll
        for (int t = 0; t < 6; ++t)
#pragma unroll
            for (int q = 0; q < 4; ++q) acc[t][q] = 0.f;
#pragma unroll
        for (int ks = 0; ks < 4; ++ks) {
            unsigned a[4];
            int r = mt * 16 + g;
            a[0] = atU[r * 36 + ks * 8 + tig];
            a[2] = atU[r * 36 + ks * 8 + tig + 4];
            a[1] = atU[(r + 8) * 36 + ks * 8 + tig];
            a[3] = atU[(r + 8) * 36 + ks * 8 + tig + 4];
#pragma unroll
            for (int t = 0; t < 6; ++t) {
                int cb = (nhalf * 6 + t) * 8 + g;
                unsigned b0 = vtU[cb * 36 + ks * 8 + tig];
                unsigned b1 = vtU[cb * 36 + ks * 8 + tig + 4];
                mma16(acc[t], a, b0, b1);
            }
        }
#pragma unroll
        for (int t = 0; t < 6; ++t) {
            int ch = (nhalf * 6 + t) * 8 + 2 * tig;
#pragma unroll
            for (int rr = 0; rr < 2; ++rr) {
                int r = mt * 16 + g + rr * 8;
                if (r < 49) {
                    *reinterpret_cast<unsigned*>(&g_ctx[(size_t)tok_s[r] * 96 + ch]) =
                        bf2u(acc[t][rr * 2 + 0], acc[t][rr * 2 + 1]);
                }
            }
        }
    }
}

// ---------------------------------------------------------------------------
extern "C" void kernel_launch(void* const* d_in, const int* in_sizes, int n_in,
                              void* d_out, int out_size) {
    const float* x    = (const float*)d_in[0];
    const float* n1w  = (const float*)d_in[1];
    const float* n1b  = (const float*)d_in[2];
    const float* qkvw = (const float*)d_in[3];
    const float* qkvb = (const float*)d_in[4];
    const float* rel  = (const float*)d_in[5];
    const float* pw   = (const float*)d_in[6];
    const float* pb   = (const float*)d_in[7];
    const float* n2w  = (const float*)d_in[8];
    const float* n2b  = (const float*)d_in[9];
    const float* w1   = (const float*)d_in[10];
    const float* b1   = (const float*)d_in[11];
    const float* w2   = (const float*)d_in[12];
    const float* b2   = (const float*)d_in[13];
    float* out = (float*)d_out;

    void *p_ln1, *p_qkv, *p_ctx, *p_h, *p_ln2, *p_m1;
    void *p_bwq, *p_bwp, *p_bw1, *p_bw2;
    cudaGetSymbolAddress(&p_ln1, g_ln1);
    cudaGetSymbolAddress(&p_qkv, g_qkv);
    cudaGetSymbolAddress(&p_ctx, g_ctx);
    cudaGetSymbolAddress(&p_h,   g_h);
    cudaGetSymbolAddress(&p_ln2, g_ln2);
    cudaGetSymbolAddress(&p_m1,  g_m1);
    cudaGetSymbolAddress(&p_bwq, g_bwq);
    cudaGetSymbolAddress(&p_bwp, g_bwp);
    cudaGetSymbolAddress(&p_bw1, g_bw1);
    cudaGetSymbolAddress(&p_bw2, g_bw2);

    const int SM96   = (128 + 96) * 52 * 4;   // 46592
    const int SM96_3 = 128 * 100 * 4;         // 51200 (proj: LN staging)
    const int SM384  = 2 * (128 * 36 + 96 * 36) * 4;  // 64512
    const int SMATTN = (12416 + 64 * 68) * 4;         // 67072

    cudaFuncSetAttribute(k_mma96<288, 0>, cudaFuncAttributeMaxDynamicSharedMemorySize, SM96);
    cudaFuncSetAttribute(k_mma96<384, 2>, cudaFuncAttributeMaxDynamicSharedMemorySize, SM96);
    cudaFuncSetAttribute(k_mma96<96, 3>,  cudaFuncAttributeMaxDynamicSharedMemorySize, SM96_3);
    cudaFuncSetAttribute(k_mma384, cudaFuncAttributeMaxDynamicSharedMemorySize, SM384);
    cudaFuncSetAttribute(k_attn,   cudaFuncAttributeMaxDynamicSharedMemorySize, SMATTN);

    // 0) weights -> bf16
    k_prep<<<432, 256>>>(qkvw, pw, w1, w2);
    // 1) NCHW->NHWC + LN1
    k_in_ln<<<12544, 256>>>(x, n1w, n1b);
    // 2) QKV
    k_mma96<288, 0><<<dim3(3136, 3), 256, SM96>>>(
        (const __nv_bfloat16*)p_ln1, (const __nv_bfloat16*)p_bwq, qkvb,
        nullptr, p_qkv, nullptr, nullptr, nullptr);
    // 3) attention
    k_attn<<<NWIN, 256, SMATTN>>>(rel);
    // 4) proj + x residual + fused LN2
    k_mma96<96, 3><<<dim3(3136, 1), 256, SM96_3>>>(
        (const __nv_bfloat16*)p_ctx, (const __nv_bfloat16*)p_bwp, pb,
        x, p_h, n2w, n2b, (__nv_bfloat16*)p_ln2);
    // 5) MLP1 + GELU
    k_mma96<384, 2><<<dim3(3136, 4), 256, SM96>>>(
        (const __nv_bfloat16*)p_ln2, (const __nv_bfloat16*)p_bw1, b1,
        nullptr, p_m1, nullptr, nullptr, nullptr);
    // 6) MLP2 + h residual + fused NCHW transpose -> d_out
    k_mma384<<<3136, 256, SM384>>>(
        (const __nv_bfloat16*)p_m1, (const __nv_bfloat16*)p_bw2, b2,
        (const float*)p_h, out);
}

// round 6
// speedup vs baseline: 4.6997x; 1.0323x over previous
#include <cuda_runtime.h>
#include <cuda_bf16.h>
#include <math.h>

#define HW 50176              // 224*224
#define L_TOK 401408          // 8*224*224
#define NWIN 8192

// Scratch
__device__ __nv_bfloat16 g_ln1[(size_t)L_TOK * 96];
__device__ __nv_bfloat16 g_qkv[(size_t)L_TOK * 288];
__device__ __nv_bfloat16 g_ctx[(size_t)L_TOK * 96];
__device__ float         g_h[(size_t)L_TOK * 96];
__device__ __nv_bfloat16 g_ln2[(size_t)L_TOK * 96];
__device__ __nv_bfloat16 g_m1[(size_t)L_TOK * 384];
// bf16 weights
__device__ __nv_bfloat16 g_bwq[288 * 96];
__device__ __nv_bfloat16 g_bwp[96 * 96];
__device__ __nv_bfloat16 g_bw1[384 * 96];
__device__ __nv_bfloat16 g_bw2[96 * 384];
// combined rel-pos bias + shift-mask tables, 4 window classes, [49][56] bf16
__device__ __nv_bfloat16 g_tbl[4 * 49 * 56];

// ---- helpers --------------------------------------------------------------
__device__ __forceinline__ unsigned bf2u(float a, float b) {
    __nv_bfloat162 h = __floats2bfloat162_rn(a, b);
    return *reinterpret_cast<unsigned*>(&h);
}
__device__ __forceinline__ void mma16(float* c, const unsigned* a,
                                      unsigned b0, unsigned b1) {
    asm("mma.sync.aligned.m16n8k16.row.col.f32.bf16.bf16.f32 "
        "{%0,%1,%2,%3}, {%4,%5,%6,%7}, {%8,%9}, {%0,%1,%2,%3};"
        : "+f"(c[0]), "+f"(c[1]), "+f"(c[2]), "+f"(c[3])
        : "r"(a[0]), "r"(a[1]), "r"(a[2]), "r"(a[3]), "r"(b0), "r"(b1));
}
__device__ __forceinline__ unsigned s2u(const void* p) {
    return (unsigned)__cvta_generic_to_shared(p);
}
__device__ __forceinline__ void cp16(unsigned dst, const void* src) {
    asm volatile("cp.async.cg.shared.global [%0], [%1], 16;" :: "r"(dst), "l"(src));
}
#define CP_COMMIT() asm volatile("cp.async.commit_group;")
#define CP_WAIT0()  asm volatile("cp.async.wait_group 0;")
#define CP_WAIT1()  asm volatile("cp.async.wait_group 1;")

// ---------------------------------------------------------------------------
// Kernel 0a: weights fp32 -> bf16
// ---------------------------------------------------------------------------
__global__ __launch_bounds__(256) void k_prep(const float* __restrict__ qkvw,
                                              const float* __restrict__ pw,
                                              const float* __restrict__ w1,
                                              const float* __restrict__ w2) {
    int i = blockIdx.x * 256 + threadIdx.x;
    if (i < 27648)       g_bwq[i] = __float2bfloat16(qkvw[i]);
    else if (i < 36864)  g_bwp[i - 27648] = __float2bfloat16(pw[i - 27648]);
    else if (i < 73728)  g_bw1[i - 36864] = __float2bfloat16(w1[i - 36864]);
    else                 g_bw2[i - 73728] = __float2bfloat16(w2[i - 73728]);
}

// ---------------------------------------------------------------------------
// Kernel 0b: bias+mask class tables. cls = re*2+ce (re: wr==31, ce: wc==31)
// ---------------------------------------------------------------------------
__global__ __launch_bounds__(256) void k_tbl(const float* __restrict__ rel) {
    int cls = blockIdx.x;
    int re = cls >> 1, ce = cls & 1;
    for (int e = threadIdx.x; e < 49 * 56; e += 256) {
        int i = e / 56, j = e % 56;
        float v = 0.f;
        if (j < 49) {
            int idx = (i / 7 - j / 7 + 6) * 13 + (i % 7 - j % 7 + 6);
            v = rel[idx];
            int li = (re ? ((i / 7) < 4 ? 1 : 2) : 0) * 3 + (ce ? ((i % 7) < 4 ? 1 : 2) : 0);
            int lj = (re ? ((j / 7) < 4 ? 1 : 2) : 0) * 3 + (ce ? ((j % 7) < 4 ? 1 : 2) : 0);
            if (li != lj) v -= 100.f;
        }
        g_tbl[cls * 2744 + e] = __float2bfloat16(v);
    }
}

// ---------------------------------------------------------------------------
// Kernel 1: NCHW -> NHWC + LayerNorm1 -> bf16
// ---------------------------------------------------------------------------
__global__ __launch_bounds__(256) void k_in_ln(const float* __restrict__ x,
                                               const float* __restrict__ w,
                                               const float* __restrict__ b) {
    __shared__ float s[96][33];
    __shared__ float mu_s[32], rs_s[32];
    int tile = blockIdx.x;
    int bb = tile / 1568;
    int t0 = (tile % 1568) * 32;
    int tid = threadIdx.x;

    const float* xb = x + (size_t)bb * 96 * HW + t0;
#pragma unroll
    for (int l = 0; l < 12; ++l) {
        int e = tid + l * 256;
        int ch = e >> 5, tl = e & 31;
        s[ch][tl] = xb[(size_t)ch * HW + tl];
    }
    __syncthreads();

    int tok = tid >> 3, sub = tid & 7;
    float acc = 0.f;
#pragma unroll
    for (int k = 0; k < 12; ++k) acc += s[sub + 8 * k][tok];
    acc += __shfl_down_sync(0xffffffffu, acc, 4);
    acc += __shfl_down_sync(0xffffffffu, acc, 2);
    acc += __shfl_down_sync(0xffffffffu, acc, 1);
    float mean = __shfl_sync(0xffffffffu, acc, (tid & 31) & ~7) * (1.f / 96.f);
    float vv = 0.f;
#pragma unroll
    for (int k = 0; k < 12; ++k) {
        float d = s[sub + 8 * k][tok] - mean;
        vv += d * d;
    }
    vv += __shfl_down_sync(0xffffffffu, vv, 4);
    vv += __shfl_down_sync(0xffffffffu, vv, 2);
    vv += __shfl_down_sync(0xffffffffu, vv, 1);
    float var = __shfl_sync(0xffffffffu, vv, (tid & 31) & ~7) * (1.f / 96.f);
    if (sub == 0) { mu_s[tok] = mean; rs_s[tok] = rsqrtf(var + 1e-5f); }
    __syncthreads();

    size_t base = ((size_t)bb * HW + t0) * 96;
#pragma unroll
    for (int l = 0; l < 12; ++l) {
        int e = tid + l * 256;
        int tk = e / 96, ch = e % 96;
        float val = s[ch][tk];
        g_ln1[base + e] = __float2bfloat16((val - mu_s[tk]) * rs_s[tk] * w[ch] + b[ch]);
    }
}

// ---------------------------------------------------------------------------
// K=96 GEMM, full-K cp.async prefetch. BM=128, BN=96.
// ---------------------------------------------------------------------------
template <int N, int MODE>
__global__ __launch_bounds__(256) void k_mma96(const __nv_bfloat16* __restrict__ A,
                                               const __nv_bfloat16* __restrict__ W,
                                               const float* __restrict__ bias,
                                               const float* __restrict__ res,
                                               void* __restrict__ outv,
                                               const float* __restrict__ lnw,
                                               const float* __restrict__ lnb,
                                               __nv_bfloat16* __restrict__ out2) {
    extern __shared__ unsigned smem_u[];
    int tid = threadIdx.x;
    int lane = tid & 31, warp = tid >> 5;
    int warp_m = warp & 3, warp_n = warp >> 2;
    int g = lane >> 2, tig = lane & 3;
    int m0 = blockIdx.x * 128, n0 = blockIdx.y * 96;

    unsigned sbase = s2u(smem_u);
#pragma unroll
    for (int l = 0; l < 6; ++l) {
        int o = tid + l * 256;
        int row = o / 12, ch = o % 12;
        cp16(sbase + row * 208 + ch * 16, A + (size_t)(m0 + row) * 96 + ch * 8);
    }
#pragma unroll
    for (int l = 0; l < 5; ++l) {
        int o = tid + l * 256;
        if (o < 1152) {
            int row = o / 12, ch = o % 12;
            cp16(sbase + 26624 + row * 208 + ch * 16, W + (size_t)(n0 + row) * 96 + ch * 8);
        }
    }
    CP_COMMIT();

    float acc[2][6][4];
#pragma unroll
    for (int mt = 0; mt < 2; ++mt)
#pragma unroll
        for (int nt = 0; nt < 6; ++nt)
#pragma unroll
            for (int q = 0; q < 4; ++q) acc[mt][nt][q] = 0.f;

    CP_WAIT0();
    __syncthreads();

    const unsigned* AsU = smem_u;
    const unsigned* BsU = smem_u + 6656;
#pragma unroll
    for (int ks = 0; ks < 6; ++ks) {
        unsigned a[2][4];
#pragma unroll
        for (int mt = 0; mt < 2; ++mt) {
            int r = warp_m * 32 + mt * 16 + g;
            a[mt][0] = AsU[r * 52 + ks * 8 + tig];
            a[mt][2] = AsU[r * 52 + ks * 8 + tig + 4];
            a[mt][1] = AsU[(r + 8) * 52 + ks * 8 + tig];
            a[mt][3] = AsU[(r + 8) * 52 + ks * 8 + tig + 4];
        }
#pragma unroll
        for (int nt = 0; nt < 6; ++nt) {
            int cb = warp_n * 48 + nt * 8 + g;
            unsigned b0 = BsU[cb * 52 + ks * 8 + tig];
            unsigned b1 = BsU[cb * 52 + ks * 8 + tig + 4];
#pragma unroll
            for (int mt = 0; mt < 2; ++mt)
                mma16(acc[mt][nt], a[mt], b0, b1);
        }
    }

    if constexpr (MODE == 0 || MODE == 2) {
        __nv_bfloat16* out = reinterpret_cast<__nv_bfloat16*>(outv);
#pragma unroll
        for (int mt = 0; mt < 2; ++mt) {
            int r0 = m0 + warp_m * 32 + mt * 16 + g;
#pragma unroll
            for (int nt = 0; nt < 6; ++nt) {
                int col = n0 + warp_n * 48 + nt * 8 + 2 * tig;
                float bi0 = bias[col], bi1 = bias[col + 1];
                float v0 = acc[mt][nt][0] + bi0, v1 = acc[mt][nt][1] + bi1;
                float v2 = acc[mt][nt][2] + bi0, v3 = acc[mt][nt][3] + bi1;
                if (MODE == 2) {
                    v0 = 0.5f * v0 * (1.0f + erff(v0 * 0.70710678118654752f));
                    v1 = 0.5f * v1 * (1.0f + erff(v1 * 0.70710678118654752f));
                    v2 = 0.5f * v2 * (1.0f + erff(v2 * 0.70710678118654752f));
                    v3 = 0.5f * v3 * (1.0f + erff(v3 * 0.70710678118654752f));
                }
                *reinterpret_cast<unsigned*>(&out[(size_t)r0 * N + col]) = bf2u(v0, v1);
                *reinterpret_cast<unsigned*>(&out[(size_t)(r0 + 8) * N + col]) = bf2u(v2, v3);
            }
        }
    }
    if constexpr (MODE == 3) {
        float* hout = reinterpret_cast<float*>(outv);
        float (*st)[100] = reinterpret_cast<float (*)[100]>(smem_u);
        __syncthreads();
#pragma unroll
        for (int mt = 0; mt < 2; ++mt) {
            int lr0 = warp_m * 32 + mt * 16 + g;
#pragma unroll
            for (int nt = 0; nt < 6; ++nt) {
                int col = warp_n * 48 + nt * 8 + 2 * tig;
                float bi0 = bias[col], bi1 = bias[col + 1];
                st[lr0][col]         = acc[mt][nt][0] + bi0;
                st[lr0][col + 1]     = acc[mt][nt][1] + bi1;
                st[lr0 + 8][col]     = acc[mt][nt][2] + bi0;
                st[lr0 + 8][col + 1] = acc[mt][nt][3] + bi1;
            }
        }
        __syncthreads();
        int r = tid >> 1, half = tid & 1;
        int bb = m0 / HW, hw0 = m0 % HW;
        const float* xb = res + (size_t)bb * 96 * HW + hw0 + r;
        float vals[48];
        float s = 0.f, q = 0.f;
#pragma unroll
        for (int i = 0; i < 12; ++i) {
            float4 v = *reinterpret_cast<const float4*>(&st[r][half * 48 + i * 4]);
            float h0 = v.x + xb[(size_t)(half * 48 + i * 4 + 0) * HW];
            float h1 = v.y + xb[(size_t)(half * 48 + i * 4 + 1) * HW];
            float h2 = v.z + xb[(size_t)(half * 48 + i * 4 + 2) * HW];
            float h3 = v.w + xb[(size_t)(half * 48 + i * 4 + 3) * HW];
            vals[i * 4 + 0] = h0; vals[i * 4 + 1] = h1;
            vals[i * 4 + 2] = h2; vals[i * 4 + 3] = h3;
            s += h0 + h1 + h2 + h3;
            q += h0 * h0 + h1 * h1 + h2 * h2 + h3 * h3;
        }
        s += __shfl_xor_sync(0xffffffffu, s, 1);
        q += __shfl_xor_sync(0xffffffffu, q, 1);
        float mean = s * (1.f / 96.f);
        float var = q * (1.f / 96.f) - mean * mean;
        float rstd = rsqrtf(var + 1e-5f);
        float* hp = hout + (size_t)(m0 + r) * 96 + half * 48;
        __nv_bfloat16* lp = out2 + (size_t)(m0 + r) * 96 + half * 48;
#pragma unroll
        for (int i = 0; i < 12; ++i) {
            int c = half * 48 + i * 4;
            *reinterpret_cast<float4*>(hp + i * 4) =
                make_float4(vals[i * 4], vals[i * 4 + 1], vals[i * 4 + 2], vals[i * 4 + 3]);
            uint2 uu;
            uu.x = bf2u((vals[i * 4 + 0] - mean) * rstd * lnw[c + 0] + lnb[c + 0],
                        (vals[i * 4 + 1] - mean) * rstd * lnw[c + 1] + lnb[c + 1]);
            uu.y = bf2u((vals[i * 4 + 2] - mean) * rstd * lnw[c + 2] + lnb[c + 2],
                        (vals[i * 4 + 3] - mean) * rstd * lnw[c + 3] + lnb[c + 3]);
            *reinterpret_cast<uint2*>(lp + i * 4) = uu;
        }
    }
}

// ---------------------------------------------------------------------------
// K=384 GEMM (MLP2), 2-stage cp.async ring (BK=64). N=96.
// ---------------------------------------------------------------------------
__global__ __launch_bounds__(256) void k_mma384(const __nv_bfloat16* __restrict__ A,
                                                const __nv_bfloat16* __restrict__ W,
                                                const float* __restrict__ bias,
                                                const float* __restrict__ res,
                                                float* __restrict__ out) {
    extern __shared__ unsigned smem_u[];
    int tid = threadIdx.x;
    int lane = tid & 31, warp = tid >> 5;
    int warp_m = warp & 3, warp_n = warp >> 2;
    int g = lane >> 2, tig = lane & 3;
    int m0 = blockIdx.x * 128;

    unsigned sbase = s2u(smem_u);
    auto load_stage = [&](int s, int k0) {
#pragma unroll
        for (int l = 0; l < 4; ++l) {
            int o = tid + l * 256;
            int row = o >> 3, ch = o & 7;
            cp16(sbase + s * 18432 + row * 144 + ch * 16,
                 A + (size_t)(m0 + row) * 384 + k0 + ch * 8);
        }
#pragma unroll
        for (int l = 0; l < 3; ++l) {
            int o = tid + l * 256;
            int row = o >> 3, ch = o & 7;
            cp16(sbase + 36864 + s * 13824 + row * 144 + ch * 16,
                 W + (size_t)row * 384 + k0 + ch * 8);
        }
    };

    float acc[2][6][4];
#pragma unroll
    for (int mt = 0; mt < 2; ++mt)
#pragma unroll
        for (int nt = 0; nt < 6; ++nt)
#pragma unroll
            for (int q = 0; q < 4; ++q) acc[mt][nt][q] = 0.f;

    load_stage(0, 0);
    CP_COMMIT();

    for (int ki = 0; ki < 6; ++ki) {
        if (ki < 5) {
            load_stage((ki + 1) & 1, (ki + 1) * 64);
            CP_COMMIT();
            CP_WAIT1();
        } else {
            CP_WAIT0();
        }
        __syncthreads();
        const unsigned* AsU = smem_u + (ki & 1) * 4608;
        const unsigned* BsU = smem_u + 9216 + (ki & 1) * 3456;
#pragma unroll
        for (int ks = 0; ks < 4; ++ks) {
            unsigned a[2][4];
#pragma unroll
            for (int mt = 0; mt < 2; ++mt) {
                int r = warp_m * 32 + mt * 16 + g;
                a[mt][0] = AsU[r * 36 + ks * 8 + tig];
                a[mt][2] = AsU[r * 36 + ks * 8 + tig + 4];
                a[mt][1] = AsU[(r + 8) * 36 + ks * 8 + tig];
                a[mt][3] = AsU[(r + 8) * 36 + ks * 8 + tig + 4];
            }
#pragma unroll
            for (int nt = 0; nt < 6; ++nt) {
                int cb = warp_n * 48 + nt * 8 + g;
                unsigned b0 = BsU[cb * 36 + ks * 8 + tig];
                unsigned b1 = BsU[cb * 36 + ks * 8 + tig + 4];
#pragma unroll
                for (int mt = 0; mt < 2; ++mt)
                    mma16(acc[mt][nt], a[mt], b0, b1);
            }
        }
        __syncthreads();
    }

    float (*st)[98] = reinterpret_cast<float (*)[98]>(smem_u);
#pragma unroll
    for (int mt = 0; mt < 2; ++mt) {
        int lr0 = warp_m * 32 + mt * 16 + g;
        int r0 = m0 + lr0;
#pragma unroll
        for (int nt = 0; nt < 6; ++nt) {
            int col = warp_n * 48 + nt * 8 + 2 * tig;
            float bi0 = bias[col], bi1 = bias[col + 1];
            float2 rs0 = *reinterpret_cast<const float2*>(&res[(size_t)r0 * 96 + col]);
            float2 rs1 = *reinterpret_cast<const float2*>(&res[(size_t)(r0 + 8) * 96 + col]);
            *reinterpret_cast<float2*>(&st[lr0][col]) =
                make_float2(acc[mt][nt][0] + bi0 + rs0.x, acc[mt][nt][1] + bi1 + rs0.y);
            *reinterpret_cast<float2*>(&st[lr0 + 8][col]) =
                make_float2(acc[mt][nt][2] + bi0 + rs1.x, acc[mt][nt][3] + bi1 + rs1.y);
        }
    }
    __syncthreads();
    int bb = m0 / HW, hw0 = m0 % HW;
    float* ob = out + (size_t)bb * 96 * HW + hw0;
#pragma unroll
    for (int l = 0; l < 48; ++l) {
        int e = tid + l * 256;
        int ch = e >> 7, tok = e & 127;
        ob[(size_t)ch * HW + tok] = st[tok][ch];
    }
}

// ---------------------------------------------------------------------------
// Attention. smem (u32 units): qs[64*52]@0, ks@3328, vT[96*36]@6656,
// attb[64*36]@10112, tbl bf16[49*56]@12416 (686u... stored as 1372 halves =
// 686u? -> 49*56 halves = 2744 halves = 1372u), sc fp32[64*68] overlays @0.
// ---------------------------------------------------------------------------
#define QS_U 0
#define KS_U 3328
#define VT_U 6656
#define AT_U 10112
#define TB_U 12416
#define SM_ATTN_U (TB_U + 1372)   // 13788 u32 = 55152 B

__global__ __launch_bounds__(256) void k_attn() {
    extern __shared__ unsigned smem_u[];
    __shared__ int tok_s[49];

    int win = blockIdx.x;
    int bb = win >> 10;
    int wr = (win >> 5) & 31;
    int wc = win & 31;
    int tid = threadIdx.x;
    int lane = tid & 31, warp = tid >> 5;
    int g = lane >> 2, tig = lane & 3;
    int mt = warp & 3, nhalf = warp >> 2;
    int cls = ((wr == 31) ? 2 : 0) + ((wc == 31) ? 1 : 0);

    if (tid < 49) {
        int i = tid / 7, j = tid % 7;
        int sr = wr * 7 + i, sc = wc * 7 + j;
        int r = sr + 3; if (r >= 224) r -= 224;
        int c = sc + 3; if (c >= 224) c -= 224;
        tok_s[tid] = bb * HW + r * 224 + c;
    }
    for (int e = tid; e < 3456; e += 256) smem_u[VT_U + e] = 0u;
    __syncthreads();

    unsigned sbase = s2u(smem_u);
    // Q,K gather via cp.async
#pragma unroll
    for (int l = 0; l < 5; ++l) {
        int e = tid + l * 256;
        if (e < 1176) {
            int half = e >= 588;
            int ee = e - half * 588;
            int row = ee / 12, ch = ee % 12;
            const __nv_bfloat16* src = g_qkv + (size_t)tok_s[row] * 288 + half * 96 + ch * 8;
            cp16(sbase + (half ? KS_U * 4 : 0) + row * 208 + ch * 16, src);
        }
    }
    // class table: 1372u = 5488B = 343 16B-chunks
    {
        const __nv_bfloat16* tsrc = g_tbl + cls * 2744;
        for (int o = tid; o < 343; o += 256)
            cp16(sbase + TB_U * 4 + o * 16, tsrc + o * 8);
    }
    CP_COMMIT();
    // V gather + transpose (LDG; overlaps cp.async)
    {
        __nv_bfloat16* vth = reinterpret_cast<__nv_bfloat16*>(smem_u + VT_U);
#pragma unroll
        for (int l = 0; l < 5; ++l) {
            int e = tid + l * 256;
            if (e < 1176) {
                int row = e / 24, c4 = (e % 24) * 4;
                uint2 raw = *reinterpret_cast<const uint2*>(
                    g_qkv + (size_t)tok_s[row] * 288 + 192 + c4);
                __nv_bfloat162 p0 = *reinterpret_cast<__nv_bfloat162*>(&raw.x);
                __nv_bfloat162 p1 = *reinterpret_cast<__nv_bfloat162*>(&raw.y);
                vth[(c4 + 0) * 72 + row] = p0.x;
                vth[(c4 + 1) * 72 + row] = p0.y;
                vth[(c4 + 2) * 72 + row] = p1.x;
                vth[(c4 + 3) * 72 + row] = p1.y;
            }
        }
    }
    CP_WAIT0();
    __syncthreads();

    // ---- scores: Q[64x96] @ K^T (accumulate in regs) ----------------------
    float acc[4][4];
#pragma unroll
    for (int t = 0; t < 4; ++t)
#pragma unroll
        for (int q = 0; q < 4; ++q) acc[t][q] = 0.f;
    {
        const unsigned* qsU = smem_u + QS_U;
        const unsigned* ksU = smem_u + KS_U;
#pragma unroll
        for (int ks = 0; ks < 6; ++ks) {
            unsigned a[4];
            int r = mt * 16 + g;
            a[0] = qsU[r * 52 + ks * 8 + tig];
            a[2] = qsU[r * 52 + ks * 8 + tig + 4];
            a[1] = qsU[(r + 8) * 52 + ks * 8 + tig];
            a[3] = qsU[(r + 8) * 52 + ks * 8 + tig + 4];
#pragma unroll
            for (int t = 0; t < 4; ++t) {
                int cb = (nhalf * 4 + t) * 8 + g;
                unsigned b0 = ksU[cb * 52 + ks * 8 + tig];
                unsigned b1 = ksU[cb * 52 + ks * 8 + tig + 4];
                mma16(acc[t], a, b0, b1);
            }
        }
    }
    __syncthreads();   // Q/K reads done in all warps; sc overlays them

    // ---- epilogue: scale + table add, store sc fp32 -----------------------
    {
        float* sc = reinterpret_cast<float*>(smem_u);   // stride 68
        const __nv_bfloat16* tb = reinterpret_cast<const __nv_bfloat16*>(smem_u + TB_U);
        const float scale = 0.10206207261596575f;
#pragma unroll
        for (int t = 0; t < 4; ++t) {
            int j0 = (nhalf * 4 + t) * 8 + 2 * tig;
#pragma unroll
            for (int rr = 0; rr < 2; ++rr) {
                int i = mt * 16 + g + rr * 8;
                float v0 = acc[t][rr * 2 + 0] * scale;
                float v1 = acc[t][rr * 2 + 1] * scale;
                if (i < 49 && j0 < 56) {
                    __nv_bfloat162 t2 = *reinterpret_cast<const __nv_bfloat162*>(&tb[i * 56 + j0]);
                    v0 += __bfloat162float(t2.x);
                    v1 += __bfloat162float(t2.y);
                }
                *reinterpret_cast<float2*>(&sc[i * 68 + j0]) = make_float2(v0, v1);
            }
        }
    }
    __syncthreads();

    // ---- softmax rows 0..48 -> bf16 probs ---------------------------------
    {
        float* sc = reinterpret_cast<float*>(smem_u);
        __nv_bfloat16* atth = reinterpret_cast<__nv_bfloat16*>(smem_u + AT_U);
        for (int row = warp; row < 49; row += 8) {
            float x0 = sc[row * 68 + lane];
            float x1 = (lane + 32 < 49) ? sc[row * 68 + lane + 32] : -1e30f;
            float mx = fmaxf(x0, x1);
            for (int o = 16; o; o >>= 1) mx = fmaxf(mx, __shfl_xor_sync(0xffffffffu, mx, o));
            float e0 = __expf(x0 - mx);
            float e1 = (lane + 32 < 49) ? __expf(x1 - mx) : 0.f;
            float sum = e0 + e1;
            for (int o = 16; o; o >>= 1) sum += __shfl_xor_sync(0xffffffffu, sum, o);
            float inv = 1.0f / sum;
            atth[row * 72 + lane] = __float2bfloat16(e0 * inv);
            atth[row * 72 + lane + 32] = __float2bfloat16((lane + 32 < 49) ? e1 * inv : 0.f);
        }
    }
    __syncthreads();

    // ---- AV: P[64x64] @ V^T[96x64] -> ctx ---------------------------------
    {
        const unsigned* atU = smem_u + AT_U;
        const unsigned* vtU = smem_u + VT_U;
        float av[6][4];
#pragma unroll
        for (int t = 0; t < 6; ++t)
#pragma unroll
            for (int q = 0; q < 4; ++q) av[t][q] = 0.f;
#pragma unroll
        for (int ks = 0; ks < 4; ++ks) {
            unsigned a[4];
            int r = mt * 16 + g;
            a[0] = atU[r * 36 + ks * 8 + tig];
            a[2] = atU[r * 36 + ks * 8 + tig + 4];
            a[1] = atU[(r + 8) * 36 + ks * 8 + tig];
            a[3] = atU[(r + 8) * 36 + ks * 8 + tig + 4];
#pragma unroll
            for (int t = 0; t < 6; ++t) {
                int cb = (nhalf * 6 + t) * 8 + g;
                unsigned b0 = vtU[cb * 36 + ks * 8 + tig];
                unsigned b1 = vtU[cb * 36 + ks * 8 + tig + 4];
                mma16(av[t], a, b0, b1);
            }
        }
#pragma unroll
        for (int t = 0; t < 6; ++t) {
            int ch = (nhalf * 6 + t) * 8 + 2 * tig;
#pragma unroll
            for (int rr = 0; rr < 2; ++rr) {
                int r = mt * 16 + g + rr * 8;
                if (r < 49) {
                    *reinterpret_cast<unsigned*>(&g_ctx[(size_t)tok_s[r] * 96 + ch]) =
                        bf2u(av[t][rr * 2 + 0], av[t][rr * 2 + 1]);
                }
            }
        }
    }
}

// ---------------------------------------------------------------------------
extern "C" void kernel_launch(void* const* d_in, const int* in_sizes, int n_in,
                              void* d_out, int out_size) {
    const float* x    = (const float*)d_in[0];
    const float* n1w  = (const float*)d_in[1];
    const float* n1b  = (const float*)d_in[2];
    const float* qkvw = (const float*)d_in[3];
    const float* qkvb = (const float*)d_in[4];
    const float* rel  = (const float*)d_in[5];
    const float* pw   = (const float*)d_in[6];
    const float* pb   = (const float*)d_in[7];
    const float* n2w  = (const float*)d_in[8];
    const float* n2b  = (const float*)d_in[9];
    const float* w1   = (const float*)d_in[10];
    const float* b1   = (const float*)d_in[11];
    const float* w2   = (const float*)d_in[12];
    const float* b2   = (const float*)d_in[13];
    float* out = (float*)d_out;

    void *p_ln1, *p_qkv, *p_ctx, *p_h, *p_ln2, *p_m1;
    void *p_bwq, *p_bwp, *p_bw1, *p_bw2;
    cudaGetSymbolAddress(&p_ln1, g_ln1);
    cudaGetSymbolAddress(&p_qkv, g_qkv);
    cudaGetSymbolAddress(&p_ctx, g_ctx);
    cudaGetSymbolAddress(&p_h,   g_h);
    cudaGetSymbolAddress(&p_ln2, g_ln2);
    cudaGetSymbolAddress(&p_m1,  g_m1);
    cudaGetSymbolAddress(&p_bwq, g_bwq);
    cudaGetSymbolAddress(&p_bwp, g_bwp);
    cudaGetSymbolAddress(&p_bw1, g_bw1);
    cudaGetSymbolAddress(&p_bw2, g_bw2);

    const int SM96   = (128 + 96) * 52 * 4;           // 46592
    const int SM96_3 = 128 * 100 * 4;                 // 51200
    const int SM384  = 2 * (128 * 36 + 96 * 36) * 4;  // 64512
    const int SMATTN = SM_ATTN_U * 4;                 // 55152

    cudaFuncSetAttribute(k_mma96<288, 0>, cudaFuncAttributeMaxDynamicSharedMemorySize, SM96);
    cudaFuncSetAttribute(k_mma96<384, 2>, cudaFuncAttributeMaxDynamicSharedMemorySize, SM96);
    cudaFuncSetAttribute(k_mma96<96, 3>,  cudaFuncAttributeMaxDynamicSharedMemorySize, SM96_3);
    cudaFuncSetAttribute(k_mma384, cudaFuncAttributeMaxDynamicSharedMemorySize, SM384);
    cudaFuncSetAttribute(k_attn,   cudaFuncAttributeMaxDynamicSharedMemorySize, SMATTN);

    // 0) weights -> bf16; bias+mask class tables
    k_prep<<<432, 256>>>(qkvw, pw, w1, w2);
    k_tbl<<<4, 256>>>(rel);
    // 1) NCHW->NHWC + LN1
    k_in_ln<<<12544, 256>>>(x, n1w, n1b);
    // 2) QKV
    k_mma96<288, 0><<<dim3(3136, 3), 256, SM96>>>(
        (const __nv_bfloat16*)p_ln1, (const __nv_bfloat16*)p_bwq, qkvb,
        nullptr, p_qkv, nullptr, nullptr, nullptr);
    // 3) attention
    k_attn<<<NWIN, 256, SMATTN>>>();
    // 4) proj + x residual + fused LN2
    k_mma96<96, 3><<<dim3(3136, 1), 256, SM96_3>>>(
        (const __nv_bfloat16*)p_ctx, (const __nv_bfloat16*)p_bwp, pb,
        x, p_h, n2w, n2b, (__nv_bfloat16*)p_ln2);
    // 5) MLP1 + GELU
    k_mma96<384, 2><<<dim3(3136, 4), 256, SM96>>>(
        (const __nv_bfloat16*)p_ln2, (const __nv_bfloat16*)p_bw1, b1,
        nullptr, p_m1, nullptr, nullptr, nullptr);
    // 6) MLP2 + h residual + fused NCHW transpose -> d_out
    k_mma384<<<3136, 256, SM384>>>(
        (const __nv_bfloat16*)p_m1, (const __nv_bfloat16*)p_bw2, b2,
        (const float*)p_h, out);
}

// round 7
// speedup vs baseline: 5.0493x; 1.0744x over previous
#include <cuda_runtime.h>
#include <cuda_bf16.h>
#include <math.h>

#define HW 50176              // 224*224
#define L_TOK 401408          // 8*224*224
#define NWIN 8192

// Scratch
__device__ __nv_bfloat16 g_qkv[(size_t)L_TOK * 288];
__device__ __nv_bfloat16 g_ctx[(size_t)L_TOK * 96];
__device__ float         g_h[(size_t)L_TOK * 96];
__device__ __nv_bfloat16 g_ln2[(size_t)L_TOK * 96];
// bf16 weights
__device__ __nv_bfloat16 g_bwq[288 * 96];
__device__ __nv_bfloat16 g_bwp[96 * 96];
__device__ __nv_bfloat16 g_bw1[384 * 96];
__device__ __nv_bfloat16 g_bw2[96 * 384];
// combined rel-pos bias + shift-mask tables, 4 window classes, [49][56] bf16
__device__ __nv_bfloat16 g_tbl[4 * 49 * 56];

// ---- helpers --------------------------------------------------------------
__device__ __forceinline__ unsigned bf2u(float a, float b) {
    __nv_bfloat162 h = __floats2bfloat162_rn(a, b);
    return *reinterpret_cast<unsigned*>(&h);
}
__device__ __forceinline__ void mma16(float* c, const unsigned* a,
                                      unsigned b0, unsigned b1) {
    asm("mma.sync.aligned.m16n8k16.row.col.f32.bf16.bf16.f32 "
        "{%0,%1,%2,%3}, {%4,%5,%6,%7}, {%8,%9}, {%0,%1,%2,%3};"
        : "+f"(c[0]), "+f"(c[1]), "+f"(c[2]), "+f"(c[3])
        : "r"(a[0]), "r"(a[1]), "r"(a[2]), "r"(a[3]), "r"(b0), "r"(b1));
}
__device__ __forceinline__ unsigned s2u(const void* p) {
    return (unsigned)__cvta_generic_to_shared(p);
}
__device__ __forceinline__ void cp16(unsigned dst, const void* src) {
    asm volatile("cp.async.cg.shared.global [%0], [%1], 16;" :: "r"(dst), "l"(src));
}
#define CP_COMMIT() asm volatile("cp.async.commit_group;")
#define CP_WAIT0()  asm volatile("cp.async.wait_group 0;")

// ---------------------------------------------------------------------------
// Kernel 0a: weights fp32 -> bf16
// ---------------------------------------------------------------------------
__global__ __launch_bounds__(256) void k_prep(const float* __restrict__ qkvw,
                                              const float* __restrict__ pw,
                                              const float* __restrict__ w1,
                                              const float* __restrict__ w2) {
    int i = blockIdx.x * 256 + threadIdx.x;
    if (i < 27648)       g_bwq[i] = __float2bfloat16(qkvw[i]);
    else if (i < 36864)  g_bwp[i - 27648] = __float2bfloat16(pw[i - 27648]);
    else if (i < 73728)  g_bw1[i - 36864] = __float2bfloat16(w1[i - 36864]);
    else                 g_bw2[i - 73728] = __float2bfloat16(w2[i - 73728]);
}

// ---------------------------------------------------------------------------
// Kernel 0b: bias+mask class tables
// ---------------------------------------------------------------------------
__global__ __launch_bounds__(256) void k_tbl(const float* __restrict__ rel) {
    int cls = blockIdx.x;
    int re = cls >> 1, ce = cls & 1;
    for (int e = threadIdx.x; e < 49 * 56; e += 256) {
        int i = e / 56, j = e % 56;
        float v = 0.f;
        if (j < 49) {
            int idx = (i / 7 - j / 7 + 6) * 13 + (i % 7 - j % 7 + 6);
            v = rel[idx];
            int li = (re ? ((i / 7) < 4 ? 1 : 2) : 0) * 3 + (ce ? ((i % 7) < 4 ? 1 : 2) : 0);
            int lj = (re ? ((j / 7) < 4 ? 1 : 2) : 0) * 3 + (ce ? ((j % 7) < 4 ? 1 : 2) : 0);
            if (li != lj) v -= 100.f;
        }
        g_tbl[cls * 2744 + e] = __float2bfloat16(v);
    }
}

// ---------------------------------------------------------------------------
// Kernel 1: fused NCHW load + LN1 + QKV GEMM.
// Grid 3136, 128 tokens/CTA. smem (u32): xs fp32[96][132]@0 (12672),
// As[128][52]@12672, BA@19328 (4992); prefetch slots B0@0, B1@4992 overlay xs.
// ---------------------------------------------------------------------------
#define QKV_XS 0
#define QKV_AS 12672
#define QKV_BA 19328
#define QKV_SMEM_U 24320

__global__ __launch_bounds__(256) void k_qkv(const float* __restrict__ x,
                                             const float* __restrict__ lnw,
                                             const float* __restrict__ lnb,
                                             const float* __restrict__ bias) {
    extern __shared__ unsigned smem_u[];
    int tid = threadIdx.x;
    int lane = tid & 31, warp = tid >> 5;
    int warp_m = warp & 3, warp_n = warp >> 2;
    int g = lane >> 2, tig = lane & 3;
    int m0 = blockIdx.x * 128;
    int bb = m0 / HW, hw0 = m0 % HW;

    unsigned sbase = s2u(smem_u);
    // x tile: 96 ch x 128 tok fp32, 16B chunks (4 tokens)
#pragma unroll
    for (int l = 0; l < 12; ++l) {
        int o = tid + l * 256;
        int ch = o >> 5, t4 = o & 31;
        cp16(sbase + (QKV_XS + ch * 132 + t4 * 4) * 4,
             x + ((size_t)bb * 96 + ch) * HW + hw0 + t4 * 4);
    }
    // W block 0
#pragma unroll
    for (int l = 0; l < 5; ++l) {
        int o = tid + l * 256;
        if (o < 1152) {
            int row = o / 12, ch = o % 12;
            cp16(sbase + QKV_BA * 4 + row * 208 + ch * 16, g_bwq + (size_t)row * 96 + ch * 8);
        }
    }
    CP_COMMIT();
    CP_WAIT0();
    __syncthreads();

    // LN over channels; 2 threads per token
    {
        const float* xs = reinterpret_cast<const float*>(smem_u + QKV_XS);
        int r = tid >> 1, half = tid & 1;
        float vals[48];
        float s = 0.f, q = 0.f;
#pragma unroll
        for (int i = 0; i < 48; ++i) {
            float v = xs[(half * 48 + i) * 132 + r];
            vals[i] = v;
            s += v; q += v * v;
        }
        s += __shfl_xor_sync(0xffffffffu, s, 1);
        q += __shfl_xor_sync(0xffffffffu, q, 1);
        float mean = s * (1.f / 96.f);
        float var = q * (1.f / 96.f) - mean * mean;
        float rstd = rsqrtf(var + 1e-5f);
        __syncthreads();   // xs reads done everywhere before As overwrite is irrelevant (distinct), but B prefetch overlays xs later; ensure reads done
        unsigned* As = smem_u + QKV_AS;
#pragma unroll
        for (int i = 0; i < 24; ++i) {
            int c = half * 48 + i * 2;
            As[r * 52 + c / 2] = bf2u((vals[i * 2] - mean) * rstd * lnw[c] + lnb[c],
                                      (vals[i * 2 + 1] - mean) * rstd * lnw[c + 1] + lnb[c + 1]);
        }
    }
    __syncthreads();

    // prefetch W blocks 1,2 into xs-overlay slots
#pragma unroll
    for (int l = 0; l < 9; ++l) {
        int o = tid + l * 256;
        if (o < 2304) {
            int blk = o / 1152;         // 0 -> W1, 1 -> W2
            int oo = o % 1152;
            int row = oo / 12, ch = oo % 12;
            cp16(sbase + blk * 4992 * 4 + row * 208 + ch * 16,
                 g_bwq + (size_t)((blk + 1) * 96 + row) * 96 + ch * 8);
        }
    }
    CP_COMMIT();

    const unsigned* AsU = smem_u + QKV_AS;
    __nv_bfloat16* out = g_qkv;

    for (int nb = 0; nb < 3; ++nb) {
        if (nb == 1) { CP_WAIT0(); __syncthreads(); }
        const unsigned* BsU = (nb == 0) ? (smem_u + QKV_BA) : (smem_u + (nb - 1) * 4992);
        float acc[2][6][4];
#pragma unroll
        for (int mt = 0; mt < 2; ++mt)
#pragma unroll
            for (int nt = 0; nt < 6; ++nt)
#pragma unroll
                for (int qq = 0; qq < 4; ++qq) acc[mt][nt][qq] = 0.f;
#pragma unroll
        for (int ks = 0; ks < 6; ++ks) {
            unsigned a[2][4];
#pragma unroll
            for (int mt = 0; mt < 2; ++mt) {
                int r = warp_m * 32 + mt * 16 + g;
                a[mt][0] = AsU[r * 52 + ks * 8 + tig];
                a[mt][2] = AsU[r * 52 + ks * 8 + tig + 4];
                a[mt][1] = AsU[(r + 8) * 52 + ks * 8 + tig];
                a[mt][3] = AsU[(r + 8) * 52 + ks * 8 + tig + 4];
            }
#pragma unroll
            for (int nt = 0; nt < 6; ++nt) {
                int cb = warp_n * 48 + nt * 8 + g;
                unsigned b0 = BsU[cb * 52 + ks * 8 + tig];
                unsigned b1 = BsU[cb * 52 + ks * 8 + tig + 4];
#pragma unroll
                for (int mt = 0; mt < 2; ++mt)
                    mma16(acc[mt][nt], a[mt], b0, b1);
            }
        }
#pragma unroll
        for (int mt = 0; mt < 2; ++mt) {
            int r0 = m0 + warp_m * 32 + mt * 16 + g;
#pragma unroll
            for (int nt = 0; nt < 6; ++nt) {
                int col = nb * 96 + warp_n * 48 + nt * 8 + 2 * tig;
                float bi0 = bias[col], bi1 = bias[col + 1];
                *reinterpret_cast<unsigned*>(&out[(size_t)r0 * 288 + col]) =
                    bf2u(acc[mt][nt][0] + bi0, acc[mt][nt][1] + bi1);
                *reinterpret_cast<unsigned*>(&out[(size_t)(r0 + 8) * 288 + col]) =
                    bf2u(acc[mt][nt][2] + bi0, acc[mt][nt][3] + bi1);
            }
        }
    }
}

// ---------------------------------------------------------------------------
// K=96 GEMM (proj), full-K cp.async. MODE 3 epilogue: +x residual, LN2 fused.
// ---------------------------------------------------------------------------
__global__ __launch_bounds__(256) void k_proj(const __nv_bfloat16* __restrict__ A,
                                              const __nv_bfloat16* __restrict__ W,
                                              const float* __restrict__ bias,
                                              const float* __restrict__ res,
                                              float* __restrict__ hout,
                                              const float* __restrict__ lnw,
                                              const float* __restrict__ lnb,
                                              __nv_bfloat16* __restrict__ out2) {
    extern __shared__ unsigned smem_u[];
    int tid = threadIdx.x;
    int lane = tid & 31, warp = tid >> 5;
    int warp_m = warp & 3, warp_n = warp >> 2;
    int g = lane >> 2, tig = lane & 3;
    int m0 = blockIdx.x * 128;

    unsigned sbase = s2u(smem_u);
#pragma unroll
    for (int l = 0; l < 6; ++l) {
        int o = tid + l * 256;
        int row = o / 12, ch = o % 12;
        cp16(sbase + row * 208 + ch * 16, A + (size_t)(m0 + row) * 96 + ch * 8);
    }
#pragma unroll
    for (int l = 0; l < 5; ++l) {
        int o = tid + l * 256;
        if (o < 1152) {
            int row = o / 12, ch = o % 12;
            cp16(sbase + 26624 + row * 208 + ch * 16, W + (size_t)row * 96 + ch * 8);
        }
    }
    CP_COMMIT();

    float acc[2][6][4];
#pragma unroll
    for (int mt = 0; mt < 2; ++mt)
#pragma unroll
        for (int nt = 0; nt < 6; ++nt)
#pragma unroll
            for (int q = 0; q < 4; ++q) acc[mt][nt][q] = 0.f;

    CP_WAIT0();
    __syncthreads();

    const unsigned* AsU = smem_u;
    const unsigned* BsU = smem_u + 6656;
#pragma unroll
    for (int ks = 0; ks < 6; ++ks) {
        unsigned a[2][4];
#pragma unroll
        for (int mt = 0; mt < 2; ++mt) {
            int r = warp_m * 32 + mt * 16 + g;
            a[mt][0] = AsU[r * 52 + ks * 8 + tig];
            a[mt][2] = AsU[r * 52 + ks * 8 + tig + 4];
            a[mt][1] = AsU[(r + 8) * 52 + ks * 8 + tig];
            a[mt][3] = AsU[(r + 8) * 52 + ks * 8 + tig + 4];
        }
#pragma unroll
        for (int nt = 0; nt < 6; ++nt) {
            int cb = warp_n * 48 + nt * 8 + g;
            unsigned b0 = BsU[cb * 52 + ks * 8 + tig];
            unsigned b1 = BsU[cb * 52 + ks * 8 + tig + 4];
#pragma unroll
            for (int mt = 0; mt < 2; ++mt)
                mma16(acc[mt][nt], a[mt], b0, b1);
        }
    }

    float (*st)[100] = reinterpret_cast<float (*)[100]>(smem_u);
    __syncthreads();
#pragma unroll
    for (int mt = 0; mt < 2; ++mt) {
        int lr0 = warp_m * 32 + mt * 16 + g;
#pragma unroll
        for (int nt = 0; nt < 6; ++nt) {
            int col = warp_n * 48 + nt * 8 + 2 * tig;
            float bi0 = bias[col], bi1 = bias[col + 1];
            st[lr0][col]         = acc[mt][nt][0] + bi0;
            st[lr0][col + 1]     = acc[mt][nt][1] + bi1;
            st[lr0 + 8][col]     = acc[mt][nt][2] + bi0;
            st[lr0 + 8][col + 1] = acc[mt][nt][3] + bi1;
        }
    }
    __syncthreads();
    int r = tid >> 1, half = tid & 1;
    int bb = m0 / HW, hw0 = m0 % HW;
    const float* xb = res + (size_t)bb * 96 * HW + hw0 + r;
    float vals[48];
    float s = 0.f, q = 0.f;
#pragma unroll
    for (int i = 0; i < 12; ++i) {
        float4 v = *reinterpret_cast<const float4*>(&st[r][half * 48 + i * 4]);
        float h0 = v.x + xb[(size_t)(half * 48 + i * 4 + 0) * HW];
        float h1 = v.y + xb[(size_t)(half * 48 + i * 4 + 1) * HW];
        float h2 = v.z + xb[(size_t)(half * 48 + i * 4 + 2) * HW];
        float h3 = v.w + xb[(size_t)(half * 48 + i * 4 + 3) * HW];
        vals[i * 4 + 0] = h0; vals[i * 4 + 1] = h1;
        vals[i * 4 + 2] = h2; vals[i * 4 + 3] = h3;
        s += h0 + h1 + h2 + h3;
        q += h0 * h0 + h1 * h1 + h2 * h2 + h3 * h3;
    }
    s += __shfl_xor_sync(0xffffffffu, s, 1);
    q += __shfl_xor_sync(0xffffffffu, q, 1);
    float mean = s * (1.f / 96.f);
    float var = q * (1.f / 96.f) - mean * mean;
    float rstd = rsqrtf(var + 1e-5f);
    float* hp = hout + (size_t)(m0 + r) * 96 + half * 48;
    __nv_bfloat16* lp = out2 + (size_t)(m0 + r) * 96 + half * 48;
#pragma unroll
    for (int i = 0; i < 12; ++i) {
        int c = half * 48 + i * 4;
        *reinterpret_cast<float4*>(hp + i * 4) =
            make_float4(vals[i * 4], vals[i * 4 + 1], vals[i * 4 + 2], vals[i * 4 + 3]);
        uint2 uu;
        uu.x = bf2u((vals[i * 4 + 0] - mean) * rstd * lnw[c + 0] + lnb[c + 0],
                    (vals[i * 4 + 1] - mean) * rstd * lnw[c + 1] + lnb[c + 1]);
        uu.y = bf2u((vals[i * 4 + 2] - mean) * rstd * lnw[c + 2] + lnb[c + 2],
                    (vals[i * 4 + 3] - mean) * rstd * lnw[c + 3] + lnb[c + 3]);
        *reinterpret_cast<uint2*>(lp + i * 4) = uu;
    }
}

// ---------------------------------------------------------------------------
// Fused MLP: m1 = gelu(ln2@W1^T+b1) in smem; out = m1@W2^T + b2 + h, NCHW.
// BM=64. smem (u32): A[64][52]@0 (3328), M[64][196]@3328 (12544),
// W slots @15872, @20864 (4992 each). Total 25856 u = 103424 B.
// Warps: 2(M) x 4(N); warp tile 32 x 24 (2 mt x 3 nt).
// ---------------------------------------------------------------------------
#define MLP_M 3328
#define MLP_W0 15872
#define MLP_W1 20864
#define MLP_SMEM_U 25856

__global__ __launch_bounds__(256) void k_mlp(const __nv_bfloat16* __restrict__ A,
                                             const float* __restrict__ b1,
                                             const float* __restrict__ b2,
                                             const float* __restrict__ res,
                                             float* __restrict__ out) {
    extern __shared__ unsigned smem_u[];
    int tid = threadIdx.x;
    int lane = tid & 31, warp = tid >> 5;
    int warp_m = warp & 1, warp_n = warp >> 1;
    int g = lane >> 2, tig = lane & 3;
    int m0 = blockIdx.x * 64;

    unsigned sbase = s2u(smem_u);
    // A tile: 64 rows x 12 chunks
#pragma unroll
    for (int l = 0; l < 3; ++l) {
        int o = tid + l * 256;
        int row = o / 12, ch = o % 12;
        cp16(sbase + row * 208 + ch * 16, A + (size_t)(m0 + row) * 96 + ch * 8);
    }
    // W1 block 0
#pragma unroll
    for (int l = 0; l < 5; ++l) {
        int o = tid + l * 256;
        if (o < 1152) {
            int row = o / 12, ch = o % 12;
            cp16(sbase + MLP_W0 * 4 + row * 208 + ch * 16, g_bw1 + (size_t)row * 96 + ch * 8);
        }
    }
    CP_COMMIT();

    const unsigned* AsU = smem_u;
    unsigned* MU = smem_u + MLP_M;
    const unsigned wslot[2] = {MLP_W0, MLP_W1};

    // ---- phase 1: 4 N-blocks of MLP1 + GELU -> M smem ---------------------
    for (int nb = 0; nb < 4; ++nb) {
        CP_WAIT0();
        __syncthreads();
        if (nb < 3) {
#pragma unroll
            for (int l = 0; l < 5; ++l) {
                int o = tid + l * 256;
                if (o < 1152) {
                    int row = o / 12, ch = o % 12;
                    cp16(sbase + wslot[(nb + 1) & 1] * 4 + row * 208 + ch * 16,
                         g_bw1 + (size_t)((nb + 1) * 96 + row) * 96 + ch * 8);
                }
            }
            CP_COMMIT();
        } else {
            // prefetch W2 chunk 0 into the other slot
#pragma unroll
            for (int l = 0; l < 5; ++l) {
                int o = tid + l * 256;
                if (o < 1152) {
                    int row = o / 12, ch = o % 12;
                    cp16(sbase + wslot[(nb + 1) & 1] * 4 + row * 208 + ch * 16,
                         g_bw2 + (size_t)row * 384 + ch * 8);
                }
            }
            CP_COMMIT();
        }
        const unsigned* BsU = smem_u + wslot[nb & 1];
        float acc[2][3][4];
#pragma unroll
        for (int mt = 0; mt < 2; ++mt)
#pragma unroll
            for (int nt = 0; nt < 3; ++nt)
#pragma unroll
                for (int q = 0; q < 4; ++q) acc[mt][nt][q] = 0.f;
#pragma unroll
        for (int ks = 0; ks < 6; ++ks) {
            unsigned a[2][4];
#pragma unroll
            for (int mt = 0; mt < 2; ++mt) {
                int r = warp_m * 32 + mt * 16 + g;
                a[mt][0] = AsU[r * 52 + ks * 8 + tig];
                a[mt][2] = AsU[r * 52 + ks * 8 + tig + 4];
                a[mt][1] = AsU[(r + 8) * 52 + ks * 8 + tig];
                a[mt][3] = AsU[(r + 8) * 52 + ks * 8 + tig + 4];
            }
#pragma unroll
            for (int nt = 0; nt < 3; ++nt) {
                int cb = warp_n * 24 + nt * 8 + g;
                unsigned b0 = BsU[cb * 52 + ks * 8 + tig];
                unsigned b1 = BsU[cb * 52 + ks * 8 + tig + 4];
#pragma unroll
                for (int mt = 0; mt < 2; ++mt)
                    mma16(acc[mt][nt], a[mt], b0, b1);
            }
        }
        // GELU + store bf16 to M
#pragma unroll
        for (int mt = 0; mt < 2; ++mt) {
            int r0 = warp_m * 32 + mt * 16 + g;
#pragma unroll
            for (int nt = 0; nt < 3; ++nt) {
                int col = warp_n * 24 + nt * 8 + 2 * tig;
                float bi0 = b1[nb * 96 + col], bi1 = b1[nb * 96 + col + 1];
                float v0 = acc[mt][nt][0] + bi0, v1 = acc[mt][nt][1] + bi1;
                float v2 = acc[mt][nt][2] + bi0, v3 = acc[mt][nt][3] + bi1;
                v0 = 0.5f * v0 * (1.0f + erff(v0 * 0.70710678118654752f));
                v1 = 0.5f * v1 * (1.0f + erff(v1 * 0.70710678118654752f));
                v2 = 0.5f * v2 * (1.0f + erff(v2 * 0.70710678118654752f));
                v3 = 0.5f * v3 * (1.0f + erff(v3 * 0.70710678118654752f));
                MU[r0 * 196 + nb * 48 + col / 2] = bf2u(v0, v1);
                MU[(r0 + 8) * 196 + nb * 48 + col / 2] = bf2u(v2, v3);
            }
        }
    }

    // ---- phase 2: out = M @ W2^T over 4 K-chunks --------------------------
    float acc2[2][3][4];
#pragma unroll
    for (int mt = 0; mt < 2; ++mt)
#pragma unroll
        for (int nt = 0; nt < 3; ++nt)
#pragma unroll
            for (int q = 0; q < 4; ++q) acc2[mt][nt][q] = 0.f;

    for (int kc = 0; kc < 4; ++kc) {
        CP_WAIT0();
        __syncthreads();   // also fences phase-1 M writes on kc==0
        if (kc < 3) {
#pragma unroll
            for (int l = 0; l < 5; ++l) {
                int o = tid + l * 256;
                if (o < 1152) {
                    int row = o / 12, ch = o % 12;
                    cp16(sbase + wslot[(kc + 1) & 1] * 4 + row * 208 + ch * 16,
                         g_bw2 + (size_t)row * 384 + (kc + 1) * 96 + ch * 8);
                }
            }
            CP_COMMIT();
        }
        const unsigned* BsU = smem_u + wslot[kc & 1];
#pragma unroll
        for (int ks = 0; ks < 6; ++ks) {
            unsigned a[2][4];
#pragma unroll
            for (int mt = 0; mt < 2; ++mt) {
                int r = warp_m * 32 + mt * 16 + g;
                a[mt][0] = MU[r * 196 + kc * 48 + ks * 8 + tig];
                a[mt][2] = MU[r * 196 + kc * 48 + ks * 8 + tig + 4];
                a[mt][1] = MU[(r + 8) * 196 + kc * 48 + ks * 8 + tig];
                a[mt][3] = MU[(r + 8) * 196 + kc * 48 + ks * 8 + tig + 4];
            }
#pragma unroll
            for (int nt = 0; nt < 3; ++nt) {
                int cb = warp_n * 24 + nt * 8 + g;
                unsigned b0 = BsU[cb * 52 + ks * 8 + tig];
                unsigned b1 = BsU[cb * 52 + ks * 8 + tig + 4];
#pragma unroll
                for (int mt = 0; mt < 2; ++mt)
                    mma16(acc2[mt][nt], a[mt], b0, b1);
            }
        }
    }

    // ---- epilogue: +b2 +h residual, NCHW store ----------------------------
    __syncthreads();
    float (*st)[98] = reinterpret_cast<float (*)[98]>(smem_u + MLP_M);
#pragma unroll
    for (int mt = 0; mt < 2; ++mt) {
        int lr0 = warp_m * 32 + mt * 16 + g;
        int r0 = m0 + lr0;
#pragma unroll
        for (int nt = 0; nt < 3; ++nt) {
            int col = warp_n * 24 + nt * 8 + 2 * tig;
            float bi0 = b2[col], bi1 = b2[col + 1];
            float2 rs0 = *reinterpret_cast<const float2*>(&res[(size_t)r0 * 96 + col]);
            float2 rs1 = *reinterpret_cast<const float2*>(&res[(size_t)(r0 + 8) * 96 + col]);
            *reinterpret_cast<float2*>(&st[lr0][col]) =
                make_float2(acc2[mt][nt][0] + bi0 + rs0.x, acc2[mt][nt][1] + bi1 + rs0.y);
            *reinterpret_cast<float2*>(&st[lr0 + 8][col]) =
                make_float2(acc2[mt][nt][2] + bi0 + rs1.x, acc2[mt][nt][3] + bi1 + rs1.y);
        }
    }
    __syncthreads();
    int bb = m0 / HW, hw0 = m0 % HW;
    float* ob = out + (size_t)bb * 96 * HW + hw0;
#pragma unroll
    for (int l = 0; l < 24; ++l) {
        int e = tid + l * 256;
        int ch = e >> 6, tok = e & 63;
        ob[(size_t)ch * HW + tok] = st[tok][ch];
    }
}

// ---------------------------------------------------------------------------
// Attention (unchanged from round 6)
// ---------------------------------------------------------------------------
#define QS_U 0
#define KS_U 3328
#define VT_U 6656
#define AT_U 10112
#define TB_U 12416
#define SM_ATTN_U (TB_U + 1372)

__global__ __launch_bounds__(256) void k_attn() {
    extern __shared__ unsigned smem_u[];
    __shared__ int tok_s[49];

    int win = blockIdx.x;
    int bb = win >> 10;
    int wr = (win >> 5) & 31;
    int wc = win & 31;
    int tid = threadIdx.x;
    int lane = tid & 31, warp = tid >> 5;
    int g = lane >> 2, tig = lane & 3;
    int mt = warp & 3, nhalf = warp >> 2;
    int cls = ((wr == 31) ? 2 : 0) + ((wc == 31) ? 1 : 0);

    if (tid < 49) {
        int i = tid / 7, j = tid % 7;
        int sr = wr * 7 + i, sc = wc * 7 + j;
        int r = sr + 3; if (r >= 224) r -= 224;
        int c = sc + 3; if (c >= 224) c -= 224;
        tok_s[tid] = bb * HW + r * 224 + c;
    }
    for (int e = tid; e < 3456; e += 256) smem_u[VT_U + e] = 0u;
    __syncthreads();

    unsigned sbase = s2u(smem_u);
#pragma unroll
    for (int l = 0; l < 5; ++l) {
        int e = tid + l * 256;
        if (e < 1176) {
            int half = e >= 588;
            int ee = e - half * 588;
            int row = ee / 12, ch = ee % 12;
            const __nv_bfloat16* src = g_qkv + (size_t)tok_s[row] * 288 + half * 96 + ch * 8;
            cp16(sbase + (half ? KS_U * 4 : 0) + row * 208 + ch * 16, src);
        }
    }
    {
        const __nv_bfloat16* tsrc = g_tbl + cls * 2744;
        for (int o = tid; o < 343; o += 256)
            cp16(sbase + TB_U * 4 + o * 16, tsrc + o * 8);
    }
    CP_COMMIT();
    {
        __nv_bfloat16* vth = reinterpret_cast<__nv_bfloat16*>(smem_u + VT_U);
#pragma unroll
        for (int l = 0; l < 5; ++l) {
            int e = tid + l * 256;
            if (e < 1176) {
                int row = e / 24, c4 = (e % 24) * 4;
                uint2 raw = *reinterpret_cast<const uint2*>(
                    g_qkv + (size_t)tok_s[row] * 288 + 192 + c4);
                __nv_bfloat162 p0 = *reinterpret_cast<__nv_bfloat162*>(&raw.x);
                __nv_bfloat162 p1 = *reinterpret_cast<__nv_bfloat162*>(&raw.y);
                vth[(c4 + 0) * 72 + row] = p0.x;
                vth[(c4 + 1) * 72 + row] = p0.y;
                vth[(c4 + 2) * 72 + row] = p1.x;
                vth[(c4 + 3) * 72 + row] = p1.y;
            }
        }
    }
    CP_WAIT0();
    __syncthreads();

    float acc[4][4];
#pragma unroll
    for (int t = 0; t < 4; ++t)
#pragma unroll
        for (int q = 0; q < 4; ++q) acc[t][q] = 0.f;
    {
        const unsigned* qsU = smem_u + QS_U;
        const unsigned* ksU = smem_u + KS_U;
#pragma unroll
        for (int ks = 0; ks < 6; ++ks) {
            unsigned a[4];
            int r = mt * 16 + g;
            a[0] = qsU[r * 52 + ks * 8 + tig];
            a[2] = qsU[r * 52 + ks * 8 + tig + 4];
            a[1] = qsU[(r + 8) * 52 + ks * 8 + tig];
            a[3] = qsU[(r + 8) * 52 + ks * 8 + tig + 4];
#pragma unroll
            for (int t = 0; t < 4; ++t) {
                int cb = (nhalf * 4 + t) * 8 + g;
                unsigned b0 = ksU[cb * 52 + ks * 8 + tig];
                unsigned b1 = ksU[cb * 52 + ks * 8 + tig + 4];
                mma16(acc[t], a, b0, b1);
            }
        }
    }
    __syncthreads();

    {
        float* sc = reinterpret_cast<float*>(smem_u);
        const __nv_bfloat16* tb = reinterpret_cast<const __nv_bfloat16*>(smem_u + TB_U);
        const float scale = 0.10206207261596575f;
#pragma unroll
        for (int t = 0; t < 4; ++t) {
            int j0 = (nhalf * 4 + t) * 8 + 2 * tig;
#pragma unroll
            for (int rr = 0; rr < 2; ++rr) {
                int i = mt * 16 + g + rr * 8;
                float v0 = acc[t][rr * 2 + 0] * scale;
                float v1 = acc[t][rr * 2 + 1] * scale;
                if (i < 49 && j0 < 56) {
                    __nv_bfloat162 t2 = *reinterpret_cast<const __nv_bfloat162*>(&tb[i * 56 + j0]);
                    v0 += __bfloat162float(t2.x);
                    v1 += __bfloat162float(t2.y);
                }
                *reinterpret_cast<float2*>(&sc[i * 68 + j0]) = make_float2(v0, v1);
            }
        }
    }
    __syncthreads();

    {
        float* sc = reinterpret_cast<float*>(smem_u);
        __nv_bfloat16* atth = reinterpret_cast<__nv_bfloat16*>(smem_u + AT_U);
        for (int row = warp; row < 49; row += 8) {
            float x0 = sc[row * 68 + lane];
            float x1 = (lane + 32 < 49) ? sc[row * 68 + lane + 32] : -1e30f;
            float mx = fmaxf(x0, x1);
            for (int o = 16; o; o >>= 1) mx = fmaxf(mx, __shfl_xor_sync(0xffffffffu, mx, o));
            float e0 = __expf(x0 - mx);
            float e1 = (lane + 32 < 49) ? __expf(x1 - mx) : 0.f;
            float sum = e0 + e1;
            for (int o = 16; o; o >>= 1) sum += __shfl_xor_sync(0xffffffffu, sum, o);
            float inv = 1.0f / sum;
            atth[row * 72 + lane] = __float2bfloat16(e0 * inv);
            atth[row * 72 + lane + 32] = __float2bfloat16((lane + 32 < 49) ? e1 * inv : 0.f);
        }
    }
    __syncthreads();

    {
        const unsigned* atU = smem_u + AT_U;
        const unsigned* vtU = smem_u + VT_U;
        float av[6][4];
#pragma unroll
        for (int t = 0; t < 6; ++t)
#pragma unroll
            for (int q = 0; q < 4; ++q) av[t][q] = 0.f;
#pragma unroll
        for (int ks = 0; ks < 4; ++ks) {
            unsigned a[4];
            int r = mt * 16 + g;
            a[0] = atU[r * 36 + ks * 8 + tig];
            a[2] = atU[r * 36 + ks * 8 + tig + 4];
            a[1] = atU[(r + 8) * 36 + ks * 8 + tig];
            a[3] = atU[(r + 8) * 36 + ks * 8 + tig + 4];
#pragma unroll
            for (int t = 0; t < 6; ++t) {
                int cb = (nhalf * 6 + t) * 8 + g;
                unsigned b0 = vtU[cb * 36 + ks * 8 + tig];
                unsigned b1 = vtU[cb * 36 + ks * 8 + tig + 4];
                mma16(av[t], a, b0, b1);
            }
        }
#pragma unroll
        for (int t = 0; t < 6; ++t) {
            int ch = (nhalf * 6 + t) * 8 + 2 * tig;
#pragma unroll
            for (int rr = 0; rr < 2; ++rr) {
                int r = mt * 16 + g + rr * 8;
                if (r < 49) {
                    *reinterpret_cast<unsigned*>(&g_ctx[(size_t)tok_s[r] * 96 + ch]) =
                        bf2u(av[t][rr * 2 + 0], av[t][rr * 2 + 1]);
                }
            }
        }
    }
}

// ---------------------------------------------------------------------------
extern "C" void kernel_launch(void* const* d_in, const int* in_sizes, int n_in,
                              void* d_out, int out_size) {
    const float* x    = (const float*)d_in[0];
    const float* n1w  = (const float*)d_in[1];
    const float* n1b  = (const float*)d_in[2];
    const float* qkvw = (const float*)d_in[3];
    const float* qkvb = (const float*)d_in[4];
    const float* rel  = (const float*)d_in[5];
    const float* pw   = (const float*)d_in[6];
    const float* pb   = (const float*)d_in[7];
    const float* n2w  = (const float*)d_in[8];
    const float* n2b  = (const float*)d_in[9];
    const float* w1   = (const float*)d_in[10];
    const float* b1   = (const float*)d_in[11];
    const float* w2   = (const float*)d_in[12];
    const float* b2   = (const float*)d_in[13];
    float* out = (float*)d_out;

    void *p_qkv, *p_ctx, *p_h, *p_ln2, *p_bwp;
    cudaGetSymbolAddress(&p_qkv, g_qkv);
    cudaGetSymbolAddress(&p_ctx, g_ctx);
    cudaGetSymbolAddress(&p_h,   g_h);
    cudaGetSymbolAddress(&p_ln2, g_ln2);
    cudaGetSymbolAddress(&p_bwp, g_bwp);

    const int SMQKV  = QKV_SMEM_U * 4;    // 97280
    const int SMPROJ = 128 * 100 * 4;     // 51200
    const int SMMLP  = MLP_SMEM_U * 4;    // 103424
    const int SMATTN = SM_ATTN_U * 4;     // 55152

    cudaFuncSetAttribute(k_qkv,  cudaFuncAttributeMaxDynamicSharedMemorySize, SMQKV);
    cudaFuncSetAttribute(k_proj, cudaFuncAttributeMaxDynamicSharedMemorySize, SMPROJ);
    cudaFuncSetAttribute(k_mlp,  cudaFuncAttributeMaxDynamicSharedMemorySize, SMMLP);
    cudaFuncSetAttribute(k_attn, cudaFuncAttributeMaxDynamicSharedMemorySize, SMATTN);

    // 0) weight conversion + class tables
    k_prep<<<432, 256>>>(qkvw, pw, w1, w2);
    k_tbl<<<4, 256>>>(rel);
    // 1) fused NCHW + LN1 + QKV
    k_qkv<<<3136, 256, SMQKV>>>(x, n1w, n1b, qkvb);
    // 2) attention
    k_attn<<<NWIN, 256, SMATTN>>>();
    // 3) proj + x residual + fused LN2
    k_proj<<<3136, 256, SMPROJ>>>(
        (const __nv_bfloat16*)p_ctx, (const __nv_bfloat16*)p_bwp, pb,
        x, (float*)p_h, n2w, n2b, (__nv_bfloat16*)p_ln2);
    // 4) fused MLP (MLP1+GELU+MLP2+residual+NCHW out)
    k_mlp<<<6272, 256, SMMLP>>>(
        (const __nv_bfloat16*)p_ln2, b1, b2, (const float*)p_h, out);
}

// round 8
// speedup vs baseline: 5.5329x; 1.0958x over previous
#include <cuda_runtime.h>
#include <cuda_bf16.h>
#include <math.h>

#define HW 50176              // 224*224
#define L_TOK 401408          // 8*224*224
#define NWIN 8192

// Scratch
__device__ __nv_bfloat16 g_qkv[(size_t)L_TOK * 288];
__device__ __nv_bfloat16 g_ctx[(size_t)L_TOK * 96];
__device__ float         g_h[(size_t)L_TOK * 96];
__device__ __nv_bfloat16 g_ln2[(size_t)L_TOK * 96];
// bf16 weights
__device__ __nv_bfloat16 g_bwq[288 * 96];
__device__ __nv_bfloat16 g_bwp[96 * 96];
__device__ __nv_bfloat16 g_bw1[384 * 96];
__device__ __nv_bfloat16 g_bw2[96 * 384];
// combined rel-pos bias + shift-mask tables, 4 window classes, [49][56] bf16
__device__ __nv_bfloat16 g_tbl[4 * 49 * 56];

// ---- helpers --------------------------------------------------------------
__device__ __forceinline__ unsigned bf2u(float a, float b) {
    __nv_bfloat162 h = __floats2bfloat162_rn(a, b);
    return *reinterpret_cast<unsigned*>(&h);
}
__device__ __forceinline__ void mma16(float* c, const unsigned* a,
                                      unsigned b0, unsigned b1) {
    asm("mma.sync.aligned.m16n8k16.row.col.f32.bf16.bf16.f32 "
        "{%0,%1,%2,%3}, {%4,%5,%6,%7}, {%8,%9}, {%0,%1,%2,%3};"
        : "+f"(c[0]), "+f"(c[1]), "+f"(c[2]), "+f"(c[3])
        : "r"(a[0]), "r"(a[1]), "r"(a[2]), "r"(a[3]), "r"(b0), "r"(b1));
}
__device__ __forceinline__ unsigned s2u(const void* p) {
    return (unsigned)__cvta_generic_to_shared(p);
}
__device__ __forceinline__ void cp16(unsigned dst, const void* src) {
    asm volatile("cp.async.cg.shared.global [%0], [%1], 16;" :: "r"(dst), "l"(src));
}
#define CP_COMMIT() asm volatile("cp.async.commit_group;")
#define CP_WAIT0()  asm volatile("cp.async.wait_group 0;")

__device__ __forceinline__ void ldsm_x4(unsigned& r0, unsigned& r1,
                                        unsigned& r2, unsigned& r3, unsigned addr) {
    asm volatile("ldmatrix.sync.aligned.m8n8.x4.shared.b16 {%0,%1,%2,%3}, [%4];"
                 : "=r"(r0), "=r"(r1), "=r"(r2), "=r"(r3) : "r"(addr));
}
__device__ __forceinline__ void ldsm_x2(unsigned& r0, unsigned& r1, unsigned addr) {
    asm volatile("ldmatrix.sync.aligned.m8n8.x2.shared.b16 {%0,%1}, [%2];"
                 : "=r"(r0), "=r"(r1) : "r"(addr));
}
__device__ __forceinline__ void ldsm_x2t(unsigned& r0, unsigned& r1, unsigned addr) {
    asm volatile("ldmatrix.sync.aligned.m8n8.x2.trans.shared.b16 {%0,%1}, [%2];"
                 : "=r"(r0), "=r"(r1) : "r"(addr));
}
// A fragment (16x16): rows r0.., k-chunk byte offset ksB, row stride strideB
__device__ __forceinline__ void lda_frag(unsigned* a, unsigned baseB, int r0,
                                         int ksB, int strideB, int lane) {
    unsigned addr = baseB + (unsigned)((r0 + (lane & 15)) * strideB + ksB + (lane >> 4) * 16);
    ldsm_x4(a[0], a[1], a[2], a[3], addr);
}
// B fragment (n8 x k16): n-rows cb.., k-chunk byte offset ksB
__device__ __forceinline__ void ldb_frag(unsigned& b0, unsigned& b1, unsigned baseB,
                                         int cb, int ksB, int strideB, int lane) {
    unsigned addr = baseB + (unsigned)((cb + (lane & 7)) * strideB + ksB + ((lane >> 3) & 1) * 16);
    ldsm_x2(b0, b1, addr);
}

// ---------------------------------------------------------------------------
// Kernel 0a: weights fp32 -> bf16
// ---------------------------------------------------------------------------
__global__ __launch_bounds__(256) void k_prep(const float* __restrict__ qkvw,
                                              const float* __restrict__ pw,
                                              const float* __restrict__ w1,
                                              const float* __restrict__ w2) {
    int i = blockIdx.x * 256 + threadIdx.x;
    if (i < 27648)       g_bwq[i] = __float2bfloat16(qkvw[i]);
    else if (i < 36864)  g_bwp[i - 27648] = __float2bfloat16(pw[i - 27648]);
    else if (i < 73728)  g_bw1[i - 36864] = __float2bfloat16(w1[i - 36864]);
    else                 g_bw2[i - 73728] = __float2bfloat16(w2[i - 73728]);
}

// ---------------------------------------------------------------------------
// Kernel 0b: bias+mask class tables
// ---------------------------------------------------------------------------
__global__ __launch_bounds__(256) void k_tbl(const float* __restrict__ rel) {
    int cls = blockIdx.x;
    int re = cls >> 1, ce = cls & 1;
    for (int e = threadIdx.x; e < 49 * 56; e += 256) {
        int i = e / 56, j = e % 56;
        float v = 0.f;
        if (j < 49) {
            int idx = (i / 7 - j / 7 + 6) * 13 + (i % 7 - j % 7 + 6);
            v = rel[idx];
            int li = (re ? ((i / 7) < 4 ? 1 : 2) : 0) * 3 + (ce ? ((i % 7) < 4 ? 1 : 2) : 0);
            int lj = (re ? ((j / 7) < 4 ? 1 : 2) : 0) * 3 + (ce ? ((j % 7) < 4 ? 1 : 2) : 0);
            if (li != lj) v -= 100.f;
        }
        g_tbl[cls * 2744 + e] = __float2bfloat16(v);
    }
}

// ---------------------------------------------------------------------------
// Kernel 1: fused NCHW load + LN1 + QKV GEMM.
// ---------------------------------------------------------------------------
#define QKV_XS 0
#define QKV_AS 12672
#define QKV_BA 19328
#define QKV_SMEM_U 24320

__global__ __launch_bounds__(256) void k_qkv(const float* __restrict__ x,
                                             const float* __restrict__ lnw,
                                             const float* __restrict__ lnb,
                                             const float* __restrict__ bias) {
    extern __shared__ unsigned smem_u[];
    int tid = threadIdx.x;
    int lane = tid & 31, warp = tid >> 5;
    int warp_m = warp & 3, warp_n = warp >> 2;
    int g = lane >> 2, tig = lane & 3;
    int m0 = blockIdx.x * 128;
    int bb = m0 / HW, hw0 = m0 % HW;

    unsigned sbase = s2u(smem_u);
#pragma unroll
    for (int l = 0; l < 12; ++l) {
        int o = tid + l * 256;
        int ch = o >> 5, t4 = o & 31;
        cp16(sbase + (QKV_XS + ch * 132 + t4 * 4) * 4,
             x + ((size_t)bb * 96 + ch) * HW + hw0 + t4 * 4);
    }
#pragma unroll
    for (int l = 0; l < 5; ++l) {
        int o = tid + l * 256;
        if (o < 1152) {
            int row = o / 12, ch = o % 12;
            cp16(sbase + QKV_BA * 4 + row * 208 + ch * 16, g_bwq + (size_t)row * 96 + ch * 8);
        }
    }
    CP_COMMIT();
    CP_WAIT0();
    __syncthreads();

    {
        const float* xs = reinterpret_cast<const float*>(smem_u + QKV_XS);
        int r = tid >> 1, half = tid & 1;
        float vals[48];
        float s = 0.f, q = 0.f;
#pragma unroll
        for (int i = 0; i < 48; ++i) {
            float v = xs[(half * 48 + i) * 132 + r];
            vals[i] = v;
            s += v; q += v * v;
        }
        s += __shfl_xor_sync(0xffffffffu, s, 1);
        q += __shfl_xor_sync(0xffffffffu, q, 1);
        float mean = s * (1.f / 96.f);
        float var = q * (1.f / 96.f) - mean * mean;
        float rstd = rsqrtf(var + 1e-5f);
        __syncthreads();
        unsigned* As = smem_u + QKV_AS;
#pragma unroll
        for (int i = 0; i < 24; ++i) {
            int c = half * 48 + i * 2;
            As[r * 52 + c / 2] = bf2u((vals[i * 2] - mean) * rstd * lnw[c] + lnb[c],
                                      (vals[i * 2 + 1] - mean) * rstd * lnw[c + 1] + lnb[c + 1]);
        }
    }
    __syncthreads();

#pragma unroll
    for (int l = 0; l < 9; ++l) {
        int o = tid + l * 256;
        if (o < 2304) {
            int blk = o / 1152;
            int oo = o % 1152;
            int row = oo / 12, ch = oo % 12;
            cp16(sbase + blk * 4992 * 4 + row * 208 + ch * 16,
                 g_bwq + (size_t)((blk + 1) * 96 + row) * 96 + ch * 8);
        }
    }
    CP_COMMIT();

    unsigned aBase = sbase + QKV_AS * 4;
    __nv_bfloat16* out = g_qkv;

    for (int nb = 0; nb < 3; ++nb) {
        if (nb == 1) { CP_WAIT0(); __syncthreads(); }
        unsigned bBase = (nb == 0) ? (sbase + QKV_BA * 4) : (sbase + (nb - 1) * 4992 * 4);
        float acc[2][6][4];
#pragma unroll
        for (int mt = 0; mt < 2; ++mt)
#pragma unroll
            for (int nt = 0; nt < 6; ++nt)
#pragma unroll
                for (int qq = 0; qq < 4; ++qq) acc[mt][nt][qq] = 0.f;
#pragma unroll
        for (int ks = 0; ks < 6; ++ks) {
            unsigned a[2][4];
#pragma unroll
            for (int mt = 0; mt < 2; ++mt)
                lda_frag(a[mt], aBase, warp_m * 32 + mt * 16, ks * 32, 208, lane);
#pragma unroll
            for (int nt = 0; nt < 6; ++nt) {
                unsigned b0, b1;
                ldb_frag(b0, b1, bBase, warp_n * 48 + nt * 8, ks * 32, 208, lane);
#pragma unroll
                for (int mt = 0; mt < 2; ++mt)
                    mma16(acc[mt][nt], a[mt], b0, b1);
            }
        }
#pragma unroll
        for (int mt = 0; mt < 2; ++mt) {
            int r0 = m0 + warp_m * 32 + mt * 16 + g;
#pragma unroll
            for (int nt = 0; nt < 6; ++nt) {
                int col = nb * 96 + warp_n * 48 + nt * 8 + 2 * tig;
                float bi0 = bias[col], bi1 = bias[col + 1];
                *reinterpret_cast<unsigned*>(&out[(size_t)r0 * 288 + col]) =
                    bf2u(acc[mt][nt][0] + bi0, acc[mt][nt][1] + bi1);
                *reinterpret_cast<unsigned*>(&out[(size_t)(r0 + 8) * 288 + col]) =
                    bf2u(acc[mt][nt][2] + bi0, acc[mt][nt][3] + bi1);
            }
        }
    }
}

// ---------------------------------------------------------------------------
// K=96 GEMM (proj) + x residual + fused LN2
// ---------------------------------------------------------------------------
__global__ __launch_bounds__(256) void k_proj(const __nv_bfloat16* __restrict__ A,
                                              const __nv_bfloat16* __restrict__ W,
                                              const float* __restrict__ bias,
                                              const float* __restrict__ res,
                                              float* __restrict__ hout,
                                              const float* __restrict__ lnw,
                                              const float* __restrict__ lnb,
                                              __nv_bfloat16* __restrict__ out2) {
    extern __shared__ unsigned smem_u[];
    int tid = threadIdx.x;
    int lane = tid & 31, warp = tid >> 5;
    int warp_m = warp & 3, warp_n = warp >> 2;
    int g = lane >> 2, tig = lane & 3;
    int m0 = blockIdx.x * 128;

    unsigned sbase = s2u(smem_u);
#pragma unroll
    for (int l = 0; l < 6; ++l) {
        int o = tid + l * 256;
        int row = o / 12, ch = o % 12;
        cp16(sbase + row * 208 + ch * 16, A + (size_t)(m0 + row) * 96 + ch * 8);
    }
#pragma unroll
    for (int l = 0; l < 5; ++l) {
        int o = tid + l * 256;
        if (o < 1152) {
            int row = o / 12, ch = o % 12;
            cp16(sbase + 26624 + row * 208 + ch * 16, W + (size_t)row * 96 + ch * 8);
        }
    }
    CP_COMMIT();

    float acc[2][6][4];
#pragma unroll
    for (int mt = 0; mt < 2; ++mt)
#pragma unroll
        for (int nt = 0; nt < 6; ++nt)
#pragma unroll
            for (int q = 0; q < 4; ++q) acc[mt][nt][q] = 0.f;

    CP_WAIT0();
    __syncthreads();

#pragma unroll
    for (int ks = 0; ks < 6; ++ks) {
        unsigned a[2][4];
#pragma unroll
        for (int mt = 0; mt < 2; ++mt)
            lda_frag(a[mt], sbase, warp_m * 32 + mt * 16, ks * 32, 208, lane);
#pragma unroll
        for (int nt = 0; nt < 6; ++nt) {
            unsigned b0, b1;
            ldb_frag(b0, b1, sbase + 26624, warp_n * 48 + nt * 8, ks * 32, 208, lane);
#pragma unroll
            for (int mt = 0; mt < 2; ++mt)
                mma16(acc[mt][nt], a[mt], b0, b1);
        }
    }

    float (*st)[100] = reinterpret_cast<float (*)[100]>(smem_u);
    __syncthreads();
#pragma unroll
    for (int mt = 0; mt < 2; ++mt) {
        int lr0 = warp_m * 32 + mt * 16 + g;
#pragma unroll
        for (int nt = 0; nt < 6; ++nt) {
            int col = warp_n * 48 + nt * 8 + 2 * tig;
            float bi0 = bias[col], bi1 = bias[col + 1];
            st[lr0][col]         = acc[mt][nt][0] + bi0;
            st[lr0][col + 1]     = acc[mt][nt][1] + bi1;
            st[lr0 + 8][col]     = acc[mt][nt][2] + bi0;
            st[lr0 + 8][col + 1] = acc[mt][nt][3] + bi1;
        }
    }
    __syncthreads();
    int r = tid >> 1, half = tid & 1;
    int bb = m0 / HW, hw0 = m0 % HW;
    const float* xb = res + (size_t)bb * 96 * HW + hw0 + r;
    float vals[48];
    float s = 0.f, q = 0.f;
#pragma unroll
    for (int i = 0; i < 12; ++i) {
        float4 v = *reinterpret_cast<const float4*>(&st[r][half * 48 + i * 4]);
        float h0 = v.x + xb[(size_t)(half * 48 + i * 4 + 0) * HW];
        float h1 = v.y + xb[(size_t)(half * 48 + i * 4 + 1) * HW];
        float h2 = v.z + xb[(size_t)(half * 48 + i * 4 + 2) * HW];
        float h3 = v.w + xb[(size_t)(half * 48 + i * 4 + 3) * HW];
        vals[i * 4 + 0] = h0; vals[i * 4 + 1] = h1;
        vals[i * 4 + 2] = h2; vals[i * 4 + 3] = h3;
        s += h0 + h1 + h2 + h3;
        q += h0 * h0 + h1 * h1 + h2 * h2 + h3 * h3;
    }
    s += __shfl_xor_sync(0xffffffffu, s, 1);
    q += __shfl_xor_sync(0xffffffffu, q, 1);
    float mean = s * (1.f / 96.f);
    float var = q * (1.f / 96.f) - mean * mean;
    float rstd = rsqrtf(var + 1e-5f);
    float* hp = hout + (size_t)(m0 + r) * 96 + half * 48;
    __nv_bfloat16* lp = out2 + (size_t)(m0 + r) * 96 + half * 48;
#pragma unroll
    for (int i = 0; i < 12; ++i) {
        int c = half * 48 + i * 4;
        *reinterpret_cast<float4*>(hp + i * 4) =
            make_float4(vals[i * 4], vals[i * 4 + 1], vals[i * 4 + 2], vals[i * 4 + 3]);
        uint2 uu;
        uu.x = bf2u((vals[i * 4 + 0] - mean) * rstd * lnw[c + 0] + lnb[c + 0],
                    (vals[i * 4 + 1] - mean) * rstd * lnw[c + 1] + lnb[c + 1]);
        uu.y = bf2u((vals[i * 4 + 2] - mean) * rstd * lnw[c + 2] + lnb[c + 2],
                    (vals[i * 4 + 3] - mean) * rstd * lnw[c + 3] + lnb[c + 3]);
        *reinterpret_cast<uint2*>(lp + i * 4) = uu;
    }
}

// ---------------------------------------------------------------------------
// Fused MLP: m1 in smem; out = m1@W2^T + b2 + h, NCHW.
// ---------------------------------------------------------------------------
#define MLP_M 3328
#define MLP_W0 15872
#define MLP_W1 20864
#define MLP_SMEM_U 25856

__global__ __launch_bounds__(256) void k_mlp(const __nv_bfloat16* __restrict__ A,
                                             const float* __restrict__ b1,
                                             const float* __restrict__ b2,
                                             const float* __restrict__ res,
                                             float* __restrict__ out) {
    extern __shared__ unsigned smem_u[];
    int tid = threadIdx.x;
    int lane = tid & 31, warp = tid >> 5;
    int warp_m = warp & 1, warp_n = warp >> 1;
    int g = lane >> 2, tig = lane & 3;
    int m0 = blockIdx.x * 64;

    unsigned sbase = s2u(smem_u);
#pragma unroll
    for (int l = 0; l < 3; ++l) {
        int o = tid + l * 256;
        int row = o / 12, ch = o % 12;
        cp16(sbase + row * 208 + ch * 16, A + (size_t)(m0 + row) * 96 + ch * 8);
    }
#pragma unroll
    for (int l = 0; l < 5; ++l) {
        int o = tid + l * 256;
        if (o < 1152) {
            int row = o / 12, ch = o % 12;
            cp16(sbase + MLP_W0 * 4 + row * 208 + ch * 16, g_bw1 + (size_t)row * 96 + ch * 8);
        }
    }
    CP_COMMIT();

    unsigned* MU = smem_u + MLP_M;
    const unsigned wslot[2] = {MLP_W0, MLP_W1};

    for (int nb = 0; nb < 4; ++nb) {
        CP_WAIT0();
        __syncthreads();
        if (nb < 3) {
#pragma unroll
            for (int l = 0; l < 5; ++l) {
                int o = tid + l * 256;
                if (o < 1152) {
                    int row = o / 12, ch = o % 12;
                    cp16(sbase + wslot[(nb + 1) & 1] * 4 + row * 208 + ch * 16,
                         g_bw1 + (size_t)((nb + 1) * 96 + row) * 96 + ch * 8);
                }
            }
            CP_COMMIT();
        } else {
#pragma unroll
            for (int l = 0; l < 5; ++l) {
                int o = tid + l * 256;
                if (o < 1152) {
                    int row = o / 12, ch = o % 12;
                    cp16(sbase + wslot[(nb + 1) & 1] * 4 + row * 208 + ch * 16,
                         g_bw2 + (size_t)row * 384 + ch * 8);
                }
            }
            CP_COMMIT();
        }
        unsigned bBase = sbase + wslot[nb & 1] * 4;
        float acc[2][3][4];
#pragma unroll
        for (int mt = 0; mt < 2; ++mt)
#pragma unroll
            for (int nt = 0; nt < 3; ++nt)
#pragma unroll
                for (int q = 0; q < 4; ++q) acc[mt][nt][q] = 0.f;
#pragma unroll
        for (int ks = 0; ks < 6; ++ks) {
            unsigned a[2][4];
#pragma unroll
            for (int mt = 0; mt < 2; ++mt)
                lda_frag(a[mt], sbase, warp_m * 32 + mt * 16, ks * 32, 208, lane);
#pragma unroll
            for (int nt = 0; nt < 3; ++nt) {
                unsigned b0, b1;
                ldb_frag(b0, b1, bBase, warp_n * 24 + nt * 8, ks * 32, 208, lane);
#pragma unroll
                for (int mt = 0; mt < 2; ++mt)
                    mma16(acc[mt][nt], a[mt], b0, b1);
            }
        }
#pragma unroll
        for (int mt = 0; mt < 2; ++mt) {
            int r0 = warp_m * 32 + mt * 16 + g;
#pragma unroll
            for (int nt = 0; nt < 3; ++nt) {
                int col = warp_n * 24 + nt * 8 + 2 * tig;
                float bi0 = b1[nb * 96 + col], bi1 = b1[nb * 96 + col + 1];
                float v0 = acc[mt][nt][0] + bi0, v1 = acc[mt][nt][1] + bi1;
                float v2 = acc[mt][nt][2] + bi0, v3 = acc[mt][nt][3] + bi1;
                v0 = 0.5f * v0 * (1.0f + erff(v0 * 0.70710678118654752f));
                v1 = 0.5f * v1 * (1.0f + erff(v1 * 0.70710678118654752f));
                v2 = 0.5f * v2 * (1.0f + erff(v2 * 0.70710678118654752f));
                v3 = 0.5f * v3 * (1.0f + erff(v3 * 0.70710678118654752f));
                MU[r0 * 196 + nb * 48 + col / 2] = bf2u(v0, v1);
                MU[(r0 + 8) * 196 + nb * 48 + col / 2] = bf2u(v2, v3);
            }
        }
    }

    float acc2[2][3][4];
#pragma unroll
    for (int mt = 0; mt < 2; ++mt)
#pragma unroll
        for (int nt = 0; nt < 3; ++nt)
#pragma unroll
            for (int q = 0; q < 4; ++q) acc2[mt][nt][q] = 0.f;

    for (int kc = 0; kc < 4; ++kc) {
        CP_WAIT0();
        __syncthreads();
        if (kc < 3) {
#pragma unroll
            for (int l = 0; l < 5; ++l) {
                int o = tid + l * 256;
                if (o < 1152) {
                    int row = o / 12, ch = o % 12;
                    cp16(sbase + wslot[(kc + 1) & 1] * 4 + row * 208 + ch * 16,
                         g_bw2 + (size_t)row * 384 + (kc + 1) * 96 + ch * 8);
                }
            }
            CP_COMMIT();
        }
        unsigned bBase = sbase + wslot[kc & 1] * 4;
        unsigned mBase = sbase + MLP_M * 4 + kc * 192;
#pragma unroll
        for (int ks = 0; ks < 6; ++ks) {
            unsigned a[2][4];
#pragma unroll
            for (int mt = 0; mt < 2; ++mt)
                lda_frag(a[mt], mBase, warp_m * 32 + mt * 16, ks * 32, 784, lane);
#pragma unroll
            for (int nt = 0; nt < 3; ++nt) {
                unsigned b0, b1;
                ldb_frag(b0, b1, bBase, warp_n * 24 + nt * 8, ks * 32, 208, lane);
#pragma unroll
                for (int mt = 0; mt < 2; ++mt)
                    mma16(acc2[mt][nt], a[mt], b0, b1);
            }
        }
    }

    __syncthreads();
    float (*st)[98] = reinterpret_cast<float (*)[98]>(smem_u + MLP_M);
#pragma unroll
    for (int mt = 0; mt < 2; ++mt) {
        int lr0 = warp_m * 32 + mt * 16 + g;
        int r0 = m0 + lr0;
#pragma unroll
        for (int nt = 0; nt < 3; ++nt) {
            int col = warp_n * 24 + nt * 8 + 2 * tig;
            float bi0 = b2[col], bi1 = b2[col + 1];
            float2 rs0 = *reinterpret_cast<const float2*>(&res[(size_t)r0 * 96 + col]);
            float2 rs1 = *reinterpret_cast<const float2*>(&res[(size_t)(r0 + 8) * 96 + col]);
            *reinterpret_cast<float2*>(&st[lr0][col]) =
                make_float2(acc2[mt][nt][0] + bi0 + rs0.x, acc2[mt][nt][1] + bi1 + rs0.y);
            *reinterpret_cast<float2*>(&st[lr0 + 8][col]) =
                make_float2(acc2[mt][nt][2] + bi0 + rs1.x, acc2[mt][nt][3] + bi1 + rs1.y);
        }
    }
    __syncthreads();
    int bb = m0 / HW, hw0 = m0 % HW;
    float* ob = out + (size_t)bb * 96 * HW + hw0;
#pragma unroll
    for (int l = 0; l < 24; ++l) {
        int e = tid + l * 256;
        int ch = e >> 6, tok = e & 63;
        ob[(size_t)ch * HW + tok] = st[tok][ch];
    }
}

// ---------------------------------------------------------------------------
// Attention. smem (u32): qs[64*52]@0, ks@3328, vs[64*52]@6656 (row-major,
// rows 49-63 zeroed), attb[64*36]@9984, tbl bf16@12288; sc fp32[64*68]
// overlays qs after score MMA.
// ---------------------------------------------------------------------------
#define QS_U 0
#define KS_U 3328
#define VS_U 6656
#define AT_U 9984
#define TB_U 12288
#define SM_ATTN_U 13660

__global__ __launch_bounds__(256) void k_attn() {
    extern __shared__ unsigned smem_u[];
    __shared__ int tok_s[49];

    int win = blockIdx.x;
    int bb = win >> 10;
    int wr = (win >> 5) & 31;
    int wc = win & 31;
    int tid = threadIdx.x;
    int lane = tid & 31, warp = tid >> 5;
    int g = lane >> 2, tig = lane & 3;
    int mt = warp & 3, nhalf = warp >> 2;
    int cls = ((wr == 31) ? 2 : 0) + ((wc == 31) ? 1 : 0);

    if (tid < 49) {
        int i = tid / 7, j = tid % 7;
        int sr = wr * 7 + i, sc = wc * 7 + j;
        int r = sr + 3; if (r >= 224) r -= 224;
        int c = sc + 3; if (c >= 224) c -= 224;
        tok_s[tid] = bb * HW + r * 224 + c;
    }
    // zero V rows 49-63 (padded P columns must hit exact zeros)
    for (int e = tid; e < 780; e += 256) smem_u[VS_U + 49 * 52 + e] = 0u;
    __syncthreads();

    unsigned sbase = s2u(smem_u);
    // gather Q, K, V rows via cp.async (row-major, stride 208B)
#pragma unroll
    for (int l = 0; l < 7; ++l) {
        int e = tid + l * 256;
        if (e < 1764) {
            int third = e / 588;
            int ee = e - third * 588;
            int row = ee / 12, ch = ee % 12;
            cp16(sbase + third * 13312 + row * 208 + ch * 16,
                 g_qkv + (size_t)tok_s[row] * 288 + third * 96 + ch * 8);
        }
    }
    // class table
    {
        const __nv_bfloat16* tsrc = g_tbl + cls * 2744;
        for (int o = tid; o < 343; o += 256)
            cp16(sbase + TB_U * 4 + o * 16, tsrc + o * 8);
    }
    CP_COMMIT();
    CP_WAIT0();
    __syncthreads();

    // ---- scores: Q[64x96] @ K^T -------------------------------------------
    float acc[4][4];
#pragma unroll
    for (int t = 0; t < 4; ++t)
#pragma unroll
        for (int q = 0; q < 4; ++q) acc[t][q] = 0.f;
#pragma unroll
    for (int ks = 0; ks < 6; ++ks) {
        unsigned a[4];
        lda_frag(a, sbase, mt * 16, ks * 32, 208, lane);
#pragma unroll
        for (int t = 0; t < 4; ++t) {
            unsigned b0, b1;
            ldb_frag(b0, b1, sbase + KS_U * 4, (nhalf * 4 + t) * 8, ks * 32, 208, lane);
            mma16(acc[t], a, b0, b1);
        }
    }
    __syncthreads();   // Q/K reads done; sc overlays qs

    // ---- epilogue: scale + table, store sc fp32 ---------------------------
    {
        float* sc = reinterpret_cast<float*>(smem_u);
        const __nv_bfloat16* tb = reinterpret_cast<const __nv_bfloat16*>(smem_u + TB_U);
        const float scale = 0.10206207261596575f;
#pragma unroll
        for (int t = 0; t < 4; ++t) {
            int j0 = (nhalf * 4 + t) * 8 + 2 * tig;
#pragma unroll
            for (int rr = 0; rr < 2; ++rr) {
                int i = mt * 16 + g + rr * 8;
                float v0 = acc[t][rr * 2 + 0] * scale;
                float v1 = acc[t][rr * 2 + 1] * scale;
                if (i < 49 && j0 < 56) {
                    __nv_bfloat162 t2 = *reinterpret_cast<const __nv_bfloat162*>(&tb[i * 56 + j0]);
                    v0 += __bfloat162float(t2.x);
                    v1 += __bfloat162float(t2.y);
                }
                *reinterpret_cast<float2*>(&sc[i * 68 + j0]) = make_float2(v0, v1);
            }
        }
    }
    __syncthreads();

    // ---- softmax rows 0..48 -> bf16 probs ---------------------------------
    {
        float* sc = reinterpret_cast<float*>(smem_u);
        __nv_bfloat16* atth = reinterpret_cast<__nv_bfloat16*>(smem_u + AT_U);
        for (int row = warp; row < 49; row += 8) {
            float x0 = sc[row * 68 + lane];
            float x1 = (lane + 32 < 49) ? sc[row * 68 + lane + 32] : -1e30f;
            float mx = fmaxf(x0, x1);
            for (int o = 16; o; o >>= 1) mx = fmaxf(mx, __shfl_xor_sync(0xffffffffu, mx, o));
            float e0 = __expf(x0 - mx);
            float e1 = (lane + 32 < 49) ? __expf(x1 - mx) : 0.f;
            float sum = e0 + e1;
            for (int o = 16; o; o >>= 1) sum += __shfl_xor_sync(0xffffffffu, sum, o);
            float inv = 1.0f / sum;
            atth[row * 72 + lane] = __float2bfloat16(e0 * inv);
            atth[row * 72 + lane + 32] = __float2bfloat16((lane + 32 < 49) ? e1 * inv : 0.f);
        }
    }
    __syncthreads();

    // ---- AV: P[64x64] @ V (B frags via ldmatrix.trans) --------------------
    {
        unsigned atBase = sbase + AT_U * 4;
        unsigned vBase = sbase + VS_U * 4;
        float av[6][4];
#pragma unroll
        for (int t = 0; t < 6; ++t)
#pragma unroll
            for (int q = 0; q < 4; ++q) av[t][q] = 0.f;
#pragma unroll
        for (int ks = 0; ks < 4; ++ks) {
            unsigned a[4];
            lda_frag(a, atBase, mt * 16, ks * 32, 144, lane);
            unsigned vrow = vBase + (ks * 16 + (lane & 15)) * 208;
#pragma unroll
            for (int t = 0; t < 6; ++t) {
                int ch0 = (nhalf * 6 + t) * 8;
                unsigned b0, b1;
                ldsm_x2t(b0, b1, vrow + ch0 * 2);
                mma16(av[t], a, b0, b1);
            }
        }
#pragma unroll
        for (int t = 0; t < 6; ++t) {
            int ch = (nhalf * 6 + t) * 8 + 2 * tig;
#pragma unroll
            for (int rr = 0; rr < 2; ++rr) {
                int r = mt * 16 + g + rr * 8;
                if (r < 49) {
                    *reinterpret_cast<unsigned*>(&g_ctx[(size_t)tok_s[r] * 96 + ch]) =
                        bf2u(av[t][rr * 2 + 0], av[t][rr * 2 + 1]);
                }
            }
        }
    }
}

// ---------------------------------------------------------------------------
extern "C" void kernel_launch(void* const* d_in, const int* in_sizes, int n_in,
                              void* d_out, int out_size) {
    const float* x    = (const float*)d_in[0];
    const float* n1w  = (const float*)d_in[1];
    const float* n1b  = (const float*)d_in[2];
    const float* qkvw = (const float*)d_in[3];
    const float* qkvb = (const float*)d_in[4];
    const float* rel  = (const float*)d_in[5];
    const float* pw   = (const float*)d_in[6];
    const float* pb   = (const float*)d_in[7];
    const float* n2w  = (const float*)d_in[8];
    const float* n2b  = (const float*)d_in[9];
    const float* w1   = (const float*)d_in[10];
    const float* b1   = (const float*)d_in[11];
    const float* w2   = (const float*)d_in[12];
    const float* b2   = (const float*)d_in[13];
    float* out = (float*)d_out;

    void *p_qkv, *p_ctx, *p_h, *p_ln2, *p_bwp;
    cudaGetSymbolAddress(&p_qkv, g_qkv);
    cudaGetSymbolAddress(&p_ctx, g_ctx);
    cudaGetSymbolAddress(&p_h,   g_h);
    cudaGetSymbolAddress(&p_ln2, g_ln2);
    cudaGetSymbolAddress(&p_bwp, g_bwp);

    const int SMQKV  = QKV_SMEM_U * 4;    // 97280
    const int SMPROJ = 128 * 100 * 4;     // 51200
    const int SMMLP  = MLP_SMEM_U * 4;    // 103424
    const int SMATTN = SM_ATTN_U * 4;     // 54640

    cudaFuncSetAttribute(k_qkv,  cudaFuncAttributeMaxDynamicSharedMemorySize, SMQKV);
    cudaFuncSetAttribute(k_proj, cudaFuncAttributeMaxDynamicSharedMemorySize, SMPROJ);
    cudaFuncSetAttribute(k_mlp,  cudaFuncAttributeMaxDynamicSharedMemorySize, SMMLP);
    cudaFuncSetAttribute(k_attn, cudaFuncAttributeMaxDynamicSharedMemorySize, SMATTN);

    k_prep<<<432, 256>>>(qkvw, pw, w1, w2);
    k_tbl<<<4, 256>>>(rel);
    k_qkv<<<3136, 256, SMQKV>>>(x, n1w, n1b, qkvb);
    k_attn<<<NWIN, 256, SMATTN>>>();
    k_proj<<<3136, 256, SMPROJ>>>(
        (const __nv_bfloat16*)p_ctx, (const __nv_bfloat16*)p_bwp, pb,
        x, (float*)p_h, n2w, n2b, (__nv_bfloat16*)p_ln2);
    k_mlp<<<6272, 256, SMMLP>>>(
        (const __nv_bfloat16*)p_ln2, b1, b2, (const float*)p_h, out);
}

// round 9
// speedup vs baseline: 5.5562x; 1.0042x over previous
#include <cuda_runtime.h>
#include <cuda_bf16.h>
#include <math.h>

#define HW 50176              // 224*224
#define L_TOK 401408          // 8*224*224
#define NWIN 8192

// Scratch
__device__ __nv_bfloat16 g_qkv[(size_t)L_TOK * 288];
__device__ __nv_bfloat16 g_ctx[(size_t)L_TOK * 96];
__device__ float         g_h[(size_t)L_TOK * 96];
__device__ __nv_bfloat16 g_ln2[(size_t)L_TOK * 96];
// bf16 weights
__device__ __nv_bfloat16 g_bwq[288 * 96];
__device__ __nv_bfloat16 g_bwp[96 * 96];
__device__ __nv_bfloat16 g_bw1[384 * 96];
__device__ __nv_bfloat16 g_bw2[96 * 384];
// combined rel-pos bias + shift-mask tables, 4 window classes, [49][56] bf16
__device__ __nv_bfloat16 g_tbl[4 * 49 * 56];

// ---- helpers --------------------------------------------------------------
__device__ __forceinline__ unsigned bf2u(float a, float b) {
    __nv_bfloat162 h = __floats2bfloat162_rn(a, b);
    return *reinterpret_cast<unsigned*>(&h);
}
__device__ __forceinline__ void mma16(float* c, const unsigned* a,
                                      unsigned b0, unsigned b1) {
    asm("mma.sync.aligned.m16n8k16.row.col.f32.bf16.bf16.f32 "
        "{%0,%1,%2,%3}, {%4,%5,%6,%7}, {%8,%9}, {%0,%1,%2,%3};"
        : "+f"(c[0]), "+f"(c[1]), "+f"(c[2]), "+f"(c[3])
        : "r"(a[0]), "r"(a[1]), "r"(a[2]), "r"(a[3]), "r"(b0), "r"(b1));
}
__device__ __forceinline__ unsigned s2u(const void* p) {
    return (unsigned)__cvta_generic_to_shared(p);
}
__device__ __forceinline__ void cp16(unsigned dst, const void* src) {
    asm volatile("cp.async.cg.shared.global [%0], [%1], 16;" :: "r"(dst), "l"(src));
}
#define CP_COMMIT() asm volatile("cp.async.commit_group;")
#define CP_WAIT0()  asm volatile("cp.async.wait_group 0;")

__device__ __forceinline__ void ldsm_x4(unsigned& r0, unsigned& r1,
                                        unsigned& r2, unsigned& r3, unsigned addr) {
    asm volatile("ldmatrix.sync.aligned.m8n8.x4.shared.b16 {%0,%1,%2,%3}, [%4];"
                 : "=r"(r0), "=r"(r1), "=r"(r2), "=r"(r3) : "r"(addr));
}
__device__ __forceinline__ void ldsm_x2(unsigned& r0, unsigned& r1, unsigned addr) {
    asm volatile("ldmatrix.sync.aligned.m8n8.x2.shared.b16 {%0,%1}, [%2];"
                 : "=r"(r0), "=r"(r1) : "r"(addr));
}
__device__ __forceinline__ void ldsm_x2t(unsigned& r0, unsigned& r1, unsigned addr) {
    asm volatile("ldmatrix.sync.aligned.m8n8.x2.trans.shared.b16 {%0,%1}, [%2];"
                 : "=r"(r0), "=r"(r1) : "r"(addr));
}
__device__ __forceinline__ void lda_frag(unsigned* a, unsigned baseB, int r0,
                                         int ksB, int strideB, int lane) {
    unsigned addr = baseB + (unsigned)((r0 + (lane & 15)) * strideB + ksB + (lane >> 4) * 16);
    ldsm_x4(a[0], a[1], a[2], a[3], addr);
}
__device__ __forceinline__ void ldb_frag(unsigned& b0, unsigned& b1, unsigned baseB,
                                         int cb, int ksB, int strideB, int lane) {
    unsigned addr = baseB + (unsigned)((cb + (lane & 7)) * strideB + ksB + ((lane >> 3) & 1) * 16);
    ldsm_x2(b0, b1, addr);
}

// ---------------------------------------------------------------------------
// Kernel 0a: weights fp32 -> bf16
// ---------------------------------------------------------------------------
__global__ __launch_bounds__(256) void k_prep(const float* __restrict__ qkvw,
                                              const float* __restrict__ pw,
                                              const float* __restrict__ w1,
                                              const float* __restrict__ w2) {
    int i = blockIdx.x * 256 + threadIdx.x;
    if (i < 27648)       g_bwq[i] = __float2bfloat16(qkvw[i]);
    else if (i < 36864)  g_bwp[i - 27648] = __float2bfloat16(pw[i - 27648]);
    else if (i < 73728)  g_bw1[i - 36864] = __float2bfloat16(w1[i - 36864]);
    else                 g_bw2[i - 73728] = __float2bfloat16(w2[i - 73728]);
}

// ---------------------------------------------------------------------------
// Kernel 0b: bias+mask class tables
// ---------------------------------------------------------------------------
__global__ __launch_bounds__(256) void k_tbl(const float* __restrict__ rel) {
    int cls = blockIdx.x;
    int re = cls >> 1, ce = cls & 1;
    for (int e = threadIdx.x; e < 49 * 56; e += 256) {
        int i = e / 56, j = e % 56;
        float v = 0.f;
        if (j < 49) {
            int idx = (i / 7 - j / 7 + 6) * 13 + (i % 7 - j % 7 + 6);
            v = rel[idx];
            int li = (re ? ((i / 7) < 4 ? 1 : 2) : 0) * 3 + (ce ? ((i % 7) < 4 ? 1 : 2) : 0);
            int lj = (re ? ((j / 7) < 4 ? 1 : 2) : 0) * 3 + (ce ? ((j % 7) < 4 ? 1 : 2) : 0);
            if (li != lj) v -= 100.f;
        }
        g_tbl[cls * 2744 + e] = __float2bfloat16(v);
    }
}

// ---------------------------------------------------------------------------
// Kernel 1: fused NCHW load + LN1 + QKV GEMM.
// ---------------------------------------------------------------------------
#define QKV_XS 0
#define QKV_AS 12672
#define QKV_BA 19328
#define QKV_SMEM_U 24320

__global__ __launch_bounds__(256) void k_qkv(const float* __restrict__ x,
                                             const float* __restrict__ lnw,
                                             const float* __restrict__ lnb,
                                             const float* __restrict__ bias) {
    extern __shared__ unsigned smem_u[];
    int tid = threadIdx.x;
    int lane = tid & 31, warp = tid >> 5;
    int warp_m = warp & 3, warp_n = warp >> 2;
    int g = lane >> 2, tig = lane & 3;
    int m0 = blockIdx.x * 128;
    int bb = m0 / HW, hw0 = m0 % HW;

    unsigned sbase = s2u(smem_u);
#pragma unroll
    for (int l = 0; l < 12; ++l) {
        int o = tid + l * 256;
        int ch = o >> 5, t4 = o & 31;
        cp16(sbase + (QKV_XS + ch * 132 + t4 * 4) * 4,
             x + ((size_t)bb * 96 + ch) * HW + hw0 + t4 * 4);
    }
#pragma unroll
    for (int l = 0; l < 5; ++l) {
        int o = tid + l * 256;
        if (o < 1152) {
            int row = o / 12, ch = o % 12;
            cp16(sbase + QKV_BA * 4 + row * 208 + ch * 16, g_bwq + (size_t)row * 96 + ch * 8);
        }
    }
    CP_COMMIT();
    CP_WAIT0();
    __syncthreads();

    {
        const float* xs = reinterpret_cast<const float*>(smem_u + QKV_XS);
        int r = tid >> 1, half = tid & 1;
        float vals[48];
        float s = 0.f, q = 0.f;
#pragma unroll
        for (int i = 0; i < 48; ++i) {
            float v = xs[(half * 48 + i) * 132 + r];
            vals[i] = v;
            s += v; q += v * v;
        }
        s += __shfl_xor_sync(0xffffffffu, s, 1);
        q += __shfl_xor_sync(0xffffffffu, q, 1);
        float mean = s * (1.f / 96.f);
        float var = q * (1.f / 96.f) - mean * mean;
        float rstd = rsqrtf(var + 1e-5f);
        __syncthreads();
        unsigned* As = smem_u + QKV_AS;
#pragma unroll
        for (int i = 0; i < 24; ++i) {
            int c = half * 48 + i * 2;
            As[r * 52 + c / 2] = bf2u((vals[i * 2] - mean) * rstd * lnw[c] + lnb[c],
                                      (vals[i * 2 + 1] - mean) * rstd * lnw[c + 1] + lnb[c + 1]);
        }
    }
    __syncthreads();

#pragma unroll
    for (int l = 0; l < 9; ++l) {
        int o = tid + l * 256;
        if (o < 2304) {
            int blk = o / 1152;
            int oo = o % 1152;
            int row = oo / 12, ch = oo % 12;
            cp16(sbase + blk * 4992 * 4 + row * 208 + ch * 16,
                 g_bwq + (size_t)((blk + 1) * 96 + row) * 96 + ch * 8);
        }
    }
    CP_COMMIT();

    unsigned aBase = sbase + QKV_AS * 4;
    __nv_bfloat16* out = g_qkv;

    for (int nb = 0; nb < 3; ++nb) {
        if (nb == 1) { CP_WAIT0(); __syncthreads(); }
        unsigned bBase = (nb == 0) ? (sbase + QKV_BA * 4) : (sbase + (nb - 1) * 4992 * 4);
        float acc[2][6][4];
#pragma unroll
        for (int mt = 0; mt < 2; ++mt)
#pragma unroll
            for (int nt = 0; nt < 6; ++nt)
#pragma unroll
                for (int qq = 0; qq < 4; ++qq) acc[mt][nt][qq] = 0.f;
#pragma unroll
        for (int ks = 0; ks < 6; ++ks) {
            unsigned a[2][4];
#pragma unroll
            for (int mt = 0; mt < 2; ++mt)
                lda_frag(a[mt], aBase, warp_m * 32 + mt * 16, ks * 32, 208, lane);
#pragma unroll
            for (int nt = 0; nt < 6; ++nt) {
                unsigned b0, b1;
                ldb_frag(b0, b1, bBase, warp_n * 48 + nt * 8, ks * 32, 208, lane);
#pragma unroll
                for (int mt = 0; mt < 2; ++mt)
                    mma16(acc[mt][nt], a[mt], b0, b1);
            }
        }
#pragma unroll
        for (int mt = 0; mt < 2; ++mt) {
            int r0 = m0 + warp_m * 32 + mt * 16 + g;
#pragma unroll
            for (int nt = 0; nt < 6; ++nt) {
                int col = nb * 96 + warp_n * 48 + nt * 8 + 2 * tig;
                float bi0 = bias[col], bi1 = bias[col + 1];
                *reinterpret_cast<unsigned*>(&out[(size_t)r0 * 288 + col]) =
                    bf2u(acc[mt][nt][0] + bi0, acc[mt][nt][1] + bi1);
                *reinterpret_cast<unsigned*>(&out[(size_t)(r0 + 8) * 288 + col]) =
                    bf2u(acc[mt][nt][2] + bi0, acc[mt][nt][3] + bi1);
            }
        }
    }
}

// ---------------------------------------------------------------------------
// K=96 GEMM (proj) + x residual + fused LN2
// ---------------------------------------------------------------------------
__global__ __launch_bounds__(256) void k_proj(const __nv_bfloat16* __restrict__ A,
                                              const __nv_bfloat16* __restrict__ W,
                                              const float* __restrict__ bias,
                                              const float* __restrict__ res,
                                              float* __restrict__ hout,
                                              const float* __restrict__ lnw,
                                              const float* __restrict__ lnb,
                                              __nv_bfloat16* __restrict__ out2) {
    extern __shared__ unsigned smem_u[];
    int tid = threadIdx.x;
    int lane = tid & 31, warp = tid >> 5;
    int warp_m = warp & 3, warp_n = warp >> 2;
    int g = lane >> 2, tig = lane & 3;
    int m0 = blockIdx.x * 128;

    unsigned sbase = s2u(smem_u);
#pragma unroll
    for (int l = 0; l < 6; ++l) {
        int o = tid + l * 256;
        int row = o / 12, ch = o % 12;
        cp16(sbase + row * 208 + ch * 16, A + (size_t)(m0 + row) * 96 + ch * 8);
    }
#pragma unroll
    for (int l = 0; l < 5; ++l) {
        int o = tid + l * 256;
        if (o < 1152) {
            int row = o / 12, ch = o % 12;
            cp16(sbase + 26624 + row * 208 + ch * 16, W + (size_t)row * 96 + ch * 8);
        }
    }
    CP_COMMIT();

    float acc[2][6][4];
#pragma unroll
    for (int mt = 0; mt < 2; ++mt)
#pragma unroll
        for (int nt = 0; nt < 6; ++nt)
#pragma unroll
            for (int q = 0; q < 4; ++q) acc[mt][nt][q] = 0.f;

    CP_WAIT0();
    __syncthreads();

#pragma unroll
    for (int ks = 0; ks < 6; ++ks) {
        unsigned a[2][4];
#pragma unroll
        for (int mt = 0; mt < 2; ++mt)
            lda_frag(a[mt], sbase, warp_m * 32 + mt * 16, ks * 32, 208, lane);
#pragma unroll
        for (int nt = 0; nt < 6; ++nt) {
            unsigned b0, b1;
            ldb_frag(b0, b1, sbase + 26624, warp_n * 48 + nt * 8, ks * 32, 208, lane);
#pragma unroll
            for (int mt = 0; mt < 2; ++mt)
                mma16(acc[mt][nt], a[mt], b0, b1);
        }
    }

    float (*st)[100] = reinterpret_cast<float (*)[100]>(smem_u);
    __syncthreads();
#pragma unroll
    for (int mt = 0; mt < 2; ++mt) {
        int lr0 = warp_m * 32 + mt * 16 + g;
#pragma unroll
        for (int nt = 0; nt < 6; ++nt) {
            int col = warp_n * 48 + nt * 8 + 2 * tig;
            float bi0 = bias[col], bi1 = bias[col + 1];
            st[lr0][col]         = acc[mt][nt][0] + bi0;
            st[lr0][col + 1]     = acc[mt][nt][1] + bi1;
            st[lr0 + 8][col]     = acc[mt][nt][2] + bi0;
            st[lr0 + 8][col + 1] = acc[mt][nt][3] + bi1;
        }
    }
    __syncthreads();
    int r = tid >> 1, half = tid & 1;
    int bb = m0 / HW, hw0 = m0 % HW;
    const float* xb = res + (size_t)bb * 96 * HW + hw0 + r;
    float vals[48];
    float s = 0.f, q = 0.f;
#pragma unroll
    for (int i = 0; i < 12; ++i) {
        float4 v = *reinterpret_cast<const float4*>(&st[r][half * 48 + i * 4]);
        float h0 = v.x + xb[(size_t)(half * 48 + i * 4 + 0) * HW];
        float h1 = v.y + xb[(size_t)(half * 48 + i * 4 + 1) * HW];
        float h2 = v.z + xb[(size_t)(half * 48 + i * 4 + 2) * HW];
        float h3 = v.w + xb[(size_t)(half * 48 + i * 4 + 3) * HW];
        vals[i * 4 + 0] = h0; vals[i * 4 + 1] = h1;
        vals[i * 4 + 2] = h2; vals[i * 4 + 3] = h3;
        s += h0 + h1 + h2 + h3;
        q += h0 * h0 + h1 * h1 + h2 * h2 + h3 * h3;
    }
    s += __shfl_xor_sync(0xffffffffu, s, 1);
    q += __shfl_xor_sync(0xffffffffu, q, 1);
    float mean = s * (1.f / 96.f);
    float var = q * (1.f / 96.f) - mean * mean;
    float rstd = rsqrtf(var + 1e-5f);
    float* hp = hout + (size_t)(m0 + r) * 96 + half * 48;
    __nv_bfloat16* lp = out2 + (size_t)(m0 + r) * 96 + half * 48;
#pragma unroll
    for (int i = 0; i < 12; ++i) {
        int c = half * 48 + i * 4;
        *reinterpret_cast<float4*>(hp + i * 4) =
            make_float4(vals[i * 4], vals[i * 4 + 1], vals[i * 4 + 2], vals[i * 4 + 3]);
        uint2 uu;
        uu.x = bf2u((vals[i * 4 + 0] - mean) * rstd * lnw[c + 0] + lnb[c + 0],
                    (vals[i * 4 + 1] - mean) * rstd * lnw[c + 1] + lnb[c + 1]);
        uu.y = bf2u((vals[i * 4 + 2] - mean) * rstd * lnw[c + 2] + lnb[c + 2],
                    (vals[i * 4 + 3] - mean) * rstd * lnw[c + 3] + lnb[c + 3]);
        *reinterpret_cast<uint2*>(lp + i * 4) = uu;
    }
}

// ---------------------------------------------------------------------------
// Fused MLP: m1 in smem; out = m1@W2^T + b2 + h, NCHW.
// ---------------------------------------------------------------------------
#define MLP_M 3328
#define MLP_W0 15872
#define MLP_W1 20864
#define MLP_SMEM_U 25856

__global__ __launch_bounds__(256) void k_mlp(const __nv_bfloat16* __restrict__ A,
                                             const float* __restrict__ b1,
                                             const float* __restrict__ b2,
                                             const float* __restrict__ res,
                                             float* __restrict__ out) {
    extern __shared__ unsigned smem_u[];
    int tid = threadIdx.x;
    int lane = tid & 31, warp = tid >> 5;
    int warp_m = warp & 1, warp_n = warp >> 1;
    int g = lane >> 2, tig = lane & 3;
    int m0 = blockIdx.x * 64;

    unsigned sbase = s2u(smem_u);
#pragma unroll
    for (int l = 0; l < 3; ++l) {
        int o = tid + l * 256;
        int row = o / 12, ch = o % 12;
        cp16(sbase + row * 208 + ch * 16, A + (size_t)(m0 + row) * 96 + ch * 8);
    }
#pragma unroll
    for (int l = 0; l < 5; ++l) {
        int o = tid + l * 256;
        if (o < 1152) {
            int row = o / 12, ch = o % 12;
            cp16(sbase + MLP_W0 * 4 + row * 208 + ch * 16, g_bw1 + (size_t)row * 96 + ch * 8);
        }
    }
    CP_COMMIT();

    unsigned* MU = smem_u + MLP_M;
    const unsigned wslot[2] = {MLP_W0, MLP_W1};

    for (int nb = 0; nb < 4; ++nb) {
        CP_WAIT0();
        __syncthreads();
        if (nb < 3) {
#pragma unroll
            for (int l = 0; l < 5; ++l) {
                int o = tid + l * 256;
                if (o < 1152) {
                    int row = o / 12, ch = o % 12;
                    cp16(sbase + wslot[(nb + 1) & 1] * 4 + row * 208 + ch * 16,
                         g_bw1 + (size_t)((nb + 1) * 96 + row) * 96 + ch * 8);
                }
            }
            CP_COMMIT();
        } else {
#pragma unroll
            for (int l = 0; l < 5; ++l) {
                int o = tid + l * 256;
                if (o < 1152) {
                    int row = o / 12, ch = o % 12;
                    cp16(sbase + wslot[(nb + 1) & 1] * 4 + row * 208 + ch * 16,
                         g_bw2 + (size_t)row * 384 + ch * 8);
                }
            }
            CP_COMMIT();
        }
        unsigned bBase = sbase + wslot[nb & 1] * 4;
        float acc[2][3][4];
#pragma unroll
        for (int mt = 0; mt < 2; ++mt)
#pragma unroll
            for (int nt = 0; nt < 3; ++nt)
#pragma unroll
                for (int q = 0; q < 4; ++q) acc[mt][nt][q] = 0.f;
#pragma unroll
        for (int ks = 0; ks < 6; ++ks) {
            unsigned a[2][4];
#pragma unroll
            for (int mt = 0; mt < 2; ++mt)
                lda_frag(a[mt], sbase, warp_m * 32 + mt * 16, ks * 32, 208, lane);
#pragma unroll
            for (int nt = 0; nt < 3; ++nt) {
                unsigned b0, b1;
                ldb_frag(b0, b1, bBase, warp_n * 24 + nt * 8, ks * 32, 208, lane);
#pragma unroll
                for (int mt = 0; mt < 2; ++mt)
                    mma16(acc[mt][nt], a[mt], b0, b1);
            }
        }
#pragma unroll
        for (int mt = 0; mt < 2; ++mt) {
            int r0 = warp_m * 32 + mt * 16 + g;
#pragma unroll
            for (int nt = 0; nt < 3; ++nt) {
                int col = warp_n * 24 + nt * 8 + 2 * tig;
                float bi0 = b1[nb * 96 + col], bi1 = b1[nb * 96 + col + 1];
                float v0 = acc[mt][nt][0] + bi0, v1 = acc[mt][nt][1] + bi1;
                float v2 = acc[mt][nt][2] + bi0, v3 = acc[mt][nt][3] + bi1;
                v0 = 0.5f * v0 * (1.0f + erff(v0 * 0.70710678118654752f));
                v1 = 0.5f * v1 * (1.0f + erff(v1 * 0.70710678118654752f));
                v2 = 0.5f * v2 * (1.0f + erff(v2 * 0.70710678118654752f));
                v3 = 0.5f * v3 * (1.0f + erff(v3 * 0.70710678118654752f));
                MU[r0 * 196 + nb * 48 + col / 2] = bf2u(v0, v1);
                MU[(r0 + 8) * 196 + nb * 48 + col / 2] = bf2u(v2, v3);
            }
        }
    }

    float acc2[2][3][4];
#pragma unroll
    for (int mt = 0; mt < 2; ++mt)
#pragma unroll
        for (int nt = 0; nt < 3; ++nt)
#pragma unroll
            for (int q = 0; q < 4; ++q) acc2[mt][nt][q] = 0.f;

    for (int kc = 0; kc < 4; ++kc) {
        CP_WAIT0();
        __syncthreads();
        if (kc < 3) {
#pragma unroll
            for (int l = 0; l < 5; ++l) {
                int o = tid + l * 256;
                if (o < 1152) {
                    int row = o / 12, ch = o % 12;
                    cp16(sbase + wslot[(kc + 1) & 1] * 4 + row * 208 + ch * 16,
                         g_bw2 + (size_t)row * 384 + (kc + 1) * 96 + ch * 8);
                }
            }
            CP_COMMIT();
        }
        unsigned bBase = sbase + wslot[kc & 1] * 4;
        unsigned mBase = sbase + MLP_M * 4 + kc * 192;
#pragma unroll
        for (int ks = 0; ks < 6; ++ks) {
            unsigned a[2][4];
#pragma unroll
            for (int mt = 0; mt < 2; ++mt)
                lda_frag(a[mt], mBase, warp_m * 32 + mt * 16, ks * 32, 784, lane);
#pragma unroll
            for (int nt = 0; nt < 3; ++nt) {
                unsigned b0, b1;
                ldb_frag(b0, b1, bBase, warp_n * 24 + nt * 8, ks * 32, 208, lane);
#pragma unroll
                for (int mt = 0; mt < 2; ++mt)
                    mma16(acc2[mt][nt], a[mt], b0, b1);
            }
        }
    }

    __syncthreads();
    float (*st)[98] = reinterpret_cast<float (*)[98]>(smem_u + MLP_M);
#pragma unroll
    for (int mt = 0; mt < 2; ++mt) {
        int lr0 = warp_m * 32 + mt * 16 + g;
        int r0 = m0 + lr0;
#pragma unroll
        for (int nt = 0; nt < 3; ++nt) {
            int col = warp_n * 24 + nt * 8 + 2 * tig;
            float bi0 = b2[col], bi1 = b2[col + 1];
            float2 rs0 = *reinterpret_cast<const float2*>(&res[(size_t)r0 * 96 + col]);
            float2 rs1 = *reinterpret_cast<const float2*>(&res[(size_t)(r0 + 8) * 96 + col]);
            *reinterpret_cast<float2*>(&st[lr0][col]) =
                make_float2(acc2[mt][nt][0] + bi0 + rs0.x, acc2[mt][nt][1] + bi1 + rs0.y);
            *reinterpret_cast<float2*>(&st[lr0 + 8][col]) =
                make_float2(acc2[mt][nt][2] + bi0 + rs1.x, acc2[mt][nt][3] + bi1 + rs1.y);
        }
    }
    __syncthreads();
    int bb = m0 / HW, hw0 = m0 % HW;
    float* ob = out + (size_t)bb * 96 * HW + hw0;
#pragma unroll
    for (int l = 0; l < 24; ++l) {
        int e = tid + l * 256;
        int ch = e >> 6, tok = e & 63;
        ob[(size_t)ch * HW + tok] = st[tok][ch];
    }
}

// ---------------------------------------------------------------------------
// Attention with register softmax.
// smem (u32): qs[64*52]@0, ks@3328, vs[64*52]@6656 (rows 49-63 zeroed),
// tbl bf16@9984 (1372u). Overlays: P bf16 [64*36] on qs; (max,sum) exchange
// float2[128] on ks. Total 11356u = 45424B.
// ---------------------------------------------------------------------------
#define QS_U 0
#define KS_U 3328
#define VS_U 6656
#define TB_U 9984
#define EX_U 3328
#define SM_ATTN_U 11356

__global__ __launch_bounds__(256) void k_attn() {
    extern __shared__ unsigned smem_u[];
    __shared__ int tok_s[49];

    int win = blockIdx.x;
    int bb = win >> 10;
    int wr = (win >> 5) & 31;
    int wc = win & 31;
    int tid = threadIdx.x;
    int lane = tid & 31, warp = tid >> 5;
    int g = lane >> 2, tig = lane & 3;
    int mt = warp & 3, nhalf = warp >> 2;
    int cls = ((wr == 31) ? 2 : 0) + ((wc == 31) ? 1 : 0);

    if (tid < 49) {
        int i = tid / 7, j = tid % 7;
        int sr = wr * 7 + i, sc = wc * 7 + j;
        int r = sr + 3; if (r >= 224) r -= 224;
        int c = sc + 3; if (c >= 224) c -= 224;
        tok_s[tid] = bb * HW + r * 224 + c;
    }
    // zero V rows 49-63 (padded P columns hit exact zeros, no NaN from junk)
    for (int e = tid; e < 780; e += 256) smem_u[VS_U + 49 * 52 + e] = 0u;
    __syncthreads();

    unsigned sbase = s2u(smem_u);
    // gather Q, K, V rows via cp.async (row-major, stride 208B)
#pragma unroll
    for (int l = 0; l < 7; ++l) {
        int e = tid + l * 256;
        if (e < 1764) {
            int third = e / 588;
            int ee = e - third * 588;
            int row = ee / 12, ch = ee % 12;
            cp16(sbase + third * 13312 + row * 208 + ch * 16,
                 g_qkv + (size_t)tok_s[row] * 288 + third * 96 + ch * 8);
        }
    }
    // class table
    {
        const __nv_bfloat16* tsrc = g_tbl + cls * 2744;
        for (int o = tid; o < 343; o += 256)
            cp16(sbase + TB_U * 4 + o * 16, tsrc + o * 8);
    }
    CP_COMMIT();
    CP_WAIT0();
    __syncthreads();

    // ---- scores: Q[64x96] @ K^T -------------------------------------------
    float acc[4][4];
#pragma unroll
    for (int t = 0; t < 4; ++t)
#pragma unroll
        for (int q = 0; q < 4; ++q) acc[t][q] = 0.f;
#pragma unroll
    for (int ks = 0; ks < 6; ++ks) {
        unsigned a[4];
        lda_frag(a, sbase, mt * 16, ks * 32, 208, lane);
#pragma unroll
        for (int t = 0; t < 4; ++t) {
            unsigned b0, b1;
            ldb_frag(b0, b1, sbase + KS_U * 4, (nhalf * 4 + t) * 8, ks * 32, 208, lane);
            mma16(acc[t], a, b0, b1);
        }
    }

    // ---- scale + table + mask in regs; half-row max -----------------------
    const __nv_bfloat16* tb = reinterpret_cast<const __nv_bfloat16*>(smem_u + TB_U);
    const float scale = 0.10206207261596575f;
    float mx[2] = {-1e30f, -1e30f};
#pragma unroll
    for (int t = 0; t < 4; ++t) {
        int j0 = (nhalf * 4 + t) * 8 + 2 * tig;
#pragma unroll
        for (int rr = 0; rr < 2; ++rr) {
            int i = mt * 16 + g + rr * 8;
            float v0 = acc[t][rr * 2 + 0] * scale;
            float v1 = acc[t][rr * 2 + 1] * scale;
            if (i < 49 && j0 < 56) {
                __nv_bfloat162 t2 = *reinterpret_cast<const __nv_bfloat162*>(&tb[i * 56 + j0]);
                v0 += __bfloat162float(t2.x);
                v1 += __bfloat162float(t2.y);
            }
            if (j0 > 48) v0 = -1e30f;
            if (j0 + 1 > 48) v1 = -1e30f;
            acc[t][rr * 2 + 0] = v0;
            acc[t][rr * 2 + 1] = v1;
            mx[rr] = fmaxf(mx[rr], fmaxf(v0, v1));
        }
    }
#pragma unroll
    for (int rr = 0; rr < 2; ++rr) {
        mx[rr] = fmaxf(mx[rr], __shfl_xor_sync(0xffffffffu, mx[rr], 1));
        mx[rr] = fmaxf(mx[rr], __shfl_xor_sync(0xffffffffu, mx[rr], 2));
    }
    // exp (store back into acc) + half-row sum
    float sm[2] = {0.f, 0.f};
#pragma unroll
    for (int t = 0; t < 4; ++t)
#pragma unroll
        for (int rr = 0; rr < 2; ++rr) {
            float p0 = __expf(acc[t][rr * 2 + 0] - mx[rr]);
            float p1 = __expf(acc[t][rr * 2 + 1] - mx[rr]);
            acc[t][rr * 2 + 0] = p0;
            acc[t][rr * 2 + 1] = p1;
            sm[rr] += p0 + p1;
        }
#pragma unroll
    for (int rr = 0; rr < 2; ++rr) {
        sm[rr] += __shfl_xor_sync(0xffffffffu, sm[rr], 1);
        sm[rr] += __shfl_xor_sync(0xffffffffu, sm[rr], 2);
    }

    __syncthreads();   // all qs/ks reads done; overlays become writable
    {
        float2* ex = reinterpret_cast<float2*>(smem_u + EX_U);
        if (tig == 0) {
#pragma unroll
            for (int rr = 0; rr < 2; ++rr) {
                int i = mt * 16 + g + rr * 8;
                ex[i * 2 + nhalf] = make_float2(mx[rr], sm[rr]);
            }
        }
    }
    __syncthreads();
    {
        const float2* ex = reinterpret_cast<const float2*>(smem_u + EX_U);
        __nv_bfloat16* atth = reinterpret_cast<__nv_bfloat16*>(smem_u + QS_U);
#pragma unroll
        for (int rr = 0; rr < 2; ++rr) {
            int i = mt * 16 + g + rr * 8;
            float2 e0 = ex[i * 2 + 0];
            float2 e1 = ex[i * 2 + 1];
            float M = fmaxf(e0.x, e1.x);
            float S = e0.y * __expf(e0.x - M) + e1.y * __expf(e1.x - M);
            float f = __expf(mx[rr] - M) / S;
#pragma unroll
            for (int t = 0; t < 4; ++t) {
                unsigned* dst = reinterpret_cast<unsigned*>(atth) +
                                i * 36 + (nhalf * 4 + t) * 4 + tig;
                *dst = bf2u(acc[t][rr * 2 + 0] * f, acc[t][rr * 2 + 1] * f);
            }
        }
    }
    __syncthreads();

    // ---- AV: P[64x64] @ V (B frags via ldmatrix.trans) --------------------
    {
        unsigned atBase = sbase;                // P overlays qs, stride 144B
        unsigned vBase = sbase + VS_U * 4;
        float av[6][4];
#pragma unroll
        for (int t = 0; t < 6; ++t)
#pragma unroll
            for (int q = 0; q < 4; ++q) av[t][q] = 0.f;
#pragma unroll
        for (int ks = 0; ks < 4; ++ks) {
            unsigned a[4];
            lda_frag(a, atBase, mt * 16, ks * 32, 144, lane);
            unsigned vrow = vBase + (ks * 16 + (lane & 15)) * 208;
#pragma unroll
            for (int t = 0; t < 6; ++t) {
                int ch0 = (nhalf * 6 + t) * 8;
                unsigned b0, b1;
                ldsm_x2t(b0, b1, vrow + ch0 * 2);
                mma16(av[t], a, b0, b1);
            }
        }
#pragma unroll
        for (int t = 0; t < 6; ++t) {
            int ch = (nhalf * 6 + t) * 8 + 2 * tig;
#pragma unroll
            for (int rr = 0; rr < 2; ++rr) {
                int r = mt * 16 + g + rr * 8;
                if (r < 49) {
                    *reinterpret_cast<unsigned*>(&g_ctx[(size_t)tok_s[r] * 96 + ch]) =
                        bf2u(av[t][rr * 2 + 0], av[t][rr * 2 + 1]);
                }
            }
        }
    }
}

// ---------------------------------------------------------------------------
extern "C" void kernel_launch(void* const* d_in, const int* in_sizes, int n_in,
                              void* d_out, int out_size) {
    const float* x    = (const float*)d_in[0];
    const float* n1w  = (const float*)d_in[1];
    const float* n1b  = (const float*)d_in[2];
    const float* qkvw = (const float*)d_in[3];
    const float* qkvb = (const float*)d_in[4];
    const float* rel  = (const float*)d_in[5];
    const float* pw   = (const float*)d_in[6];
    const float* pb   = (const float*)d_in[7];
    const float* n2w  = (const float*)d_in[8];
    const float* n2b  = (const float*)d_in[9];
    const float* w1   = (const float*)d_in[10];
    const float* b1   = (const float*)d_in[11];
    const float* w2   = (const float*)d_in[12];
    const float* b2   = (const float*)d_in[13];
    float* out = (float*)d_out;

    void *p_qkv, *p_ctx, *p_h, *p_ln2, *p_bwp;
    cudaGetSymbolAddress(&p_qkv, g_qkv);
    cudaGetSymbolAddress(&p_ctx, g_ctx);
    cudaGetSymbolAddress(&p_h,   g_h);
    cudaGetSymbolAddress(&p_ln2, g_ln2);
    cudaGetSymbolAddress(&p_bwp, g_bwp);

    const int SMQKV  = QKV_SMEM_U * 4;    // 97280
    const int SMPROJ = 128 * 100 * 4;     // 51200
    const int SMMLP  = MLP_SMEM_U * 4;    // 103424
    const int SMATTN = SM_ATTN_U * 4;     // 45424

    cudaFuncSetAttribute(k_qkv,  cudaFuncAttributeMaxDynamicSharedMemorySize, SMQKV);
    cudaFuncSetAttribute(k_proj, cudaFuncAttributeMaxDynamicSharedMemorySize, SMPROJ);
    cudaFuncSetAttribute(k_mlp,  cudaFuncAttributeMaxDynamicSharedMemorySize, SMMLP);
    cudaFuncSetAttribute(k_attn, cudaFuncAttributeMaxDynamicSharedMemorySize, SMATTN);

    k_prep<<<432, 256>>>(qkvw, pw, w1, w2);
    k_tbl<<<4, 256>>>(rel);
    k_qkv<<<3136, 256, SMQKV>>>(x, n1w, n1b, qkvb);
    k_attn<<<NWIN, 256, SMATTN>>>();
    k_proj<<<3136, 256, SMPROJ>>>(
        (const __nv_bfloat16*)p_ctx, (const __nv_bfloat16*)p_bwp, pb,
        x, (float*)p_h, n2w, n2b, (__nv_bfloat16*)p_ln2);
    k_mlp<<<6272, 256, SMMLP>>>(
        (const __nv_bfloat16*)p_ln2, b1, b2, (const float*)p_h, out);
}

// round 10
// speedup vs baseline: 6.6968x; 1.2053x over previous
#include <cuda_runtime.h>
#include <cuda_bf16.h>
#include <math.h>

#define HW 50176              // 224*224
#define L_TOK 401408          // 8*224*224
#define NWIN 8192

// Scratch
__device__ __nv_bfloat16 g_qkv[(size_t)L_TOK * 288];
__device__ __nv_bfloat16 g_ctx[(size_t)L_TOK * 96];
// bf16 weights
__device__ __nv_bfloat16 g_bwq[288 * 96];
__device__ __nv_bfloat16 g_bwp[96 * 96];
__device__ __nv_bfloat16 g_bw1[384 * 96];
__device__ __nv_bfloat16 g_bw2[96 * 384];
// combined rel-pos bias + shift-mask tables, 4 window classes, [49][56] bf16
__device__ __nv_bfloat16 g_tbl[4 * 49 * 56];

// ---- helpers --------------------------------------------------------------
__device__ __forceinline__ unsigned bf2u(float a, float b) {
    __nv_bfloat162 h = __floats2bfloat162_rn(a, b);
    return *reinterpret_cast<unsigned*>(&h);
}
__device__ __forceinline__ void mma16(float* c, const unsigned* a,
                                      unsigned b0, unsigned b1) {
    asm("mma.sync.aligned.m16n8k16.row.col.f32.bf16.bf16.f32 "
        "{%0,%1,%2,%3}, {%4,%5,%6,%7}, {%8,%9}, {%0,%1,%2,%3};"
        : "+f"(c[0]), "+f"(c[1]), "+f"(c[2]), "+f"(c[3])
        : "r"(a[0]), "r"(a[1]), "r"(a[2]), "r"(a[3]), "r"(b0), "r"(b1));
}
__device__ __forceinline__ unsigned s2u(const void* p) {
    return (unsigned)__cvta_generic_to_shared(p);
}
__device__ __forceinline__ void cp16(unsigned dst, const void* src) {
    asm volatile("cp.async.cg.shared.global [%0], [%1], 16;" :: "r"(dst), "l"(src));
}
#define CP_COMMIT() asm volatile("cp.async.commit_group;")
#define CP_WAIT0()  asm volatile("cp.async.wait_group 0;")
#define CP_WAIT1()  asm volatile("cp.async.wait_group 1;")

__device__ __forceinline__ void ldsm_x4(unsigned& r0, unsigned& r1,
                                        unsigned& r2, unsigned& r3, unsigned addr) {
    asm volatile("ldmatrix.sync.aligned.m8n8.x4.shared.b16 {%0,%1,%2,%3}, [%4];"
                 : "=r"(r0), "=r"(r1), "=r"(r2), "=r"(r3) : "r"(addr));
}
__device__ __forceinline__ void ldsm_x2(unsigned& r0, unsigned& r1, unsigned addr) {
    asm volatile("ldmatrix.sync.aligned.m8n8.x2.shared.b16 {%0,%1}, [%2];"
                 : "=r"(r0), "=r"(r1) : "r"(addr));
}
__device__ __forceinline__ void ldsm_x2t(unsigned& r0, unsigned& r1, unsigned addr) {
    asm volatile("ldmatrix.sync.aligned.m8n8.x2.trans.shared.b16 {%0,%1}, [%2];"
                 : "=r"(r0), "=r"(r1) : "r"(addr));
}
__device__ __forceinline__ void lda_frag(unsigned* a, unsigned baseB, int r0,
                                         int ksB, int strideB, int lane) {
    unsigned addr = baseB + (unsigned)((r0 + (lane & 15)) * strideB + ksB + (lane >> 4) * 16);
    ldsm_x4(a[0], a[1], a[2], a[3], addr);
}
__device__ __forceinline__ void ldb_frag(unsigned& b0, unsigned& b1, unsigned baseB,
                                         int cb, int ksB, int strideB, int lane) {
    unsigned addr = baseB + (unsigned)((cb + (lane & 7)) * strideB + ksB + ((lane >> 3) & 1) * 16);
    ldsm_x2(b0, b1, addr);
}

// ---------------------------------------------------------------------------
// Kernel 0a: weights fp32 -> bf16
// ---------------------------------------------------------------------------
__global__ __launch_bounds__(256) void k_prep(const float* __restrict__ qkvw,
                                              const float* __restrict__ pw,
                                              const float* __restrict__ w1,
                                              const float* __restrict__ w2) {
    int i = blockIdx.x * 256 + threadIdx.x;
    if (i < 27648)       g_bwq[i] = __float2bfloat16(qkvw[i]);
    else if (i < 36864)  g_bwp[i - 27648] = __float2bfloat16(pw[i - 27648]);
    else if (i < 73728)  g_bw1[i - 36864] = __float2bfloat16(w1[i - 36864]);
    else                 g_bw2[i - 73728] = __float2bfloat16(w2[i - 73728]);
}

// ---------------------------------------------------------------------------
// Kernel 0b: bias+mask class tables
// ---------------------------------------------------------------------------
__global__ __launch_bounds__(256) void k_tbl(const float* __restrict__ rel) {
    int cls = blockIdx.x;
    int re = cls >> 1, ce = cls & 1;
    for (int e = threadIdx.x; e < 49 * 56; e += 256) {
        int i = e / 56, j = e % 56;
        float v = 0.f;
        if (j < 49) {
            int idx = (i / 7 - j / 7 + 6) * 13 + (i % 7 - j % 7 + 6);
            v = rel[idx];
            int li = (re ? ((i / 7) < 4 ? 1 : 2) : 0) * 3 + (ce ? ((i % 7) < 4 ? 1 : 2) : 0);
            int lj = (re ? ((j / 7) < 4 ? 1 : 2) : 0) * 3 + (ce ? ((j % 7) < 4 ? 1 : 2) : 0);
            if (li != lj) v -= 100.f;
        }
        g_tbl[cls * 2744 + e] = __float2bfloat16(v);
    }
}

// ---------------------------------------------------------------------------
// Kernel 1: fused NCHW load + LN1 + QKV GEMM. (unchanged)
// ---------------------------------------------------------------------------
#define QKV_XS 0
#define QKV_AS 12672
#define QKV_BA 19328
#define QKV_SMEM_U 24320

__global__ __launch_bounds__(256) void k_qkv(const float* __restrict__ x,
                                             const float* __restrict__ lnw,
                                             const float* __restrict__ lnb,
                                             const float* __restrict__ bias) {
    extern __shared__ unsigned smem_u[];
    int tid = threadIdx.x;
    int lane = tid & 31, warp = tid >> 5;
    int warp_m = warp & 3, warp_n = warp >> 2;
    int g = lane >> 2, tig = lane & 3;
    int m0 = blockIdx.x * 128;
    int bb = m0 / HW, hw0 = m0 % HW;

    unsigned sbase = s2u(smem_u);
#pragma unroll
    for (int l = 0; l < 12; ++l) {
        int o = tid + l * 256;
        int ch = o >> 5, t4 = o & 31;
        cp16(sbase + (QKV_XS + ch * 132 + t4 * 4) * 4,
             x + ((size_t)bb * 96 + ch) * HW + hw0 + t4 * 4);
    }
#pragma unroll
    for (int l = 0; l < 5; ++l) {
        int o = tid + l * 256;
        if (o < 1152) {
            int row = o / 12, ch = o % 12;
            cp16(sbase + QKV_BA * 4 + row * 208 + ch * 16, g_bwq + (size_t)row * 96 + ch * 8);
        }
    }
    CP_COMMIT();
    CP_WAIT0();
    __syncthreads();

    {
        const float* xs = reinterpret_cast<const float*>(smem_u + QKV_XS);
        int r = tid >> 1, half = tid & 1;
        float vals[48];
        float s = 0.f, q = 0.f;
#pragma unroll
        for (int i = 0; i < 48; ++i) {
            float v = xs[(half * 48 + i) * 132 + r];
            vals[i] = v;
            s += v; q += v * v;
        }
        s += __shfl_xor_sync(0xffffffffu, s, 1);
        q += __shfl_xor_sync(0xffffffffu, q, 1);
        float mean = s * (1.f / 96.f);
        float var = q * (1.f / 96.f) - mean * mean;
        float rstd = rsqrtf(var + 1e-5f);
        __syncthreads();
        unsigned* As = smem_u + QKV_AS;
#pragma unroll
        for (int i = 0; i < 24; ++i) {
            int c = half * 48 + i * 2;
            As[r * 52 + c / 2] = bf2u((vals[i * 2] - mean) * rstd * lnw[c] + lnb[c],
                                      (vals[i * 2 + 1] - mean) * rstd * lnw[c + 1] + lnb[c + 1]);
        }
    }
    __syncthreads();

#pragma unroll
    for (int l = 0; l < 9; ++l) {
        int o = tid + l * 256;
        if (o < 2304) {
            int blk = o / 1152;
            int oo = o % 1152;
            int row = oo / 12, ch = oo % 12;
            cp16(sbase + blk * 4992 * 4 + row * 208 + ch * 16,
                 g_bwq + (size_t)((blk + 1) * 96 + row) * 96 + ch * 8);
        }
    }
    CP_COMMIT();

    unsigned aBase = sbase + QKV_AS * 4;
    __nv_bfloat16* out = g_qkv;

    for (int nb = 0; nb < 3; ++nb) {
        if (nb == 1) { CP_WAIT0(); __syncthreads(); }
        unsigned bBase = (nb == 0) ? (sbase + QKV_BA * 4) : (sbase + (nb - 1) * 4992 * 4);
        float acc[2][6][4];
#pragma unroll
        for (int mt = 0; mt < 2; ++mt)
#pragma unroll
            for (int nt = 0; nt < 6; ++nt)
#pragma unroll
                for (int qq = 0; qq < 4; ++qq) acc[mt][nt][qq] = 0.f;
#pragma unroll
        for (int ks = 0; ks < 6; ++ks) {
            unsigned a[2][4];
#pragma unroll
            for (int mt = 0; mt < 2; ++mt)
                lda_frag(a[mt], aBase, warp_m * 32 + mt * 16, ks * 32, 208, lane);
#pragma unroll
            for (int nt = 0; nt < 6; ++nt) {
                unsigned b0, b1;
                ldb_frag(b0, b1, bBase, warp_n * 48 + nt * 8, ks * 32, 208, lane);
#pragma unroll
                for (int mt = 0; mt < 2; ++mt)
                    mma16(acc[mt][nt], a[mt], b0, b1);
            }
        }
#pragma unroll
        for (int mt = 0; mt < 2; ++mt) {
            int r0 = m0 + warp_m * 32 + mt * 16 + g;
#pragma unroll
            for (int nt = 0; nt < 6; ++nt) {
                int col = nb * 96 + warp_n * 48 + nt * 8 + 2 * tig;
                float bi0 = bias[col], bi1 = bias[col + 1];
                *reinterpret_cast<unsigned*>(&out[(size_t)r0 * 288 + col]) =
                    bf2u(acc[mt][nt][0] + bi0, acc[mt][nt][1] + bi1);
                *reinterpret_cast<unsigned*>(&out[(size_t)(r0 + 8) * 288 + col]) =
                    bf2u(acc[mt][nt][2] + bi0, acc[mt][nt][3] + bi1);
            }
        }
    }
}

// ---------------------------------------------------------------------------
// Fused proj + x-residual + LN2 + MLP1 + GELU + MLP2 + residual + NCHW out.
// BM=64, 256 threads: warp_m = warp&1 (2), warp_n = warp>>1 (4).
// h residual lives in registers from proj epilogue to MLP2 epilogue.
// smem (u32): A@0 (3328: ctx, then ln2 bf16 tile), S0@3328, S1@8320 (4992 ea),
//             M@13312 (12544), EX@25856 (1024). Total 26880u = 107520B.
// ---------------------------------------------------------------------------
#define PML_S0 3328
#define PML_S1 8320
#define PML_M  13312
#define PML_EX 25856
#define PML_SMEM_U 26880

__global__ __launch_bounds__(256) void k_pml(const __nv_bfloat16* __restrict__ A,
                                             const float* __restrict__ pbias,
                                             const float* __restrict__ x,
                                             const float* __restrict__ lnw,
                                             const float* __restrict__ lnb,
                                             const float* __restrict__ b1,
                                             const float* __restrict__ b2,
                                             float* __restrict__ out) {
    extern __shared__ unsigned smem_u[];
    int tid = threadIdx.x;
    int lane = tid & 31, warp = tid >> 5;
    int warp_m = warp & 1, warp_n = warp >> 1;
    int g = lane >> 2, tig = lane & 3;
    int m0 = blockIdx.x * 64;
    int bb = m0 / HW, hw0 = m0 % HW;

    unsigned sbase = s2u(smem_u);
    // group1: ctx A-tile + proj W -> S0
#pragma unroll
    for (int l = 0; l < 3; ++l) {
        int o = tid + l * 256;
        int row = o / 12, ch = o % 12;
        cp16(sbase + row * 208 + ch * 16, A + (size_t)(m0 + row) * 96 + ch * 8);
    }
#pragma unroll
    for (int l = 0; l < 5; ++l) {
        int o = tid + l * 256;
        if (o < 1152) {
            int row = o / 12, ch = o % 12;
            cp16(sbase + PML_S0 * 4 + row * 208 + ch * 16, g_bwp + (size_t)row * 96 + ch * 8);
        }
    }
    CP_COMMIT();
    // group2: W1 block 0 -> S1
#pragma unroll
    for (int l = 0; l < 5; ++l) {
        int o = tid + l * 256;
        if (o < 1152) {
            int row = o / 12, ch = o % 12;
            cp16(sbase + PML_S1 * 4 + row * 208 + ch * 16, g_bw1 + (size_t)row * 96 + ch * 8);
        }
    }
    CP_COMMIT();
    CP_WAIT1();
    __syncthreads();

    // ---- proj GEMM -> h regs ---------------------------------------------
    float h[2][3][4];
#pragma unroll
    for (int mt = 0; mt < 2; ++mt)
#pragma unroll
        for (int nt = 0; nt < 3; ++nt)
#pragma unroll
            for (int q = 0; q < 4; ++q) h[mt][nt][q] = 0.f;
#pragma unroll
    for (int ks = 0; ks < 6; ++ks) {
        unsigned a[2][4];
#pragma unroll
        for (int mt = 0; mt < 2; ++mt)
            lda_frag(a[mt], sbase, warp_m * 32 + mt * 16, ks * 32, 208, lane);
#pragma unroll
        for (int nt = 0; nt < 3; ++nt) {
            unsigned b0, b1;
            ldb_frag(b0, b1, sbase + PML_S0 * 4, warp_n * 24 + nt * 8, ks * 32, 208, lane);
#pragma unroll
            for (int mt = 0; mt < 2; ++mt)
                mma16(h[mt][nt], a[mt], b0, b1);
        }
    }
    // epilogue: + proj bias + x residual (NCHW direct)
#pragma unroll
    for (int mt = 0; mt < 2; ++mt) {
        int r0 = warp_m * 32 + mt * 16 + g;
#pragma unroll
        for (int nt = 0; nt < 3; ++nt) {
            int col = warp_n * 24 + nt * 8 + 2 * tig;
            const float* x0 = x + ((size_t)bb * 96 + col) * HW + hw0;
            const float* x1 = x + ((size_t)bb * 96 + col + 1) * HW + hw0;
            h[mt][nt][0] += pbias[col]     + x0[r0];
            h[mt][nt][1] += pbias[col + 1] + x1[r0];
            h[mt][nt][2] += pbias[col]     + x0[r0 + 8];
            h[mt][nt][3] += pbias[col + 1] + x1[r0 + 8];
        }
    }
    // ---- LN2: register partials + smem exchange ---------------------------
    float ps[2][2], pq[2][2];
#pragma unroll
    for (int mt = 0; mt < 2; ++mt)
#pragma unroll
        for (int rr = 0; rr < 2; ++rr) {
            float s = 0.f, q = 0.f;
#pragma unroll
            for (int nt = 0; nt < 3; ++nt) {
                s += h[mt][nt][rr * 2 + 0] + h[mt][nt][rr * 2 + 1];
                q += h[mt][nt][rr * 2 + 0] * h[mt][nt][rr * 2 + 0] +
                     h[mt][nt][rr * 2 + 1] * h[mt][nt][rr * 2 + 1];
            }
            s += __shfl_xor_sync(0xffffffffu, s, 1);
            q += __shfl_xor_sync(0xffffffffu, q, 1);
            s += __shfl_xor_sync(0xffffffffu, s, 2);
            q += __shfl_xor_sync(0xffffffffu, q, 2);
            ps[mt][rr] = s; pq[mt][rr] = q;
        }
    __syncthreads();   // all warps past proj GEMM; EX/A overlays writable
    {
        float2* ex = reinterpret_cast<float2*>(smem_u + PML_EX);
        if (tig == 0) {
#pragma unroll
            for (int mt = 0; mt < 2; ++mt)
#pragma unroll
                for (int rr = 0; rr < 2; ++rr) {
                    int row = warp_m * 32 + mt * 16 + g + rr * 8;
                    ex[row * 4 + warp_n] = make_float2(ps[mt][rr], pq[mt][rr]);
                }
        }
    }
    __syncthreads();
    {
        const float2* ex = reinterpret_cast<const float2*>(smem_u + PML_EX);
        unsigned* As = smem_u;   // ln2 bf16 tile overlays ctx
#pragma unroll
        for (int mt = 0; mt < 2; ++mt)
#pragma unroll
            for (int rr = 0; rr < 2; ++rr) {
                int row = warp_m * 32 + mt * 16 + g + rr * 8;
                float2 e0 = ex[row * 4 + 0], e1 = ex[row * 4 + 1];
                float2 e2 = ex[row * 4 + 2], e3 = ex[row * 4 + 3];
                float s = e0.x + e1.x + e2.x + e3.x;
                float q = e0.y + e1.y + e2.y + e3.y;
                float mean = s * (1.f / 96.f);
                float var = q * (1.f / 96.f) - mean * mean;
                float rstd = rsqrtf(var + 1e-5f);
#pragma unroll
                for (int nt = 0; nt < 3; ++nt) {
                    int col = warp_n * 24 + nt * 8 + 2 * tig;
                    float v0 = (h[mt][nt][rr * 2 + 0] - mean) * rstd * lnw[col] + lnb[col];
                    float v1 = (h[mt][nt][rr * 2 + 1] - mean) * rstd * lnw[col + 1] + lnb[col + 1];
                    As[row * 52 + col / 2] = bf2u(v0, v1);
                }
            }
    }
    __syncthreads();

    unsigned* MU = smem_u + PML_M;
    const unsigned wslot[2] = {PML_S1, PML_S0};   // idx&1==0 -> S1

    // ---- MLP1: 4 N-blocks + GELU -> M smem --------------------------------
    for (int nb = 0; nb < 4; ++nb) {
        CP_WAIT0();
        __syncthreads();
        // prefetch next weight into the other slot
        {
            const __nv_bfloat16* nsrc = (nb < 3)
                ? g_bw1 + (size_t)(nb + 1) * 96 * 96
                : g_bw2;
            unsigned dslot = wslot[(nb + 1) & 1];
#pragma unroll
            for (int l = 0; l < 5; ++l) {
                int o = tid + l * 256;
                if (o < 1152) {
                    int row = o / 12, ch = o % 12;
                    if (nb < 3)
                        cp16(sbase + dslot * 4 + row * 208 + ch * 16, nsrc + (size_t)row * 96 + ch * 8);
                    else
                        cp16(sbase + dslot * 4 + row * 208 + ch * 16, nsrc + (size_t)row * 384 + ch * 8);
                }
            }
            CP_COMMIT();
        }
        unsigned bBase = sbase + wslot[nb & 1] * 4;
        float acc[2][3][4];
#pragma unroll
        for (int mt = 0; mt < 2; ++mt)
#pragma unroll
            for (int nt = 0; nt < 3; ++nt)
#pragma unroll
                for (int q = 0; q < 4; ++q) acc[mt][nt][q] = 0.f;
#pragma unroll
        for (int ks = 0; ks < 6; ++ks) {
            unsigned a[2][4];
#pragma unroll
            for (int mt = 0; mt < 2; ++mt)
                lda_frag(a[mt], sbase, warp_m * 32 + mt * 16, ks * 32, 208, lane);
#pragma unroll
            for (int nt = 0; nt < 3; ++nt) {
                unsigned b0, b1;
                ldb_frag(b0, b1, bBase, warp_n * 24 + nt * 8, ks * 32, 208, lane);
#pragma unroll
                for (int mt = 0; mt < 2; ++mt)
                    mma16(acc[mt][nt], a[mt], b0, b1);
            }
        }
#pragma unroll
        for (int mt = 0; mt < 2; ++mt) {
            int r0 = warp_m * 32 + mt * 16 + g;
#pragma unroll
            for (int nt = 0; nt < 3; ++nt) {
                int col = warp_n * 24 + nt * 8 + 2 * tig;
                float bi0 = b1[nb * 96 + col], bi1 = b1[nb * 96 + col + 1];
                float v0 = acc[mt][nt][0] + bi0, v1 = acc[mt][nt][1] + bi1;
                float v2 = acc[mt][nt][2] + bi0, v3 = acc[mt][nt][3] + bi1;
                v0 = 0.5f * v0 * (1.0f + erff(v0 * 0.70710678118654752f));
                v1 = 0.5f * v1 * (1.0f + erff(v1 * 0.70710678118654752f));
                v2 = 0.5f * v2 * (1.0f + erff(v2 * 0.70710678118654752f));
                v3 = 0.5f * v3 * (1.0f + erff(v3 * 0.70710678118654752f));
                MU[r0 * 196 + nb * 48 + col / 2] = bf2u(v0, v1);
                MU[(r0 + 8) * 196 + nb * 48 + col / 2] = bf2u(v2, v3);
            }
        }
    }

    // ---- MLP2: 4 K-chunks, accumulate acc2 --------------------------------
    float acc2[2][3][4];
#pragma unroll
    for (int mt = 0; mt < 2; ++mt)
#pragma unroll
        for (int nt = 0; nt < 3; ++nt)
#pragma unroll
            for (int q = 0; q < 4; ++q) acc2[mt][nt][q] = 0.f;

    for (int kc = 0; kc < 4; ++kc) {
        CP_WAIT0();
        __syncthreads();   // slot ready; M writes visible (kc==0)
        if (kc < 3) {
            unsigned dslot = wslot[(kc + 1) & 1];
#pragma unroll
            for (int l = 0; l < 5; ++l) {
                int o = tid + l * 256;
                if (o < 1152) {
                    int row = o / 12, ch = o % 12;
                    cp16(sbase + dslot * 4 + row * 208 + ch * 16,
                         g_bw2 + (size_t)row * 384 + (kc + 1) * 96 + ch * 8);
                }
            }
            CP_COMMIT();
        }
        unsigned bBase = sbase + wslot[kc & 1] * 4;
        unsigned mBase = sbase + PML_M * 4 + kc * 192;
#pragma unroll
        for (int ks = 0; ks < 6; ++ks) {
            unsigned a[2][4];
#pragma unroll
            for (int mt = 0; mt < 2; ++mt)
                lda_frag(a[mt], mBase, warp_m * 32 + mt * 16, ks * 32, 784, lane);
#pragma unroll
            for (int nt = 0; nt < 3; ++nt) {
                unsigned b0, b1;
                ldb_frag(b0, b1, bBase, warp_n * 24 + nt * 8, ks * 32, 208, lane);
#pragma unroll
                for (int mt = 0; mt < 2; ++mt)
                    mma16(acc2[mt][nt], a[mt], b0, b1);
            }
        }
    }

    // ---- epilogue: +b2 +h(regs), NCHW store -------------------------------
    __syncthreads();
    float (*st)[98] = reinterpret_cast<float (*)[98]>(smem_u + PML_M);
#pragma unroll
    for (int mt = 0; mt < 2; ++mt) {
        int lr0 = warp_m * 32 + mt * 16 + g;
#pragma unroll
        for (int nt = 0; nt < 3; ++nt) {
            int col = warp_n * 24 + nt * 8 + 2 * tig;
            float bi0 = b2[col], bi1 = b2[col + 1];
            *reinterpret_cast<float2*>(&st[lr0][col]) =
                make_float2(acc2[mt][nt][0] + bi0 + h[mt][nt][0],
                            acc2[mt][nt][1] + bi1 + h[mt][nt][1]);
            *reinterpret_cast<float2*>(&st[lr0 + 8][col]) =
                make_float2(acc2[mt][nt][2] + bi0 + h[mt][nt][2],
                            acc2[mt][nt][3] + bi1 + h[mt][nt][3]);
        }
    }
    __syncthreads();
    float* ob = out + (size_t)bb * 96 * HW + hw0;
#pragma unroll
    for (int l = 0; l < 24; ++l) {
        int e = tid + l * 256;
        int ch = e >> 6, tok = e & 63;
        ob[(size_t)ch * HW + tok] = st[tok][ch];
    }
}

// ---------------------------------------------------------------------------
// Attention with register softmax. (unchanged from round 9)
// ---------------------------------------------------------------------------
#define QS_U 0
#define KS_U 3328
#define VS_U 6656
#define TB_U 9984
#define EX_U 3328
#define SM_ATTN_U 11356

__global__ __launch_bounds__(256) void k_attn() {
    extern __shared__ unsigned smem_u[];
    __shared__ int tok_s[49];

    int win = blockIdx.x;
    int bb = win >> 10;
    int wr = (win >> 5) & 31;
    int wc = win & 31;
    int tid = threadIdx.x;
    int lane = tid & 31, warp = tid >> 5;
    int g = lane >> 2, tig = lane & 3;
    int mt = warp & 3, nhalf = warp >> 2;
    int cls = ((wr == 31) ? 2 : 0) + ((wc == 31) ? 1 : 0);

    if (tid < 49) {
        int i = tid / 7, j = tid % 7;
        int sr = wr * 7 + i, sc = wc * 7 + j;
        int r = sr + 3; if (r >= 224) r -= 224;
        int c = sc + 3; if (c >= 224) c -= 224;
        tok_s[tid] = bb * HW + r * 224 + c;
    }
    for (int e = tid; e < 780; e += 256) smem_u[VS_U + 49 * 52 + e] = 0u;
    __syncthreads();

    unsigned sbase = s2u(smem_u);
#pragma unroll
    for (int l = 0; l < 7; ++l) {
        int e = tid + l * 256;
        if (e < 1764) {
            int third = e / 588;
            int ee = e - third * 588;
            int row = ee / 12, ch = ee % 12;
            cp16(sbase + third * 13312 + row * 208 + ch * 16,
                 g_qkv + (size_t)tok_s[row] * 288 + third * 96 + ch * 8);
        }
    }
    {
        const __nv_bfloat16* tsrc = g_tbl + cls * 2744;
        for (int o = tid; o < 343; o += 256)
            cp16(sbase + TB_U * 4 + o * 16, tsrc + o * 8);
    }
    CP_COMMIT();
    CP_WAIT0();
    __syncthreads();

    float acc[4][4];
#pragma unroll
    for (int t = 0; t < 4; ++t)
#pragma unroll
        for (int q = 0; q < 4; ++q) acc[t][q] = 0.f;
#pragma unroll
    for (int ks = 0; ks < 6; ++ks) {
        unsigned a[4];
        lda_frag(a, sbase, mt * 16, ks * 32, 208, lane);
#pragma unroll
        for (int t = 0; t < 4; ++t) {
            unsigned b0, b1;
            ldb_frag(b0, b1, sbase + KS_U * 4, (nhalf * 4 + t) * 8, ks * 32, 208, lane);
            mma16(acc[t], a, b0, b1);
        }
    }

    const __nv_bfloat16* tb = reinterpret_cast<const __nv_bfloat16*>(smem_u + TB_U);
    const float scale = 0.10206207261596575f;
    float mx[2] = {-1e30f, -1e30f};
#pragma unroll
    for (int t = 0; t < 4; ++t) {
        int j0 = (nhalf * 4 + t) * 8 + 2 * tig;
#pragma unroll
        for (int rr = 0; rr < 2; ++rr) {
            int i = mt * 16 + g + rr * 8;
            float v0 = acc[t][rr * 2 + 0] * scale;
            float v1 = acc[t][rr * 2 + 1] * scale;
            if (i < 49 && j0 < 56) {
                __nv_bfloat162 t2 = *reinterpret_cast<const __nv_bfloat162*>(&tb[i * 56 + j0]);
                v0 += __bfloat162float(t2.x);
                v1 += __bfloat162float(t2.y);
            }
            if (j0 > 48) v0 = -1e30f;
            if (j0 + 1 > 48) v1 = -1e30f;
            acc[t][rr * 2 + 0] = v0;
            acc[t][rr * 2 + 1] = v1;
            mx[rr] = fmaxf(mx[rr], fmaxf(v0, v1));
        }
    }
#pragma unroll
    for (int rr = 0; rr < 2; ++rr) {
        mx[rr] = fmaxf(mx[rr], __shfl_xor_sync(0xffffffffu, mx[rr], 1));
        mx[rr] = fmaxf(mx[rr], __shfl_xor_sync(0xffffffffu, mx[rr], 2));
    }
    float sm[2] = {0.f, 0.f};
#pragma unroll
    for (int t = 0; t < 4; ++t)
#pragma unroll
        for (int rr = 0; rr < 2; ++rr) {
            float p0 = __expf(acc[t][rr * 2 + 0] - mx[rr]);
            float p1 = __expf(acc[t][rr * 2 + 1] - mx[rr]);
            acc[t][rr * 2 + 0] = p0;
            acc[t][rr * 2 + 1] = p1;
            sm[rr] += p0 + p1;
        }
#pragma unroll
    for (int rr = 0; rr < 2; ++rr) {
        sm[rr] += __shfl_xor_sync(0xffffffffu, sm[rr], 1);
        sm[rr] += __shfl_xor_sync(0xffffffffu, sm[rr], 2);
    }

    __syncthreads();
    {
        float2* ex = reinterpret_cast<float2*>(smem_u + EX_U);
        if (tig == 0) {
#pragma unroll
            for (int rr = 0; rr < 2; ++rr) {
                int i = mt * 16 + g + rr * 8;
                ex[i * 2 + nhalf] = make_float2(mx[rr], sm[rr]);
            }
        }
    }
    __syncthreads();
    {
        const float2* ex = reinterpret_cast<const float2*>(smem_u + EX_U);
        __nv_bfloat16* atth = reinterpret_cast<__nv_bfloat16*>(smem_u + QS_U);
#pragma unroll
        for (int rr = 0; rr < 2; ++rr) {
            int i = mt * 16 + g + rr * 8;
            float2 e0 = ex[i * 2 + 0];
            float2 e1 = ex[i * 2 + 1];
            float M = fmaxf(e0.x, e1.x);
            float S = e0.y * __expf(e0.x - M) + e1.y * __expf(e1.x - M);
            float f = __expf(mx[rr] - M) / S;
#pragma unroll
            for (int t = 0; t < 4; ++t) {
                unsigned* dst = reinterpret_cast<unsigned*>(atth) +
                                i * 36 + (nhalf * 4 + t) * 4 + tig;
                *dst = bf2u(acc[t][rr * 2 + 0] * f, acc[t][rr * 2 + 1] * f);
            }
        }
    }
    __syncthreads();

    {
        unsigned atBase = sbase;
        unsigned vBase = sbase + VS_U * 4;
        float av[6][4];
#pragma unroll
        for (int t = 0; t < 6; ++t)
#pragma unroll
            for (int q = 0; q < 4; ++q) av[t][q] = 0.f;
#pragma unroll
        for (int ks = 0; ks < 4; ++ks) {
            unsigned a[4];
            lda_frag(a, atBase, mt * 16, ks * 32, 144, lane);
            unsigned vrow = vBase + (ks * 16 + (lane & 15)) * 208;
#pragma unroll
            for (int t = 0; t < 6; ++t) {
                int ch0 = (nhalf * 6 + t) * 8;
                unsigned b0, b1;
                ldsm_x2t(b0, b1, vrow + ch0 * 2);
                mma16(av[t], a, b0, b1);
            }
        }
#pragma unroll
        for (int t = 0; t < 6; ++t) {
            int ch = (nhalf * 6 + t) * 8 + 2 * tig;
#pragma unroll
            for (int rr = 0; rr < 2; ++rr) {
                int r = mt * 16 + g + rr * 8;
                if (r < 49) {
                    *reinterpret_cast<unsigned*>(&g_ctx[(size_t)tok_s[r] * 96 + ch]) =
                        bf2u(av[t][rr * 2 + 0], av[t][rr * 2 + 1]);
                }
            }
        }
    }
}

// ---------------------------------------------------------------------------
extern "C" void kernel_launch(void* const* d_in, const int* in_sizes, int n_in,
                              void* d_out, int out_size) {
    const float* x    = (const float*)d_in[0];
    const float* n1w  = (const float*)d_in[1];
    const float* n1b  = (const float*)d_in[2];
    const float* qkvw = (const float*)d_in[3];
    const float* qkvb = (const float*)d_in[4];
    const float* rel  = (const float*)d_in[5];
    const float* pw   = (const float*)d_in[6];
    const float* pb   = (const float*)d_in[7];
    const float* n2w  = (const float*)d_in[8];
    const float* n2b  = (const float*)d_in[9];
    const float* w1   = (const float*)d_in[10];
    const float* b1   = (const float*)d_in[11];
    const float* w2   = (const float*)d_in[12];
    const float* b2   = (const float*)d_in[13];
    float* out = (float*)d_out;

    void *p_ctx;
    cudaGetSymbolAddress(&p_ctx, g_ctx);

    const int SMQKV  = QKV_SMEM_U * 4;    // 97280
    const int SMPML  = PML_SMEM_U * 4;    // 107520
    const int SMATTN = SM_ATTN_U * 4;     // 45424

    cudaFuncSetAttribute(k_qkv,  cudaFuncAttributeMaxDynamicSharedMemorySize, SMQKV);
    cudaFuncSetAttribute(k_pml,  cudaFuncAttributeMaxDynamicSharedMemorySize, SMPML);
    cudaFuncSetAttribute(k_attn, cudaFuncAttributeMaxDynamicSharedMemorySize, SMATTN);

    k_prep<<<432, 256>>>(qkvw, pw, w1, w2);
    k_tbl<<<4, 256>>>(rel);
    k_qkv<<<3136, 256, SMQKV>>>(x, n1w, n1b, qkvb);
    k_attn<<<NWIN, 256, SMATTN>>>();
    k_pml<<<6272, 256, SMPML>>>(
        (const __nv_bfloat16*)p_ctx, pb, x, n2w, n2b, b1, b2, out);
}

// round 11
// speedup vs baseline: 6.9537x; 1.0384x over previous
#include <cuda_runtime.h>
#include <cuda_bf16.h>
#include <math.h>

#define HW 50176              // 224*224
#define L_TOK 401408          // 8*224*224
#define NWIN 8192

// Scratch
__device__ __nv_bfloat16 g_qkv[(size_t)L_TOK * 288];
__device__ __nv_bfloat16 g_ctx[(size_t)L_TOK * 96];
// bf16 weights
__device__ __nv_bfloat16 g_bwq[288 * 96];
__device__ __nv_bfloat16 g_bwp[96 * 96];
__device__ __nv_bfloat16 g_bw1[384 * 96];
__device__ __nv_bfloat16 g_bw2[96 * 384];
// combined rel-pos bias + shift-mask tables, 4 classes, [49][50] bf16 (padded to 2456)
__device__ __nv_bfloat16 g_tbl[4 * 2456];

// ---- helpers --------------------------------------------------------------
__device__ __forceinline__ unsigned bf2u(float a, float b) {
    __nv_bfloat162 h = __floats2bfloat162_rn(a, b);
    return *reinterpret_cast<unsigned*>(&h);
}
__device__ __forceinline__ void mma16(float* c, const unsigned* a,
                                      unsigned b0, unsigned b1) {
    asm("mma.sync.aligned.m16n8k16.row.col.f32.bf16.bf16.f32 "
        "{%0,%1,%2,%3}, {%4,%5,%6,%7}, {%8,%9}, {%0,%1,%2,%3};"
        : "+f"(c[0]), "+f"(c[1]), "+f"(c[2]), "+f"(c[3])
        : "r"(a[0]), "r"(a[1]), "r"(a[2]), "r"(a[3]), "r"(b0), "r"(b1));
}
__device__ __forceinline__ unsigned s2u(const void* p) {
    return (unsigned)__cvta_generic_to_shared(p);
}
__device__ __forceinline__ void cp16(unsigned dst, const void* src) {
    asm volatile("cp.async.cg.shared.global [%0], [%1], 16;" :: "r"(dst), "l"(src));
}
#define CP_COMMIT() asm volatile("cp.async.commit_group;")
#define CP_WAIT0()  asm volatile("cp.async.wait_group 0;")
#define CP_WAIT1()  asm volatile("cp.async.wait_group 1;")

__device__ __forceinline__ void ldsm_x4(unsigned& r0, unsigned& r1,
                                        unsigned& r2, unsigned& r3, unsigned addr) {
    asm volatile("ldmatrix.sync.aligned.m8n8.x4.shared.b16 {%0,%1,%2,%3}, [%4];"
                 : "=r"(r0), "=r"(r1), "=r"(r2), "=r"(r3) : "r"(addr));
}
__device__ __forceinline__ void ldsm_x2(unsigned& r0, unsigned& r1, unsigned addr) {
    asm volatile("ldmatrix.sync.aligned.m8n8.x2.shared.b16 {%0,%1}, [%2];"
                 : "=r"(r0), "=r"(r1) : "r"(addr));
}
__device__ __forceinline__ void ldsm_x2t(unsigned& r0, unsigned& r1, unsigned addr) {
    asm volatile("ldmatrix.sync.aligned.m8n8.x2.trans.shared.b16 {%0,%1}, [%2];"
                 : "=r"(r0), "=r"(r1) : "r"(addr));
}
__device__ __forceinline__ void lda_frag(unsigned* a, unsigned baseB, int r0,
                                         int ksB, int strideB, int lane) {
    unsigned addr = baseB + (unsigned)((r0 + (lane & 15)) * strideB + ksB + (lane >> 4) * 16);
    ldsm_x4(a[0], a[1], a[2], a[3], addr);
}
__device__ __forceinline__ void ldb_frag(unsigned& b0, unsigned& b1, unsigned baseB,
                                         int cb, int ksB, int strideB, int lane) {
    unsigned addr = baseB + (unsigned)((cb + (lane & 7)) * strideB + ksB + ((lane >> 3) & 1) * 16);
    ldsm_x2(b0, b1, addr);
}

// ---------------------------------------------------------------------------
// Kernel 0a: weights fp32 -> bf16
// ---------------------------------------------------------------------------
__global__ __launch_bounds__(256) void k_prep(const float* __restrict__ qkvw,
                                              const float* __restrict__ pw,
                                              const float* __restrict__ w1,
                                              const float* __restrict__ w2) {
    int i = blockIdx.x * 256 + threadIdx.x;
    if (i < 27648)       g_bwq[i] = __float2bfloat16(qkvw[i]);
    else if (i < 36864)  g_bwp[i - 27648] = __float2bfloat16(pw[i - 27648]);
    else if (i < 73728)  g_bw1[i - 36864] = __float2bfloat16(w1[i - 36864]);
    else                 g_bw2[i - 73728] = __float2bfloat16(w2[i - 73728]);
}

// ---------------------------------------------------------------------------
// Kernel 0b: bias+mask class tables, stride 50
// ---------------------------------------------------------------------------
__global__ __launch_bounds__(256) void k_tbl(const float* __restrict__ rel) {
    int cls = blockIdx.x;
    int re = cls >> 1, ce = cls & 1;
    for (int e = threadIdx.x; e < 2456; e += 256) {
        int i = e / 50, j = e % 50;
        float v = 0.f;
        if (i < 49 && j < 49) {
            int idx = (i / 7 - j / 7 + 6) * 13 + (i % 7 - j % 7 + 6);
            v = rel[idx];
            int li = (re ? ((i / 7) < 4 ? 1 : 2) : 0) * 3 + (ce ? ((i % 7) < 4 ? 1 : 2) : 0);
            int lj = (re ? ((j / 7) < 4 ? 1 : 2) : 0) * 3 + (ce ? ((j % 7) < 4 ? 1 : 2) : 0);
            if (li != lj) v -= 100.f;
        }
        g_tbl[cls * 2456 + e] = __float2bfloat16(v);
    }
}

// ---------------------------------------------------------------------------
// Kernel 1: fused NCHW load + LN1 + QKV GEMM.  BM=64, smem 58KB (3 CTA/SM).
// Layout (u32): XS[96][68]@0 (6528; W-slotB overlays @0 after LN),
//               A[64][52]@6528, W-slotA@9856 (4992). Total 14848u.
// Q written pre-scaled by 96^-0.5.
// ---------------------------------------------------------------------------
#define QKV_XS 0
#define QKV_AS 6528
#define QKV_W0 9856
#define QKV_SMEM_U 14848

__global__ __launch_bounds__(256) void k_qkv(const float* __restrict__ x,
                                             const float* __restrict__ lnw,
                                             const float* __restrict__ lnb,
                                             const float* __restrict__ bias) {
    extern __shared__ unsigned smem_u[];
    int tid = threadIdx.x;
    int lane = tid & 31, warp = tid >> 5;
    int warp_m = warp & 1, warp_n = warp >> 1;
    int g = lane >> 2, tig = lane & 3;
    int m0 = blockIdx.x * 64;
    int bb = m0 / HW, hw0 = m0 % HW;

    unsigned sbase = s2u(smem_u);
    // x tile: 96 ch x 64 tok fp32 (16 chunks of 16B per channel)
#pragma unroll
    for (int l = 0; l < 6; ++l) {
        int o = tid + l * 256;
        int ch = o >> 4, t4 = o & 15;
        cp16(sbase + (QKV_XS + ch * 68 + t4 * 4) * 4,
             x + ((size_t)bb * 96 + ch) * HW + hw0 + t4 * 4);
    }
    // W block 0 -> slotA
#pragma unroll
    for (int l = 0; l < 5; ++l) {
        int o = tid + l * 256;
        if (o < 1152) {
            int row = o / 12, ch = o % 12;
            cp16(sbase + QKV_W0 * 4 + row * 208 + ch * 16, g_bwq + (size_t)row * 96 + ch * 8);
        }
    }
    CP_COMMIT();
    CP_WAIT0();
    __syncthreads();

    // LN1: 2 threads per token (128 threads active)
    if (tid < 128) {
        const float* xs = reinterpret_cast<const float*>(smem_u + QKV_XS);
        int r = tid >> 1, half = tid & 1;
        float vals[48];
        float s = 0.f, q = 0.f;
#pragma unroll
        for (int i = 0; i < 48; ++i) {
            float v = xs[(half * 48 + i) * 68 + r];
            vals[i] = v;
            s += v; q += v * v;
        }
        s += __shfl_xor_sync(0xffffffffu, s, 1);
        q += __shfl_xor_sync(0xffffffffu, q, 1);
        float mean = s * (1.f / 96.f);
        float var = q * (1.f / 96.f) - mean * mean;
        float rstd = rsqrtf(var + 1e-5f);
        unsigned* As = smem_u + QKV_AS;
#pragma unroll
        for (int i = 0; i < 24; ++i) {
            int c = half * 48 + i * 2;
            As[r * 52 + c / 2] = bf2u((vals[i * 2] - mean) * rstd * lnw[c] + lnb[c],
                                      (vals[i * 2 + 1] - mean) * rstd * lnw[c + 1] + lnb[c + 1]);
        }
    }
    __syncthreads();   // LN done; XS dead -> slotB (@0) writable

    // prefetch W block 1 -> slotB
#pragma unroll
    for (int l = 0; l < 5; ++l) {
        int o = tid + l * 256;
        if (o < 1152) {
            int row = o / 12, ch = o % 12;
            cp16(sbase + 0 + row * 208 + ch * 16, g_bwq + (size_t)(96 + row) * 96 + ch * 8);
        }
    }
    CP_COMMIT();

    unsigned aBase = sbase + QKV_AS * 4;
    __nv_bfloat16* out = g_qkv;

    auto gemm_block = [&](unsigned bBase, int nb) {
        float acc[2][3][4];
#pragma unroll
        for (int mt = 0; mt < 2; ++mt)
#pragma unroll
            for (int nt = 0; nt < 3; ++nt)
#pragma unroll
                for (int q = 0; q < 4; ++q) acc[mt][nt][q] = 0.f;
#pragma unroll
        for (int ks = 0; ks < 6; ++ks) {
            unsigned a[2][4];
#pragma unroll
            for (int mt = 0; mt < 2; ++mt)
                lda_frag(a[mt], aBase, warp_m * 32 + mt * 16, ks * 32, 208, lane);
#pragma unroll
            for (int nt = 0; nt < 3; ++nt) {
                unsigned b0, b1;
                ldb_frag(b0, b1, bBase, warp_n * 24 + nt * 8, ks * 32, 208, lane);
#pragma unroll
                for (int mt = 0; mt < 2; ++mt)
                    mma16(acc[mt][nt], a[mt], b0, b1);
            }
        }
        float sc = (nb == 0) ? 0.10206207261596575f : 1.0f;
#pragma unroll
        for (int mt = 0; mt < 2; ++mt) {
            int r0 = m0 + warp_m * 32 + mt * 16 + g;
#pragma unroll
            for (int nt = 0; nt < 3; ++nt) {
                int col = nb * 96 + warp_n * 24 + nt * 8 + 2 * tig;
                float bi0 = bias[col], bi1 = bias[col + 1];
                *reinterpret_cast<unsigned*>(&out[(size_t)r0 * 288 + col]) =
                    bf2u((acc[mt][nt][0] + bi0) * sc, (acc[mt][nt][1] + bi1) * sc);
                *reinterpret_cast<unsigned*>(&out[(size_t)(r0 + 8) * 288 + col]) =
                    bf2u((acc[mt][nt][2] + bi0) * sc, (acc[mt][nt][3] + bi1) * sc);
            }
        }
    };

    // nb0: Q (W in slotA)
    gemm_block(sbase + QKV_W0 * 4, 0);
    __syncthreads();   // all reads of slotA done
    // prefetch W block 2 -> slotA
#pragma unroll
    for (int l = 0; l < 5; ++l) {
        int o = tid + l * 256;
        if (o < 1152) {
            int row = o / 12, ch = o % 12;
            cp16(sbase + QKV_W0 * 4 + row * 208 + ch * 16,
                 g_bwq + (size_t)(192 + row) * 96 + ch * 8);
        }
    }
    CP_COMMIT();
    CP_WAIT1();        // W block 1 ready
    __syncthreads();
    // nb1: K (W in slotB)
    gemm_block(sbase + 0, 1);
    CP_WAIT0();        // W block 2 ready
    __syncthreads();
    // nb2: V (W in slotA)
    gemm_block(sbase + QKV_W0 * 4, 2);
}

// ---------------------------------------------------------------------------
// Fused proj + x-residual + LN2 + MLP1 + GELU + MLP2 + residual + NCHW out.
// x residual prefetched via cp.async into XR (overlays m1 region).
// smem (u32): A@0 (3328), S0@3328, S1@8320 (4992 ea), M/XR@13312 (12544),
//             EX@25856 (1024). Total 26880u = 107520B.
// ---------------------------------------------------------------------------
#define PML_S0 3328
#define PML_S1 8320
#define PML_M  13312
#define PML_EX 25856
#define PML_SMEM_U 26880

__global__ __launch_bounds__(256) void k_pml(const __nv_bfloat16* __restrict__ A,
                                             const float* __restrict__ pbias,
                                             const float* __restrict__ x,
                                             const float* __restrict__ lnw,
                                             const float* __restrict__ lnb,
                                             const float* __restrict__ b1,
                                             const float* __restrict__ b2,
                                             float* __restrict__ out) {
    extern __shared__ unsigned smem_u[];
    int tid = threadIdx.x;
    int lane = tid & 31, warp = tid >> 5;
    int warp_m = warp & 1, warp_n = warp >> 1;
    int g = lane >> 2, tig = lane & 3;
    int m0 = blockIdx.x * 64;
    int bb = m0 / HW, hw0 = m0 % HW;

    unsigned sbase = s2u(smem_u);
    // G1: ctx A-tile + proj W -> S0
#pragma unroll
    for (int l = 0; l < 3; ++l) {
        int o = tid + l * 256;
        int row = o / 12, ch = o % 12;
        cp16(sbase + row * 208 + ch * 16, A + (size_t)(m0 + row) * 96 + ch * 8);
    }
#pragma unroll
    for (int l = 0; l < 5; ++l) {
        int o = tid + l * 256;
        if (o < 1152) {
            int row = o / 12, ch = o % 12;
            cp16(sbase + PML_S0 * 4 + row * 208 + ch * 16, g_bwp + (size_t)row * 96 + ch * 8);
        }
    }
    CP_COMMIT();
    // G2: W1 block 0 -> S1, x residual tile -> XR (overlay on M region)
#pragma unroll
    for (int l = 0; l < 5; ++l) {
        int o = tid + l * 256;
        if (o < 1152) {
            int row = o / 12, ch = o % 12;
            cp16(sbase + PML_S1 * 4 + row * 208 + ch * 16, g_bw1 + (size_t)row * 96 + ch * 8);
        }
    }
#pragma unroll
    for (int l = 0; l < 6; ++l) {
        int o = tid + l * 256;
        int ch = o >> 4, t4 = o & 15;
        cp16(sbase + (PML_M + ch * 68 + t4 * 4) * 4,
             x + ((size_t)bb * 96 + ch) * HW + hw0 + t4 * 4);
    }
    CP_COMMIT();
    CP_WAIT1();
    __syncthreads();

    // ---- proj GEMM -> h regs ---------------------------------------------
    float h[2][3][4];
#pragma unroll
    for (int mt = 0; mt < 2; ++mt)
#pragma unroll
        for (int nt = 0; nt < 3; ++nt)
#pragma unroll
            for (int q = 0; q < 4; ++q) h[mt][nt][q] = 0.f;
#pragma unroll
    for (int ks = 0; ks < 6; ++ks) {
        unsigned a[2][4];
#pragma unroll
        for (int mt = 0; mt < 2; ++mt)
            lda_frag(a[mt], sbase, warp_m * 32 + mt * 16, ks * 32, 208, lane);
#pragma unroll
        for (int nt = 0; nt < 3; ++nt) {
            unsigned b0, b1;
            ldb_frag(b0, b1, sbase + PML_S0 * 4, warp_n * 24 + nt * 8, ks * 32, 208, lane);
#pragma unroll
            for (int mt = 0; mt < 2; ++mt)
                mma16(h[mt][nt], a[mt], b0, b1);
        }
    }
    CP_WAIT0();        // XR (and W1b0) ready
    __syncthreads();
    // epilogue: + proj bias + x residual from XR smem
    {
        const float* xr = reinterpret_cast<const float*>(smem_u + PML_M);
#pragma unroll
        for (int mt = 0; mt < 2; ++mt) {
            int r0 = warp_m * 32 + mt * 16 + g;
#pragma unroll
            for (int nt = 0; nt < 3; ++nt) {
                int col = warp_n * 24 + nt * 8 + 2 * tig;
                h[mt][nt][0] += pbias[col]     + xr[col * 68 + r0];
                h[mt][nt][1] += pbias[col + 1] + xr[(col + 1) * 68 + r0];
                h[mt][nt][2] += pbias[col]     + xr[col * 68 + r0 + 8];
                h[mt][nt][3] += pbias[col + 1] + xr[(col + 1) * 68 + r0 + 8];
            }
        }
    }
    // ---- LN2: register partials + smem exchange ---------------------------
    float ps[2][2], pq[2][2];
#pragma unroll
    for (int mt = 0; mt < 2; ++mt)
#pragma unroll
        for (int rr = 0; rr < 2; ++rr) {
            float s = 0.f, q = 0.f;
#pragma unroll
            for (int nt = 0; nt < 3; ++nt) {
                s += h[mt][nt][rr * 2 + 0] + h[mt][nt][rr * 2 + 1];
                q += h[mt][nt][rr * 2 + 0] * h[mt][nt][rr * 2 + 0] +
                     h[mt][nt][rr * 2 + 1] * h[mt][nt][rr * 2 + 1];
            }
            s += __shfl_xor_sync(0xffffffffu, s, 1);
            q += __shfl_xor_sync(0xffffffffu, q, 1);
            s += __shfl_xor_sync(0xffffffffu, s, 2);
            q += __shfl_xor_sync(0xffffffffu, q, 2);
            ps[mt][rr] = s; pq[mt][rr] = q;
        }
    __syncthreads();
    {
        float2* ex = reinterpret_cast<float2*>(smem_u + PML_EX);
        if (tig == 0) {
#pragma unroll
            for (int mt = 0; mt < 2; ++mt)
#pragma unroll
                for (int rr = 0; rr < 2; ++rr) {
                    int row = warp_m * 32 + mt * 16 + g + rr * 8;
                    ex[row * 4 + warp_n] = make_float2(ps[mt][rr], pq[mt][rr]);
                }
        }
    }
    __syncthreads();
    {
        const float2* ex = reinterpret_cast<const float2*>(smem_u + PML_EX);
        unsigned* As = smem_u;   // ln2 bf16 tile overlays ctx
#pragma unroll
        for (int mt = 0; mt < 2; ++mt)
#pragma unroll
            for (int rr = 0; rr < 2; ++rr) {
                int row = warp_m * 32 + mt * 16 + g + rr * 8;
                float2 e0 = ex[row * 4 + 0], e1 = ex[row * 4 + 1];
                float2 e2 = ex[row * 4 + 2], e3 = ex[row * 4 + 3];
                float s = e0.x + e1.x + e2.x + e3.x;
                float q = e0.y + e1.y + e2.y + e3.y;
                float mean = s * (1.f / 96.f);
                float var = q * (1.f / 96.f) - mean * mean;
                float rstd = rsqrtf(var + 1e-5f);
#pragma unroll
                for (int nt = 0; nt < 3; ++nt) {
                    int col = warp_n * 24 + nt * 8 + 2 * tig;
                    float v0 = (h[mt][nt][rr * 2 + 0] - mean) * rstd * lnw[col] + lnb[col];
                    float v1 = (h[mt][nt][rr * 2 + 1] - mean) * rstd * lnw[col + 1] + lnb[col + 1];
                    As[row * 52 + col / 2] = bf2u(v0, v1);
                }
            }
    }
    __syncthreads();

    unsigned* MU = smem_u + PML_M;
    const unsigned wslot[2] = {PML_S1, PML_S0};

    // ---- MLP1: 4 N-blocks + GELU -> M smem --------------------------------
    for (int nb = 0; nb < 4; ++nb) {
        CP_WAIT0();
        __syncthreads();
        {
            const __nv_bfloat16* nsrc = (nb < 3)
                ? g_bw1 + (size_t)(nb + 1) * 96 * 96
                : g_bw2;
            unsigned dslot = wslot[(nb + 1) & 1];
#pragma unroll
            for (int l = 0; l < 5; ++l) {
                int o = tid + l * 256;
                if (o < 1152) {
                    int row = o / 12, ch = o % 12;
                    if (nb < 3)
                        cp16(sbase + dslot * 4 + row * 208 + ch * 16, nsrc + (size_t)row * 96 + ch * 8);
                    else
                        cp16(sbase + dslot * 4 + row * 208 + ch * 16, nsrc + (size_t)row * 384 + ch * 8);
                }
            }
            CP_COMMIT();
        }
        unsigned bBase = sbase + wslot[nb & 1] * 4;
        float acc[2][3][4];
#pragma unroll
        for (int mt = 0; mt < 2; ++mt)
#pragma unroll
            for (int nt = 0; nt < 3; ++nt)
#pragma unroll
                for (int q = 0; q < 4; ++q) acc[mt][nt][q] = 0.f;
#pragma unroll
        for (int ks = 0; ks < 6; ++ks) {
            unsigned a[2][4];
#pragma unroll
            for (int mt = 0; mt < 2; ++mt)
                lda_frag(a[mt], sbase, warp_m * 32 + mt * 16, ks * 32, 208, lane);
#pragma unroll
            for (int nt = 0; nt < 3; ++nt) {
                unsigned b0, b1;
                ldb_frag(b0, b1, bBase, warp_n * 24 + nt * 8, ks * 32, 208, lane);
#pragma unroll
                for (int mt = 0; mt < 2; ++mt)
                    mma16(acc[mt][nt], a[mt], b0, b1);
            }
        }
#pragma unroll
        for (int mt = 0; mt < 2; ++mt) {
            int r0 = warp_m * 32 + mt * 16 + g;
#pragma unroll
            for (int nt = 0; nt < 3; ++nt) {
                int col = warp_n * 24 + nt * 8 + 2 * tig;
                float bi0 = b1[nb * 96 + col], bi1 = b1[nb * 96 + col + 1];
                float v0 = acc[mt][nt][0] + bi0, v1 = acc[mt][nt][1] + bi1;
                float v2 = acc[mt][nt][2] + bi0, v3 = acc[mt][nt][3] + bi1;
                v0 = 0.5f * v0 * (1.0f + erff(v0 * 0.70710678118654752f));
                v1 = 0.5f * v1 * (1.0f + erff(v1 * 0.70710678118654752f));
                v2 = 0.5f * v2 * (1.0f + erff(v2 * 0.70710678118654752f));
                v3 = 0.5f * v3 * (1.0f + erff(v3 * 0.70710678118654752f));
                MU[r0 * 196 + nb * 48 + col / 2] = bf2u(v0, v1);
                MU[(r0 + 8) * 196 + nb * 48 + col / 2] = bf2u(v2, v3);
            }
        }
    }

    // ---- MLP2: 4 K-chunks, accumulate acc2 --------------------------------
    float acc2[2][3][4];
#pragma unroll
    for (int mt = 0; mt < 2; ++mt)
#pragma unroll
        for (int nt = 0; nt < 3; ++nt)
#pragma unroll
            for (int q = 0; q < 4; ++q) acc2[mt][nt][q] = 0.f;

    for (int kc = 0; kc < 4; ++kc) {
        CP_WAIT0();
        __syncthreads();
        if (kc < 3) {
            unsigned dslot = wslot[(kc + 1) & 1];
#pragma unroll
            for (int l = 0; l < 5; ++l) {
                int o = tid + l * 256;
                if (o < 1152) {
                    int row = o / 12, ch = o % 12;
                    cp16(sbase + dslot * 4 + row * 208 + ch * 16,
                         g_bw2 + (size_t)row * 384 + (kc + 1) * 96 + ch * 8);
                }
            }
            CP_COMMIT();
        }
        unsigned bBase = sbase + wslot[kc & 1] * 4;
        unsigned mBase = sbase + PML_M * 4 + kc * 192;
#pragma unroll
        for (int ks = 0; ks < 6; ++ks) {
            unsigned a[2][4];
#pragma unroll
            for (int mt = 0; mt < 2; ++mt)
                lda_frag(a[mt], mBase, warp_m * 32 + mt * 16, ks * 32, 784, lane);
#pragma unroll
            for (int nt = 0; nt < 3; ++nt) {
                unsigned b0, b1;
                ldb_frag(b0, b1, bBase, warp_n * 24 + nt * 8, ks * 32, 208, lane);
#pragma unroll
                for (int mt = 0; mt < 2; ++mt)
                    mma16(acc2[mt][nt], a[mt], b0, b1);
            }
        }
    }

    // ---- epilogue: +b2 +h(regs), NCHW store -------------------------------
    __syncthreads();
    float (*st)[98] = reinterpret_cast<float (*)[98]>(smem_u + PML_M);
#pragma unroll
    for (int mt = 0; mt < 2; ++mt) {
        int lr0 = warp_m * 32 + mt * 16 + g;
#pragma unroll
        for (int nt = 0; nt < 3; ++nt) {
            int col = warp_n * 24 + nt * 8 + 2 * tig;
            float bi0 = b2[col], bi1 = b2[col + 1];
            *reinterpret_cast<float2*>(&st[lr0][col]) =
                make_float2(acc2[mt][nt][0] + bi0 + h[mt][nt][0],
                            acc2[mt][nt][1] + bi1 + h[mt][nt][1]);
            *reinterpret_cast<float2*>(&st[lr0 + 8][col]) =
                make_float2(acc2[mt][nt][2] + bi0 + h[mt][nt][2],
                            acc2[mt][nt][3] + bi1 + h[mt][nt][3]);
        }
    }
    __syncthreads();
    float* ob = out + (size_t)bb * 96 * HW + hw0;
#pragma unroll
    for (int l = 0; l < 24; ++l) {
        int e = tid + l * 256;
        int ch = e >> 6, tok = e & 63;
        ob[(size_t)ch * HW + tok] = st[tok][ch];
    }
}

// ---------------------------------------------------------------------------
// Attention, register softmax; Q arrives pre-scaled.
// smem (u32): qs@0, ks@3328, vs@6656 (64*52 each), tbl@9984 (1228u).
// Overlays: P on qs; exchange on ks. Total 11212u = 44848B (5 CTA/SM).
// ---------------------------------------------------------------------------
#define QS_U 0
#define KS_U 3328
#define VS_U 6656
#define TB_U 9984
#define EX_U 3328
#define SM_ATTN_U 11212

__global__ __launch_bounds__(256) void k_attn() {
    extern __shared__ unsigned smem_u[];
    __shared__ int tok_s[49];

    int win = blockIdx.x;
    int bb = win >> 10;
    int wr = (win >> 5) & 31;
    int wc = win & 31;
    int tid = threadIdx.x;
    int lane = tid & 31, warp = tid >> 5;
    int g = lane >> 2, tig = lane & 3;
    int mt = warp & 3, nhalf = warp >> 2;
    int cls = ((wr == 31) ? 2 : 0) + ((wc == 31) ? 1 : 0);

    if (tid < 49) {
        int i = tid / 7, j = tid % 7;
        int sr = wr * 7 + i, sc = wc * 7 + j;
        int r = sr + 3; if (r >= 224) r -= 224;
        int c = sc + 3; if (c >= 224) c -= 224;
        tok_s[tid] = bb * HW + r * 224 + c;
    }
    for (int e = tid; e < 780; e += 256) smem_u[VS_U + 49 * 52 + e] = 0u;
    __syncthreads();

    unsigned sbase = s2u(smem_u);
#pragma unroll
    for (int l = 0; l < 7; ++l) {
        int e = tid + l * 256;
        if (e < 1764) {
            int third = e / 588;
            int ee = e - third * 588;
            int row = ee / 12, ch = ee % 12;
            cp16(sbase + third * 13312 + row * 208 + ch * 16,
                 g_qkv + (size_t)tok_s[row] * 288 + third * 96 + ch * 8);
        }
    }
    {
        const __nv_bfloat16* tsrc = g_tbl + cls * 2456;
        for (int o = tid; o < 307; o += 256)
            cp16(sbase + TB_U * 4 + o * 16, tsrc + o * 8);
    }
    CP_COMMIT();
    CP_WAIT0();
    __syncthreads();

    float acc[4][4];
#pragma unroll
    for (int t = 0; t < 4; ++t)
#pragma unroll
        for (int q = 0; q < 4; ++q) acc[t][q] = 0.f;
#pragma unroll
    for (int ks = 0; ks < 6; ++ks) {
        unsigned a[4];
        lda_frag(a, sbase, mt * 16, ks * 32, 208, lane);
#pragma unroll
        for (int t = 0; t < 4; ++t) {
            unsigned b0, b1;
            ldb_frag(b0, b1, sbase + KS_U * 4, (nhalf * 4 + t) * 8, ks * 32, 208, lane);
            mma16(acc[t], a, b0, b1);
        }
    }

    const __nv_bfloat16* tb = reinterpret_cast<const __nv_bfloat16*>(smem_u + TB_U);
    float mx[2] = {-1e30f, -1e30f};
#pragma unroll
    for (int t = 0; t < 4; ++t) {
        int j0 = (nhalf * 4 + t) * 8 + 2 * tig;
#pragma unroll
        for (int rr = 0; rr < 2; ++rr) {
            int i = mt * 16 + g + rr * 8;
            float v0 = acc[t][rr * 2 + 0];
            float v1 = acc[t][rr * 2 + 1];
            if (i < 49 && j0 < 49) {
                __nv_bfloat162 t2 = *reinterpret_cast<const __nv_bfloat162*>(&tb[i * 50 + j0]);
                v0 += __bfloat162float(t2.x);
                v1 += __bfloat162float(t2.y);
            }
            if (j0 > 48) v0 = -1e30f;
            if (j0 + 1 > 48) v1 = -1e30f;
            acc[t][rr * 2 + 0] = v0;
            acc[t][rr * 2 + 1] = v1;
            mx[rr] = fmaxf(mx[rr], fmaxf(v0, v1));
        }
    }
#pragma unroll
    for (int rr = 0; rr < 2; ++rr) {
        mx[rr] = fmaxf(mx[rr], __shfl_xor_sync(0xffffffffu, mx[rr], 1));
        mx[rr] = fmaxf(mx[rr], __shfl_xor_sync(0xffffffffu, mx[rr], 2));
    }
    float sm[2] = {0.f, 0.f};
#pragma unroll
    for (int t = 0; t < 4; ++t)
#pragma unroll
        for (int rr = 0; rr < 2; ++rr) {
            float p0 = __expf(acc[t][rr * 2 + 0] - mx[rr]);
            float p1 = __expf(acc[t][rr * 2 + 1] - mx[rr]);
            acc[t][rr * 2 + 0] = p0;
            acc[t][rr * 2 + 1] = p1;
            sm[rr] += p0 + p1;
        }
#pragma unroll
    for (int rr = 0; rr < 2; ++rr) {
        sm[rr] += __shfl_xor_sync(0xffffffffu, sm[rr], 1);
        sm[rr] += __shfl_xor_sync(0xffffffffu, sm[rr], 2);
    }

    __syncthreads();
    {
        float2* ex = reinterpret_cast<float2*>(smem_u + EX_U);
        if (tig == 0) {
#pragma unroll
            for (int rr = 0; rr < 2; ++rr) {
                int i = mt * 16 + g + rr * 8;
                ex[i * 2 + nhalf] = make_float2(mx[rr], sm[rr]);
            }
        }
    }
    __syncthreads();
    {
        const float2* ex = reinterpret_cast<const float2*>(smem_u + EX_U);
        __nv_bfloat16* atth = reinterpret_cast<__nv_bfloat16*>(smem_u + QS_U);
#pragma unroll
        for (int rr = 0; rr < 2; ++rr) {
            int i = mt * 16 + g + rr * 8;
            float2 e0 = ex[i * 2 + 0];
            float2 e1 = ex[i * 2 + 1];
            float M = fmaxf(e0.x, e1.x);
            float S = e0.y * __expf(e0.x - M) + e1.y * __expf(e1.x - M);
            float f = __expf(mx[rr] - M) / S;
#pragma unroll
            for (int t = 0; t < 4; ++t) {
                unsigned* dst = reinterpret_cast<unsigned*>(atth) +
                                i * 36 + (nhalf * 4 + t) * 4 + tig;
                *dst = bf2u(acc[t][rr * 2 + 0] * f, acc[t][rr * 2 + 1] * f);
            }
        }
    }
    __syncthreads();

    {
        unsigned atBase = sbase;
        unsigned vBase = sbase + VS_U * 4;
        float av[6][4];
#pragma unroll
        for (int t = 0; t < 6; ++t)
#pragma unroll
            for (int q = 0; q < 4; ++q) av[t][q] = 0.f;
#pragma unroll
        for (int ks = 0; ks < 4; ++ks) {
            unsigned a[4];
            lda_frag(a, atBase, mt * 16, ks * 32, 144, lane);
            unsigned vrow = vBase + (ks * 16 + (lane & 15)) * 208;
#pragma unroll
            for (int t = 0; t < 6; ++t) {
                int ch0 = (nhalf * 6 + t) * 8;
                unsigned b0, b1;
                ldsm_x2t(b0, b1, vrow + ch0 * 2);
                mma16(av[t], a, b0, b1);
            }
        }
#pragma unroll
        for (int t = 0; t < 6; ++t) {
            int ch = (nhalf * 6 + t) * 8 + 2 * tig;
#pragma unroll
            for (int rr = 0; rr < 2; ++rr) {
                int r = mt * 16 + g + rr * 8;
                if (r < 49) {
                    *reinterpret_cast<unsigned*>(&g_ctx[(size_t)tok_s[r] * 96 + ch]) =
                        bf2u(av[t][rr * 2 + 0], av[t][rr * 2 + 1]);
                }
            }
        }
    }
}

// ---------------------------------------------------------------------------
extern "C" void kernel_launch(void* const* d_in, const int* in_sizes, int n_in,
                              void* d_out, int out_size) {
    const float* x    = (const float*)d_in[0];
    const float* n1w  = (const float*)d_in[1];
    const float* n1b  = (const float*)d_in[2];
    const float* qkvw = (const float*)d_in[3];
    const float* qkvb = (const float*)d_in[4];
    const float* rel  = (const float*)d_in[5];
    const float* pw   = (const float*)d_in[6];
    const float* pb   = (const float*)d_in[7];
    const float* n2w  = (const float*)d_in[8];
    const float* n2b  = (const float*)d_in[9];
    const float* w1   = (const float*)d_in[10];
    const float* b1   = (const float*)d_in[11];
    const float* w2   = (const float*)d_in[12];
    const float* b2   = (const float*)d_in[13];
    float* out = (float*)d_out;

    void *p_ctx;
    cudaGetSymbolAddress(&p_ctx, g_ctx);

    const int SMQKV  = QKV_SMEM_U * 4;    // 59392
    const int SMPML  = PML_SMEM_U * 4;    // 107520
    const int SMATTN = SM_ATTN_U * 4;     // 44848

    cudaFuncSetAttribute(k_qkv,  cudaFuncAttributeMaxDynamicSharedMemorySize, SMQKV);
    cudaFuncSetAttribute(k_pml,  cudaFuncAttributeMaxDynamicSharedMemorySize, SMPML);
    cudaFuncSetAttribute(k_attn, cudaFuncAttributeMaxDynamicSharedMemorySize, SMATTN);

    k_prep<<<432, 256>>>(qkvw, pw, w1, w2);
    k_tbl<<<4, 256>>>(rel);
    k_qkv<<<6272, 256, SMQKV>>>(x, n1w, n1b, qkvb);
    k_attn<<<NWIN, 256, SMATTN>>>();
    k_pml<<<6272, 256, SMPML>>>(
        (const __nv_bfloat16*)p_ctx, pb, x, n2w, n2b, b1, b2, out);
}